// round 1
// baseline (speedup 1.0000x reference)
#include <cuda_runtime.h>
#include <math.h>

#define B_SZ  2
#define S_LEN 2048
#define HID   1024
#define NH    16
#define HD    64
#define M_TOK (B_SZ * S_LEN)     // 4096

// Scratch buffers (allocation-free rule: __device__ globals)
__device__ float g_qkv[(size_t)M_TOK * 3 * HID];   // [tok][3H]
__device__ float g_ctx[(size_t)M_TOK * HID];       // [tok][H]

// ---------------------------------------------------------------------------
// Generic SGEMM with bias: C[M,N] = A[M,K] @ B[K,N] + bias[N]
// 128x128 block tile, 256 threads, 8x8 per thread (two 4x4 quads per axis).
// ---------------------------------------------------------------------------
__global__ __launch_bounds__(256) void sgemm_bias(
    const float* __restrict__ A, const float* __restrict__ Bm,
    const float* __restrict__ bias, float* __restrict__ C,
    int M, int N, int K)
{
    __shared__ float As[16][128];   // [k][m] (transposed on store)
    __shared__ float Bs[16][128];   // [k][n]

    const int tid = threadIdx.x;
    const int bm  = blockIdx.y * 128;
    const int bn  = blockIdx.x * 128;
    const int tx  = tid & 15;
    const int ty  = tid >> 4;

    float acc[8][8];
#pragma unroll
    for (int i = 0; i < 8; i++)
#pragma unroll
        for (int j = 0; j < 8; j++) acc[i][j] = 0.f;

    const int a_row = tid >> 2;          // 0..63 (and +64)
    const int a_col = (tid & 3) << 2;    // 0,4,8,12
    const int b_row = tid >> 5;          // 0..7 (and +8)
    const int b_col = (tid & 31) << 2;   // 0..124

    for (int kt = 0; kt < K; kt += 16) {
#pragma unroll
        for (int i = 0; i < 2; i++) {
            int r = a_row + i * 64;
            float4 v = *(const float4*)&A[(size_t)(bm + r) * K + kt + a_col];
            As[a_col + 0][r] = v.x;
            As[a_col + 1][r] = v.y;
            As[a_col + 2][r] = v.z;
            As[a_col + 3][r] = v.w;
        }
#pragma unroll
        for (int i = 0; i < 2; i++) {
            int r = b_row + i * 8;
            *(float4*)&Bs[r][b_col] =
                *(const float4*)&Bm[(size_t)(kt + r) * N + bn + b_col];
        }
        __syncthreads();

#pragma unroll
        for (int k = 0; k < 16; k++) {
            float a[8], b[8];
            *(float4*)&a[0] = *(float4*)&As[k][ty * 4];
            *(float4*)&a[4] = *(float4*)&As[k][ty * 4 + 64];
            *(float4*)&b[0] = *(float4*)&Bs[k][tx * 4];
            *(float4*)&b[4] = *(float4*)&Bs[k][tx * 4 + 64];
#pragma unroll
            for (int i = 0; i < 8; i++)
#pragma unroll
                for (int j = 0; j < 8; j++)
                    acc[i][j] = fmaf(a[i], b[j], acc[i][j]);
        }
        __syncthreads();
    }

#pragma unroll
    for (int ih = 0; ih < 2; ih++)
#pragma unroll
        for (int i = 0; i < 4; i++) {
            int r = bm + ih * 64 + ty * 4 + i;
#pragma unroll
            for (int jh = 0; jh < 2; jh++) {
                int c = bn + jh * 64 + tx * 4;
                float4 bv = *(const float4*)&bias[c];
                float4 o;
                o.x = acc[ih * 4 + i][jh * 4 + 0] + bv.x;
                o.y = acc[ih * 4 + i][jh * 4 + 1] + bv.y;
                o.z = acc[ih * 4 + i][jh * 4 + 2] + bv.z;
                o.w = acc[ih * 4 + i][jh * 4 + 3] + bv.w;
                *(float4*)&C[(size_t)r * N + c] = o;
            }
        }
}

// ---------------------------------------------------------------------------
// Flash attention (causal), fp32. One CTA per (batch, head, 64-query tile).
// 256 threads: ty (0..15) -> 4 query rows each, tx (0..15) -> 4 cols each.
// ---------------------------------------------------------------------------
#define BM 64
#define BN 64
#define QS_LD 65
#define KS_LD 65
#define PS_LD 68
#define FLASH_SMEM ((BM * QS_LD + BN * KS_LD + BN * HD + BM * PS_LD) * 4)

__device__ __forceinline__ float redmax16(float v) {
    v = fmaxf(v, __shfl_xor_sync(0xffffffffu, v, 8));
    v = fmaxf(v, __shfl_xor_sync(0xffffffffu, v, 4));
    v = fmaxf(v, __shfl_xor_sync(0xffffffffu, v, 2));
    v = fmaxf(v, __shfl_xor_sync(0xffffffffu, v, 1));
    return v;
}
__device__ __forceinline__ float redsum16(float v) {
    v += __shfl_xor_sync(0xffffffffu, v, 8);
    v += __shfl_xor_sync(0xffffffffu, v, 4);
    v += __shfl_xor_sync(0xffffffffu, v, 2);
    v += __shfl_xor_sync(0xffffffffu, v, 1);
    return v;
}

__global__ __launch_bounds__(256) void flash_attn(
    const float* __restrict__ qkv, float* __restrict__ ctx)
{
    extern __shared__ float sm[];
    float* Qs = sm;                     // [BM][QS_LD]
    float* Ks = Qs + BM * QS_LD;        // [BN][KS_LD]
    float* Vs = Ks + BN * KS_LD;        // [BN][HD]
    float* Ps = Vs + BN * HD;           // [BM][PS_LD]

    const int tid = threadIdx.x;
    // launch largest-work tiles first to shrink the causal tail
    const int qb = (int)gridDim.x - 1 - (int)blockIdx.x;
    const int h  = blockIdx.y;
    const int b  = blockIdx.z;
    const int tx = tid & 15;
    const int ty = tid >> 4;

    // --- load Q tile (row-major, padded) ---
#pragma unroll
    for (int it = 0; it < 4; it++) {
        int idx = tid + it * 256;            // 0..1023
        int r   = idx >> 4;
        int c   = (idx & 15) << 2;
        const float* src =
            qkv + (size_t)(b * S_LEN + qb * BM + r) * (3 * HID) + h * HD + c;
        float4 v = *(const float4*)src;
        Qs[r * QS_LD + c + 0] = v.x;
        Qs[r * QS_LD + c + 1] = v.y;
        Qs[r * QS_LD + c + 2] = v.z;
        Qs[r * QS_LD + c + 3] = v.w;
    }

    float m_i[4], l_i[4], o[4][4];
#pragma unroll
    for (int i = 0; i < 4; i++) {
        m_i[i] = -1e30f;
        l_i[i] = 0.f;
#pragma unroll
        for (int j = 0; j < 4; j++) o[i][j] = 0.f;
    }

    for (int kb = 0; kb <= qb; kb++) {
        __syncthreads();   // prev-iter PV reads done before overwriting K/V

        // --- load K (padded rows) and V (dense rows) ---
#pragma unroll
        for (int it = 0; it < 4; it++) {
            int idx = tid + it * 256;
            int r   = idx >> 4;
            int c   = (idx & 15) << 2;
            const float* base =
                qkv + (size_t)(b * S_LEN + kb * BN + r) * (3 * HID) + h * HD + c;
            float4 kv = *(const float4*)(base + HID);
            Ks[r * KS_LD + c + 0] = kv.x;
            Ks[r * KS_LD + c + 1] = kv.y;
            Ks[r * KS_LD + c + 2] = kv.z;
            Ks[r * KS_LD + c + 3] = kv.w;
            *(float4*)&Vs[r * HD + c] = *(const float4*)(base + 2 * HID);
        }
        __syncthreads();

        // --- S = Q K^T (per-thread 4x4) ---
        float s[4][4];
#pragma unroll
        for (int i = 0; i < 4; i++)
#pragma unroll
            for (int j = 0; j < 4; j++) s[i][j] = 0.f;

#pragma unroll 4
        for (int d = 0; d < HD; d++) {
            float a0 = Qs[(ty * 4 + 0) * QS_LD + d];
            float a1 = Qs[(ty * 4 + 1) * QS_LD + d];
            float a2 = Qs[(ty * 4 + 2) * QS_LD + d];
            float a3 = Qs[(ty * 4 + 3) * QS_LD + d];
            float b0 = Ks[(tx * 4 + 0) * KS_LD + d];
            float b1 = Ks[(tx * 4 + 1) * KS_LD + d];
            float b2 = Ks[(tx * 4 + 2) * KS_LD + d];
            float b3 = Ks[(tx * 4 + 3) * KS_LD + d];
            s[0][0] = fmaf(a0, b0, s[0][0]); s[0][1] = fmaf(a0, b1, s[0][1]);
            s[0][2] = fmaf(a0, b2, s[0][2]); s[0][3] = fmaf(a0, b3, s[0][3]);
            s[1][0] = fmaf(a1, b0, s[1][0]); s[1][1] = fmaf(a1, b1, s[1][1]);
            s[1][2] = fmaf(a1, b2, s[1][2]); s[1][3] = fmaf(a1, b3, s[1][3]);
            s[2][0] = fmaf(a2, b0, s[2][0]); s[2][1] = fmaf(a2, b1, s[2][1]);
            s[2][2] = fmaf(a2, b2, s[2][2]); s[2][3] = fmaf(a2, b3, s[2][3]);
            s[3][0] = fmaf(a3, b0, s[3][0]); s[3][1] = fmaf(a3, b1, s[3][1]);
            s[3][2] = fmaf(a3, b2, s[3][2]); s[3][3] = fmaf(a3, b3, s[3][3]);
        }

        const bool diag = (kb == qb);
#pragma unroll
        for (int i = 0; i < 4; i++) {
#pragma unroll
            for (int j = 0; j < 4; j++) {
                s[i][j] *= 0.125f;   // 1/sqrt(64)
                if (diag && (tx * 4 + j) > (ty * 4 + i)) s[i][j] = -1e30f;
            }
        }

        // --- online softmax update ---
#pragma unroll
        for (int i = 0; i < 4; i++) {
            float rm = fmaxf(fmaxf(s[i][0], s[i][1]), fmaxf(s[i][2], s[i][3]));
            rm = redmax16(rm);
            float mn   = fmaxf(m_i[i], rm);
            float corr = expf(m_i[i] - mn);      // exp(-1e30 - x) -> 0 first iter
            float p0 = expf(s[i][0] - mn);
            float p1 = expf(s[i][1] - mn);
            float p2 = expf(s[i][2] - mn);
            float p3 = expf(s[i][3] - mn);
            float rs = redsum16(p0 + p1 + p2 + p3);
            l_i[i] = l_i[i] * corr + rs;
            m_i[i] = mn;
#pragma unroll
            for (int j = 0; j < 4; j++) o[i][j] *= corr;
            float4 pv = make_float4(p0, p1, p2, p3);
            *(float4*)&Ps[(ty * 4 + i) * PS_LD + tx * 4] = pv;
        }
        __syncthreads();

        // --- O += P V ---
#pragma unroll 4
        for (int c = 0; c < BN; c++) {
            float4 vv = *(const float4*)&Vs[c * HD + tx * 4];
            float a0 = Ps[(ty * 4 + 0) * PS_LD + c];
            float a1 = Ps[(ty * 4 + 1) * PS_LD + c];
            float a2 = Ps[(ty * 4 + 2) * PS_LD + c];
            float a3 = Ps[(ty * 4 + 3) * PS_LD + c];
            o[0][0] = fmaf(a0, vv.x, o[0][0]); o[0][1] = fmaf(a0, vv.y, o[0][1]);
            o[0][2] = fmaf(a0, vv.z, o[0][2]); o[0][3] = fmaf(a0, vv.w, o[0][3]);
            o[1][0] = fmaf(a1, vv.x, o[1][0]); o[1][1] = fmaf(a1, vv.y, o[1][1]);
            o[1][2] = fmaf(a1, vv.z, o[1][2]); o[1][3] = fmaf(a1, vv.w, o[1][3]);
            o[2][0] = fmaf(a2, vv.x, o[2][0]); o[2][1] = fmaf(a2, vv.y, o[2][1]);
            o[2][2] = fmaf(a2, vv.z, o[2][2]); o[2][3] = fmaf(a2, vv.w, o[2][3]);
            o[3][0] = fmaf(a3, vv.x, o[3][0]); o[3][1] = fmaf(a3, vv.y, o[3][1]);
            o[3][2] = fmaf(a3, vv.z, o[3][2]); o[3][3] = fmaf(a3, vv.w, o[3][3]);
        }
    }

    // --- finalize: divide by l, write ctx in [tok][H] layout (= transpose fold) ---
#pragma unroll
    for (int i = 0; i < 4; i++) {
        float inv = 1.0f / l_i[i];
        float4 ov = make_float4(o[i][0] * inv, o[i][1] * inv,
                                o[i][2] * inv, o[i][3] * inv);
        size_t tok = (size_t)(b * S_LEN + qb * BM + ty * 4 + i);
        *(float4*)&ctx[tok * HID + h * HD + tx * 4] = ov;
    }
}

// ---------------------------------------------------------------------------
extern "C" void kernel_launch(void* const* d_in, const int* in_sizes, int n_in,
                              void* d_out, int out_size)
{
    (void)in_sizes; (void)n_in; (void)out_size;
    const float* hidden  = (const float*)d_in[0];
    // d_in[1] = ltor_mask: exactly lower-triangular causal; handled analytically
    const float* W_qkv   = (const float*)d_in[2];
    const float* b_qkv   = (const float*)d_in[3];
    const float* W_dense = (const float*)d_in[4];
    const float* b_dense = (const float*)d_in[5];
    float* out = (float*)d_out;

    float* qkv_ptr = nullptr;
    float* ctx_ptr = nullptr;
    cudaGetSymbolAddress((void**)&qkv_ptr, g_qkv);
    cudaGetSymbolAddress((void**)&ctx_ptr, g_ctx);

    cudaFuncSetAttribute(flash_attn,
                         cudaFuncAttributeMaxDynamicSharedMemorySize,
                         FLASH_SMEM);

    // 1) QKV projection: [4096,1024] @ [1024,3072] + bias
    {
        dim3 grid(3 * HID / 128, M_TOK / 128);
        sgemm_bias<<<grid, 256>>>(hidden, W_qkv, b_qkv, qkv_ptr,
                                  M_TOK, 3 * HID, HID);
    }
    // 2) Causal flash attention -> ctx [tok][H]
    {
        dim3 grid(S_LEN / BM, NH, B_SZ);
        flash_attn<<<grid, 256, FLASH_SMEM>>>(qkv_ptr, ctx_ptr);
    }
    // 3) Output projection: [4096,1024] @ [1024,1024] + bias
    {
        dim3 grid(HID / 128, M_TOK / 128);
        sgemm_bias<<<grid, 256>>>(ctx_ptr, W_dense, b_dense, out,
                                  M_TOK, HID, HID);
    }
}

// round 3
// speedup vs baseline: 1.3397x; 1.3397x over previous
#include <cuda_runtime.h>
#include <cuda_bf16.h>
#include <cstdint>
#include <math.h>

#define B_SZ  2
#define S_LEN 2048
#define HID   1024
#define NH    16
#define HD    64
#define M_TOK (B_SZ * S_LEN)     // 4096

// ---------------------------------------------------------------------------
// Scratch (__device__ globals per allocation-free rule)
// ---------------------------------------------------------------------------
__device__ float g_qkv[(size_t)M_TOK * 3 * HID];            // 48 MB
__device__ float g_ctx[(size_t)M_TOK * HID];                // 16 MB
__device__ __nv_bfloat16 g_Ah[(size_t)M_TOK * HID];
__device__ __nv_bfloat16 g_Al[(size_t)M_TOK * HID];
__device__ __nv_bfloat16 g_Bh[(size_t)3 * HID * HID];
__device__ __nv_bfloat16 g_Bl[(size_t)3 * HID * HID];

// ---------------------------------------------------------------------------
// PTX helpers (family-compatible: mma.sync / ldmatrix / cp.async only)
// ---------------------------------------------------------------------------
__device__ __forceinline__ uint32_t smem_u32(const void* p) {
    uint32_t a;
    asm("{ .reg .u64 t; cvta.to.shared.u64 t, %1; cvt.u32.u64 %0, t; }"
        : "=r"(a) : "l"(p));
    return a;
}

#define CP_ASYNC16(dst, src) \
    asm volatile("cp.async.cg.shared.global [%0], [%1], 16;" \
                 :: "r"(dst), "l"(src) : "memory")
#define CP_COMMIT() asm volatile("cp.async.commit_group;" ::: "memory")
#define CP_WAIT1()  asm volatile("cp.async.wait_group 1;" ::: "memory")
#define CP_WAIT0()  asm volatile("cp.async.wait_group 0;" ::: "memory")

#define LDSM_X4(r0, r1, r2, r3, addr) \
    asm volatile("ldmatrix.sync.aligned.m8n8.x4.shared.b16 {%0,%1,%2,%3}, [%4];" \
                 : "=r"(r0), "=r"(r1), "=r"(r2), "=r"(r3) : "r"(addr))

__device__ __forceinline__ void mma_bf16(float* c, const uint32_t* a,
                                         uint32_t b0, uint32_t b1) {
    asm volatile(
        "mma.sync.aligned.m16n8k16.row.col.f32.bf16.bf16.f32 "
        "{%0,%1,%2,%3}, {%4,%5,%6,%7}, {%8,%9}, {%0,%1,%2,%3};"
        : "+f"(c[0]), "+f"(c[1]), "+f"(c[2]), "+f"(c[3])
        : "r"(a[0]), "r"(a[1]), "r"(a[2]), "r"(a[3]), "r"(b0), "r"(b1));
}

// ---------------------------------------------------------------------------
// Prep kernels: fp32 -> (hi, lo) bf16 split
// ---------------------------------------------------------------------------
__global__ void convert_hilo(const float* __restrict__ x,
                             __nv_bfloat16* __restrict__ hi,
                             __nv_bfloat16* __restrict__ lo, int n4) {
    int i = blockIdx.x * blockDim.x + threadIdx.x;
    if (i >= n4) return;
    float4 v = ((const float4*)x)[i];
    __nv_bfloat16 h0 = __float2bfloat16_rn(v.x);
    __nv_bfloat16 h1 = __float2bfloat16_rn(v.y);
    __nv_bfloat16 h2 = __float2bfloat16_rn(v.z);
    __nv_bfloat16 h3 = __float2bfloat16_rn(v.w);
    __nv_bfloat162* hp = (__nv_bfloat162*)(hi + (size_t)i * 4);
    hp[0] = __nv_bfloat162(h0, h1);
    hp[1] = __nv_bfloat162(h2, h3);
    __nv_bfloat162* lp = (__nv_bfloat162*)(lo + (size_t)i * 4);
    lp[0] = __nv_bfloat162(__float2bfloat16_rn(v.x - __bfloat162float(h0)),
                           __float2bfloat16_rn(v.y - __bfloat162float(h1)));
    lp[1] = __nv_bfloat162(__float2bfloat16_rn(v.z - __bfloat162float(h2)),
                           __float2bfloat16_rn(v.w - __bfloat162float(h3)));
}

// W [K,N] fp32 row-major  ->  Wt hi/lo [N,K] bf16 row-major (K-major for MMA)
__global__ void transpose_hilo(const float* __restrict__ W,
                               __nv_bfloat16* __restrict__ Th,
                               __nv_bfloat16* __restrict__ Tl, int K, int N) {
    __shared__ float t[32][33];
    int tx = threadIdx.x, ty = threadIdx.y;
    int n0 = blockIdx.x * 32, k0 = blockIdx.y * 32;
#pragma unroll
    for (int j = 0; j < 4; j++) {
        int k = k0 + ty + j * 8;
        t[ty + j * 8][tx] = W[(size_t)k * N + n0 + tx];
    }
    __syncthreads();
#pragma unroll
    for (int j = 0; j < 4; j++) {
        int n = n0 + ty + j * 8;
        float v = t[tx][ty + j * 8];
        __nv_bfloat16 h = __float2bfloat16_rn(v);
        Th[(size_t)n * K + k0 + tx] = h;
        Tl[(size_t)n * K + k0 + tx] = __float2bfloat16_rn(v - __bfloat162float(h));
    }
}

// ---------------------------------------------------------------------------
// mma.sync bf16x3 GEMM: C[M,N] = A[M,K] @ Wt^T + bias, Wt stored [N,K]
// 128x128 CTA tile, 8 warps (4m x 2n), warp tile 32x64, K-chunk 32.
// cp.async double-buffered SMEM; rows padded to 80B (conflict-free ldmatrix).
// ---------------------------------------------------------------------------
#define CH_K   32
#define LDT_B  80                        // bytes per smem row (32 bf16 + pad)
#define TILE_B (128 * LDT_B)             // 10240 B per tile
#define STAGE_B (4 * TILE_B)             // Ah, Al, Bh, Bl = 40960 B
#define GEMM_SMEM (2 * STAGE_B)          // 81920 B

__device__ __forceinline__ void issue_tile(const __nv_bfloat16* __restrict__ g,
                                           int row0, int K, int kt,
                                           uint32_t smem, int tid) {
#pragma unroll
    for (int i = 0; i < 2; i++) {
        int v = tid + i * 256;
        int r = v >> 2, c = v & 3;
        const __nv_bfloat16* src = g + (size_t)(row0 + r) * K + kt + c * 8;
        uint32_t dst = smem + (uint32_t)(r * LDT_B + c * 16);
        CP_ASYNC16(dst, src);
    }
}

__global__ __launch_bounds__(256, 1) void gemm_tc(
    const __nv_bfloat16* __restrict__ Ah, const __nv_bfloat16* __restrict__ Al,
    const __nv_bfloat16* __restrict__ Bh, const __nv_bfloat16* __restrict__ Bl,
    const float* __restrict__ bias, float* __restrict__ C,
    int M, int N, int K)
{
    extern __shared__ char sm[];
    uint32_t sb = smem_u32(sm);
    const int tid  = threadIdx.x;
    const int lane = tid & 31;
    const int wid  = tid >> 5;
    const int m0   = (wid & 3) * 32;     // warp row base in tile
    const int n0   = (wid >> 2) * 64;    // warp col base in tile
    const int bm   = blockIdx.y * 128;
    const int bn   = blockIdx.x * 128;

    float acc[2][8][4];
#pragma unroll
    for (int i = 0; i < 2; i++)
#pragma unroll
        for (int j = 0; j < 8; j++)
#pragma unroll
            for (int q = 0; q < 4; q++) acc[i][j][q] = 0.f;

    // ldmatrix per-lane address components
    const uint32_t a_row  = lane & 15;
    const uint32_t a_koff = ((lane >> 4) & 1) * 16;           // bytes
    const uint32_t b_rin  = ((lane >> 4) & 1) * 8 + (lane & 7);
    const uint32_t b_koff = ((lane >> 3) & 1) * 16;           // bytes

    const int NCH = K / CH_K;

    // prologue: stage chunks 0, 1
#pragma unroll
    for (int p = 0; p < 2; p++) {
        uint32_t bb = sb + p * STAGE_B;
        issue_tile(Ah, bm, K, p * CH_K, bb + 0 * TILE_B, tid);
        issue_tile(Al, bm, K, p * CH_K, bb + 1 * TILE_B, tid);
        issue_tile(Bh, bn, K, p * CH_K, bb + 2 * TILE_B, tid);
        issue_tile(Bl, bn, K, p * CH_K, bb + 3 * TILE_B, tid);
        CP_COMMIT();
    }

    for (int c = 0; c < NCH; c++) {
        if (c + 1 < NCH) { CP_WAIT1(); } else { CP_WAIT0(); }
        __syncthreads();

        uint32_t bb   = sb + (uint32_t)(c & 1) * STAGE_B;
        uint32_t Ah_s = bb + 0 * TILE_B;
        uint32_t Al_s = bb + 1 * TILE_B;
        uint32_t Bh_s = bb + 2 * TILE_B;
        uint32_t Bl_s = bb + 3 * TILE_B;

#pragma unroll
        for (int kk = 0; kk < 2; kk++) {
            uint32_t ah[2][4], al[2][4];
#pragma unroll
            for (int i = 0; i < 2; i++) {
                uint32_t ro = (uint32_t)(m0 + i * 16 + a_row) * LDT_B
                              + kk * 32 + a_koff;
                LDSM_X4(ah[i][0], ah[i][1], ah[i][2], ah[i][3], Ah_s + ro);
                LDSM_X4(al[i][0], al[i][1], al[i][2], al[i][3], Al_s + ro);
            }
#pragma unroll
            for (int jp = 0; jp < 4; jp++) {
                uint32_t ro = (uint32_t)(n0 + jp * 16 + b_rin) * LDT_B
                              + kk * 32 + b_koff;
                uint32_t bh[4], bl[4];
                LDSM_X4(bh[0], bh[1], bh[2], bh[3], Bh_s + ro);
                LDSM_X4(bl[0], bl[1], bl[2], bl[3], Bl_s + ro);
#pragma unroll
                for (int i = 0; i < 2; i++) {
                    mma_bf16(acc[i][jp * 2 + 0], ah[i], bh[0], bh[1]);
                    mma_bf16(acc[i][jp * 2 + 0], ah[i], bl[0], bl[1]);
                    mma_bf16(acc[i][jp * 2 + 0], al[i], bh[0], bh[1]);
                    mma_bf16(acc[i][jp * 2 + 1], ah[i], bh[2], bh[3]);
                    mma_bf16(acc[i][jp * 2 + 1], ah[i], bl[2], bl[3]);
                    mma_bf16(acc[i][jp * 2 + 1], al[i], bh[2], bh[3]);
                }
            }
        }
        __syncthreads();
        if (c + 2 < NCH) {
            uint32_t nb = sb + (uint32_t)(c & 1) * STAGE_B;
            int kt = (c + 2) * CH_K;
            issue_tile(Ah, bm, K, kt, nb + 0 * TILE_B, tid);
            issue_tile(Al, bm, K, kt, nb + 1 * TILE_B, tid);
            issue_tile(Bh, bn, K, kt, nb + 2 * TILE_B, tid);
            issue_tile(Bl, bn, K, kt, nb + 3 * TILE_B, tid);
        }
        CP_COMMIT();   // keep group count in lockstep even when empty
    }

    // epilogue: acc -> global with bias
    const int rrow = lane >> 2;          // 0..7
    const int rcol = (lane & 3) * 2;
#pragma unroll
    for (int i = 0; i < 2; i++) {
        int r_lo = bm + m0 + i * 16 + rrow;
        int r_hi = r_lo + 8;
#pragma unroll
        for (int j = 0; j < 8; j++) {
            int cc = bn + n0 + j * 8 + rcol;
            float b0 = bias[cc], b1 = bias[cc + 1];
            float2 v0 = make_float2(acc[i][j][0] + b0, acc[i][j][1] + b1);
            float2 v1 = make_float2(acc[i][j][2] + b0, acc[i][j][3] + b1);
            *(float2*)&C[(size_t)r_lo * N + cc] = v0;
            *(float2*)&C[(size_t)r_hi * N + cc] = v1;
        }
    }
}

// ---------------------------------------------------------------------------
// Flash attention (causal), fp32 — unchanged from R1 (passing, 1.2e-6)
// ---------------------------------------------------------------------------
#define BM 64
#define BN 64
#define QS_LD 65
#define KS_LD 65
#define PS_LD 68
#define FLASH_SMEM ((BM * QS_LD + BN * KS_LD + BN * HD + BM * PS_LD) * 4)

__device__ __forceinline__ float redmax16(float v) {
    v = fmaxf(v, __shfl_xor_sync(0xffffffffu, v, 8));
    v = fmaxf(v, __shfl_xor_sync(0xffffffffu, v, 4));
    v = fmaxf(v, __shfl_xor_sync(0xffffffffu, v, 2));
    v = fmaxf(v, __shfl_xor_sync(0xffffffffu, v, 1));
    return v;
}
__device__ __forceinline__ float redsum16(float v) {
    v += __shfl_xor_sync(0xffffffffu, v, 8);
    v += __shfl_xor_sync(0xffffffffu, v, 4);
    v += __shfl_xor_sync(0xffffffffu, v, 2);
    v += __shfl_xor_sync(0xffffffffu, v, 1);
    return v;
}

__global__ __launch_bounds__(256) void flash_attn(
    const float* __restrict__ qkv, float* __restrict__ ctx)
{
    extern __shared__ float smf[];
    float* Qs = smf;
    float* Ks = Qs + BM * QS_LD;
    float* Vs = Ks + BN * KS_LD;
    float* Ps = Vs + BN * HD;

    const int tid = threadIdx.x;
    const int qb = (int)gridDim.x - 1 - (int)blockIdx.x;
    const int h  = blockIdx.y;
    const int b  = blockIdx.z;
    const int tx = tid & 15;
    const int ty = tid >> 4;

#pragma unroll
    for (int it = 0; it < 4; it++) {
        int idx = tid + it * 256;
        int r   = idx >> 4;
        int c   = (idx & 15) << 2;
        const float* src =
            qkv + (size_t)(b * S_LEN + qb * BM + r) * (3 * HID) + h * HD + c;
        float4 v = *(const float4*)src;
        Qs[r * QS_LD + c + 0] = v.x;
        Qs[r * QS_LD + c + 1] = v.y;
        Qs[r * QS_LD + c + 2] = v.z;
        Qs[r * QS_LD + c + 3] = v.w;
    }

    float m_i[4], l_i[4], o[4][4];
#pragma unroll
    for (int i = 0; i < 4; i++) {
        m_i[i] = -1e30f;
        l_i[i] = 0.f;
#pragma unroll
        for (int j = 0; j < 4; j++) o[i][j] = 0.f;
    }

    for (int kb = 0; kb <= qb; kb++) {
        __syncthreads();
#pragma unroll
        for (int it = 0; it < 4; it++) {
            int idx = tid + it * 256;
            int r   = idx >> 4;
            int c   = (idx & 15) << 2;
            const float* base =
                qkv + (size_t)(b * S_LEN + kb * BN + r) * (3 * HID) + h * HD + c;
            float4 kv = *(const float4*)(base + HID);
            Ks[r * KS_LD + c + 0] = kv.x;
            Ks[r * KS_LD + c + 1] = kv.y;
            Ks[r * KS_LD + c + 2] = kv.z;
            Ks[r * KS_LD + c + 3] = kv.w;
            *(float4*)&Vs[r * HD + c] = *(const float4*)(base + 2 * HID);
        }
        __syncthreads();

        float s[4][4];
#pragma unroll
        for (int i = 0; i < 4; i++)
#pragma unroll
            for (int j = 0; j < 4; j++) s[i][j] = 0.f;

#pragma unroll 4
        for (int d = 0; d < HD; d++) {
            float a0 = Qs[(ty * 4 + 0) * QS_LD + d];
            float a1 = Qs[(ty * 4 + 1) * QS_LD + d];
            float a2 = Qs[(ty * 4 + 2) * QS_LD + d];
            float a3 = Qs[(ty * 4 + 3) * QS_LD + d];
            float b0 = Ks[(tx * 4 + 0) * KS_LD + d];
            float b1 = Ks[(tx * 4 + 1) * KS_LD + d];
            float b2 = Ks[(tx * 4 + 2) * KS_LD + d];
            float b3 = Ks[(tx * 4 + 3) * KS_LD + d];
            s[0][0] = fmaf(a0, b0, s[0][0]); s[0][1] = fmaf(a0, b1, s[0][1]);
            s[0][2] = fmaf(a0, b2, s[0][2]); s[0][3] = fmaf(a0, b3, s[0][3]);
            s[1][0] = fmaf(a1, b0, s[1][0]); s[1][1] = fmaf(a1, b1, s[1][1]);
            s[1][2] = fmaf(a1, b2, s[1][2]); s[1][3] = fmaf(a1, b3, s[1][3]);
            s[2][0] = fmaf(a2, b0, s[2][0]); s[2][1] = fmaf(a2, b1, s[2][1]);
            s[2][2] = fmaf(a2, b2, s[2][2]); s[2][3] = fmaf(a2, b3, s[2][3]);
            s[3][0] = fmaf(a3, b0, s[3][0]); s[3][1] = fmaf(a3, b1, s[3][1]);
            s[3][2] = fmaf(a3, b2, s[3][2]); s[3][3] = fmaf(a3, b3, s[3][3]);
        }

        const bool diag = (kb == qb);
#pragma unroll
        for (int i = 0; i < 4; i++) {
#pragma unroll
            for (int j = 0; j < 4; j++) {
                s[i][j] *= 0.125f;
                if (diag && (tx * 4 + j) > (ty * 4 + i)) s[i][j] = -1e30f;
            }
        }

#pragma unroll
        for (int i = 0; i < 4; i++) {
            float rm = fmaxf(fmaxf(s[i][0], s[i][1]), fmaxf(s[i][2], s[i][3]));
            rm = redmax16(rm);
            float mn   = fmaxf(m_i[i], rm);
            float corr = expf(m_i[i] - mn);
            float p0 = expf(s[i][0] - mn);
            float p1 = expf(s[i][1] - mn);
            float p2 = expf(s[i][2] - mn);
            float p3 = expf(s[i][3] - mn);
            float rs = redsum16(p0 + p1 + p2 + p3);
            l_i[i] = l_i[i] * corr + rs;
            m_i[i] = mn;
#pragma unroll
            for (int j = 0; j < 4; j++) o[i][j] *= corr;
            float4 pv = make_float4(p0, p1, p2, p3);
            *(float4*)&Ps[(ty * 4 + i) * PS_LD + tx * 4] = pv;
        }
        __syncthreads();

#pragma unroll 4
        for (int c = 0; c < BN; c++) {
            float4 vv = *(const float4*)&Vs[c * HD + tx * 4];
            float a0 = Ps[(ty * 4 + 0) * PS_LD + c];
            float a1 = Ps[(ty * 4 + 1) * PS_LD + c];
            float a2 = Ps[(ty * 4 + 2) * PS_LD + c];
            float a3 = Ps[(ty * 4 + 3) * PS_LD + c];
            o[0][0] = fmaf(a0, vv.x, o[0][0]); o[0][1] = fmaf(a0, vv.y, o[0][1]);
            o[0][2] = fmaf(a0, vv.z, o[0][2]); o[0][3] = fmaf(a0, vv.w, o[0][3]);
            o[1][0] = fmaf(a1, vv.x, o[1][0]); o[1][1] = fmaf(a1, vv.y, o[1][1]);
            o[1][2] = fmaf(a1, vv.z, o[1][2]); o[1][3] = fmaf(a1, vv.w, o[1][3]);
            o[2][0] = fmaf(a2, vv.x, o[2][0]); o[2][1] = fmaf(a2, vv.y, o[2][1]);
            o[2][2] = fmaf(a2, vv.z, o[2][2]); o[2][3] = fmaf(a2, vv.w, o[2][3]);
            o[3][0] = fmaf(a3, vv.x, o[3][0]); o[3][1] = fmaf(a3, vv.y, o[3][1]);
            o[3][2] = fmaf(a3, vv.z, o[3][2]); o[3][3] = fmaf(a3, vv.w, o[3][3]);
        }
    }

#pragma unroll
    for (int i = 0; i < 4; i++) {
        float inv = 1.0f / l_i[i];
        float4 ov = make_float4(o[i][0] * inv, o[i][1] * inv,
                                o[i][2] * inv, o[i][3] * inv);
        size_t tok = (size_t)(b * S_LEN + qb * BM + ty * 4 + i);
        *(float4*)&ctx[tok * HID + h * HD + tx * 4] = ov;
    }
}

// ---------------------------------------------------------------------------
extern "C" void kernel_launch(void* const* d_in, const int* in_sizes, int n_in,
                              void* d_out, int out_size)
{
    (void)in_sizes; (void)n_in; (void)out_size;
    const float* hidden  = (const float*)d_in[0];
    // d_in[1] = ltor_mask: exactly causal lower-triangular; handled analytically
    const float* W_qkv   = (const float*)d_in[2];
    const float* b_qkv   = (const float*)d_in[3];
    const float* W_dense = (const float*)d_in[4];
    const float* b_dense = (const float*)d_in[5];
    float* out = (float*)d_out;

    float *qkv_ptr = nullptr, *ctx_ptr = nullptr;
    __nv_bfloat16 *ah, *al, *bh, *bl;
    cudaGetSymbolAddress((void**)&qkv_ptr, g_qkv);
    cudaGetSymbolAddress((void**)&ctx_ptr, g_ctx);
    cudaGetSymbolAddress((void**)&ah, g_Ah);
    cudaGetSymbolAddress((void**)&al, g_Al);
    cudaGetSymbolAddress((void**)&bh, g_Bh);
    cudaGetSymbolAddress((void**)&bl, g_Bl);

    cudaFuncSetAttribute(gemm_tc,
                         cudaFuncAttributeMaxDynamicSharedMemorySize, GEMM_SMEM);
    cudaFuncSetAttribute(flash_attn,
                         cudaFuncAttributeMaxDynamicSharedMemorySize, FLASH_SMEM);

    // 1) split hidden -> bf16 hi/lo
    {
        int n4 = M_TOK * HID / 4;
        convert_hilo<<<(n4 + 255) / 256, 256>>>(hidden, ah, al, n4);
    }
    // 2) transpose+split W_qkv [K=1024, N=3072] -> [N][K]
    {
        dim3 grid(3 * HID / 32, HID / 32);
        transpose_hilo<<<grid, dim3(32, 8)>>>(W_qkv, bh, bl, HID, 3 * HID);
    }
    // 3) QKV GEMM (mma.sync bf16x3)
    {
        dim3 grid(3 * HID / 128, M_TOK / 128);
        gemm_tc<<<grid, 256, GEMM_SMEM>>>(ah, al, bh, bl, b_qkv, qkv_ptr,
                                          M_TOK, 3 * HID, HID);
    }
    // 4) causal flash attention -> ctx
    {
        dim3 grid(S_LEN / BM, NH, B_SZ);
        flash_attn<<<grid, 256, FLASH_SMEM>>>(qkv_ptr, ctx_ptr);
    }
    // 5) split ctx -> bf16 hi/lo
    {
        int n4 = M_TOK * HID / 4;
        convert_hilo<<<(n4 + 255) / 256, 256>>>(ctx_ptr, ah, al, n4);
    }
    // 6) transpose+split W_dense [1024, 1024]
    {
        dim3 grid(HID / 32, HID / 32);
        transpose_hilo<<<grid, dim3(32, 8)>>>(W_dense, bh, bl, HID, HID);
    }
    // 7) dense GEMM (mma.sync bf16x3)
    {
        dim3 grid(HID / 128, M_TOK / 128);
        gemm_tc<<<grid, 256, GEMM_SMEM>>>(ah, al, bh, bl, b_dense, out,
                                          M_TOK, HID, HID);
    }
}

// round 4
// speedup vs baseline: 2.2700x; 1.6943x over previous
#include <cuda_runtime.h>
#include <cuda_bf16.h>
#include <cstdint>
#include <math.h>

#define B_SZ  2
#define S_LEN 2048
#define HID   1024
#define NH    16
#define HD    64
#define M_TOK (B_SZ * S_LEN)     // 4096

// ---------------------------------------------------------------------------
// Scratch (__device__ globals per allocation-free rule)
// ---------------------------------------------------------------------------
__device__ float g_qkv[(size_t)M_TOK * 3 * HID];            // 48 MB
__device__ float g_ctx[(size_t)M_TOK * HID];                // 16 MB
__device__ __nv_bfloat16 g_Ah[(size_t)M_TOK * HID];
__device__ __nv_bfloat16 g_Al[(size_t)M_TOK * HID];
__device__ __nv_bfloat16 g_Bh[(size_t)3 * HID * HID];
__device__ __nv_bfloat16 g_Bl[(size_t)3 * HID * HID];
// per-head attention operands [b][h][s][hd], bf16 hi/lo
#define HELEMS ((size_t)B_SZ * NH * S_LEN * HD)
__device__ __nv_bfloat16 g_Qh[HELEMS], g_Ql[HELEMS];
__device__ __nv_bfloat16 g_Kh[HELEMS], g_Kl[HELEMS];
__device__ __nv_bfloat16 g_Vh[HELEMS], g_Vl[HELEMS];

// ---------------------------------------------------------------------------
// PTX helpers (family-compatible: mma.sync / ldmatrix / cp.async only)
// ---------------------------------------------------------------------------
__device__ __forceinline__ uint32_t smem_u32(const void* p) {
    uint32_t a;
    asm("{ .reg .u64 t; cvta.to.shared.u64 t, %1; cvt.u32.u64 %0, t; }"
        : "=r"(a) : "l"(p));
    return a;
}

#define CP_ASYNC16(dst, src) \
    asm volatile("cp.async.cg.shared.global [%0], [%1], 16;" \
                 :: "r"(dst), "l"(src) : "memory")
#define CP_COMMIT() asm volatile("cp.async.commit_group;" ::: "memory")
#define CP_WAIT1()  asm volatile("cp.async.wait_group 1;" ::: "memory")
#define CP_WAIT0()  asm volatile("cp.async.wait_group 0;" ::: "memory")

#define LDSM_X4(r0, r1, r2, r3, addr) \
    asm volatile("ldmatrix.sync.aligned.m8n8.x4.shared.b16 {%0,%1,%2,%3}, [%4];" \
                 : "=r"(r0), "=r"(r1), "=r"(r2), "=r"(r3) : "r"(addr))
#define LDSM_X4_T(r0, r1, r2, r3, addr) \
    asm volatile("ldmatrix.sync.aligned.m8n8.x4.trans.shared.b16 {%0,%1,%2,%3}, [%4];" \
                 : "=r"(r0), "=r"(r1), "=r"(r2), "=r"(r3) : "r"(addr))

__device__ __forceinline__ void mma_bf16(float* c, const uint32_t* a,
                                         uint32_t b0, uint32_t b1) {
    asm volatile(
        "mma.sync.aligned.m16n8k16.row.col.f32.bf16.bf16.f32 "
        "{%0,%1,%2,%3}, {%4,%5,%6,%7}, {%8,%9}, {%0,%1,%2,%3};"
        : "+f"(c[0]), "+f"(c[1]), "+f"(c[2]), "+f"(c[3])
        : "r"(a[0]), "r"(a[1]), "r"(a[2]), "r"(a[3]), "r"(b0), "r"(b1));
}

// (a, b) -> packed bf16x2 hi + residual bf16x2 lo
__device__ __forceinline__ void split2(float a, float b,
                                       uint32_t& hi, uint32_t& lo) {
    __nv_bfloat162 h = __floats2bfloat162_rn(a, b);
    hi = *reinterpret_cast<uint32_t*>(&h);
    __nv_bfloat162 l = __floats2bfloat162_rn(a - __bfloat162float(h.x),
                                             b - __bfloat162float(h.y));
    lo = *reinterpret_cast<uint32_t*>(&l);
}

// ---------------------------------------------------------------------------
// Prep kernels
// ---------------------------------------------------------------------------
__global__ void convert_hilo(const float* __restrict__ x,
                             __nv_bfloat16* __restrict__ hi,
                             __nv_bfloat16* __restrict__ lo, int n4) {
    int i = blockIdx.x * blockDim.x + threadIdx.x;
    if (i >= n4) return;
    float4 v = ((const float4*)x)[i];
    uint32_t h0, l0, h1, l1;
    split2(v.x, v.y, h0, l0);
    split2(v.z, v.w, h1, l1);
    uint32_t* hp = (uint32_t*)(hi + (size_t)i * 4); hp[0] = h0; hp[1] = h1;
    uint32_t* lp = (uint32_t*)(lo + (size_t)i * 4); lp[0] = l0; lp[1] = l1;
}

// W [K,N] fp32 row-major  ->  Wt hi/lo [N,K] bf16 row-major (K-major for MMA)
__global__ void transpose_hilo(const float* __restrict__ W,
                               __nv_bfloat16* __restrict__ Th,
                               __nv_bfloat16* __restrict__ Tl, int K, int N) {
    __shared__ float t[32][33];
    int tx = threadIdx.x, ty = threadIdx.y;
    int n0 = blockIdx.x * 32, k0 = blockIdx.y * 32;
#pragma unroll
    for (int j = 0; j < 4; j++) {
        int k = k0 + ty + j * 8;
        t[ty + j * 8][tx] = W[(size_t)k * N + n0 + tx];
    }
    __syncthreads();
#pragma unroll
    for (int j = 0; j < 4; j++) {
        int n = n0 + ty + j * 8;
        float v = t[tx][ty + j * 8];
        __nv_bfloat16 h = __float2bfloat16_rn(v);
        Th[(size_t)n * K + k0 + tx] = h;
        Tl[(size_t)n * K + k0 + tx] = __float2bfloat16_rn(v - __bfloat162float(h));
    }
}

// qkv fp32 [tok][3H] -> per-head bf16 hi/lo [b][h][s][hd]; Q scaled by 1/8
__global__ void split_qkv_attn(const float* __restrict__ qkv,
    __nv_bfloat16* __restrict__ Qh, __nv_bfloat16* __restrict__ Ql,
    __nv_bfloat16* __restrict__ Kh, __nv_bfloat16* __restrict__ Kl,
    __nv_bfloat16* __restrict__ Vh, __nv_bfloat16* __restrict__ Vl)
{
    int i = blockIdx.x * blockDim.x + threadIdx.x;   // over M_TOK*HID/4
    int d4  = i & 15;
    int h   = (i >> 4) & 15;
    int tok = i >> 8;
    int b = tok >> 11, s = tok & 2047;
    size_t src = (size_t)tok * (3 * HID) + h * HD + d4 * 4;
    size_t dst = (((size_t)(b * NH + h)) * S_LEN + s) * HD + d4 * 4;

    float4 q = *(const float4*)(qkv + src);
    q.x *= 0.125f; q.y *= 0.125f; q.z *= 0.125f; q.w *= 0.125f;
    float4 k = *(const float4*)(qkv + src + HID);
    float4 v = *(const float4*)(qkv + src + 2 * HID);

    uint32_t h0, l0, h1, l1;
    split2(q.x, q.y, h0, l0); split2(q.z, q.w, h1, l1);
    ((uint32_t*)(Qh + dst))[0] = h0; ((uint32_t*)(Qh + dst))[1] = h1;
    ((uint32_t*)(Ql + dst))[0] = l0; ((uint32_t*)(Ql + dst))[1] = l1;
    split2(k.x, k.y, h0, l0); split2(k.z, k.w, h1, l1);
    ((uint32_t*)(Kh + dst))[0] = h0; ((uint32_t*)(Kh + dst))[1] = h1;
    ((uint32_t*)(Kl + dst))[0] = l0; ((uint32_t*)(Kl + dst))[1] = l1;
    split2(v.x, v.y, h0, l0); split2(v.z, v.w, h1, l1);
    ((uint32_t*)(Vh + dst))[0] = h0; ((uint32_t*)(Vh + dst))[1] = h1;
    ((uint32_t*)(Vl + dst))[0] = l0; ((uint32_t*)(Vl + dst))[1] = l1;
}

// ---------------------------------------------------------------------------
// mma.sync bf16x3 GEMM (validated in R3): C = A @ Wt^T + bias, Wt [N,K]
// ---------------------------------------------------------------------------
#define CH_K   32
#define LDT_B  80
#define TILE_B (128 * LDT_B)
#define STAGE_B (4 * TILE_B)
#define GEMM_SMEM (2 * STAGE_B)

__device__ __forceinline__ void issue_tile(const __nv_bfloat16* __restrict__ g,
                                           int row0, int K, int kt,
                                           uint32_t smem, int tid) {
#pragma unroll
    for (int i = 0; i < 2; i++) {
        int v = tid + i * 256;
        int r = v >> 2, c = v & 3;
        const __nv_bfloat16* src = g + (size_t)(row0 + r) * K + kt + c * 8;
        uint32_t dst = smem + (uint32_t)(r * LDT_B + c * 16);
        CP_ASYNC16(dst, src);
    }
}

__global__ __launch_bounds__(256, 1) void gemm_tc(
    const __nv_bfloat16* __restrict__ Ah, const __nv_bfloat16* __restrict__ Al,
    const __nv_bfloat16* __restrict__ Bh, const __nv_bfloat16* __restrict__ Bl,
    const float* __restrict__ bias, float* __restrict__ C,
    int M, int N, int K)
{
    extern __shared__ char sm[];
    uint32_t sb = smem_u32(sm);
    const int tid  = threadIdx.x;
    const int lane = tid & 31;
    const int wid  = tid >> 5;
    const int m0   = (wid & 3) * 32;
    const int n0   = (wid >> 2) * 64;
    const int bm   = blockIdx.y * 128;
    const int bn   = blockIdx.x * 128;

    float acc[2][8][4];
#pragma unroll
    for (int i = 0; i < 2; i++)
#pragma unroll
        for (int j = 0; j < 8; j++)
#pragma unroll
            for (int q = 0; q < 4; q++) acc[i][j][q] = 0.f;

    const uint32_t a_row  = lane & 15;
    const uint32_t a_koff = ((lane >> 4) & 1) * 16;
    const uint32_t b_rin  = ((lane >> 4) & 1) * 8 + (lane & 7);
    const uint32_t b_koff = ((lane >> 3) & 1) * 16;

    const int NCH = K / CH_K;

#pragma unroll
    for (int p = 0; p < 2; p++) {
        uint32_t bb = sb + p * STAGE_B;
        issue_tile(Ah, bm, K, p * CH_K, bb + 0 * TILE_B, tid);
        issue_tile(Al, bm, K, p * CH_K, bb + 1 * TILE_B, tid);
        issue_tile(Bh, bn, K, p * CH_K, bb + 2 * TILE_B, tid);
        issue_tile(Bl, bn, K, p * CH_K, bb + 3 * TILE_B, tid);
        CP_COMMIT();
    }

    for (int c = 0; c < NCH; c++) {
        if (c + 1 < NCH) { CP_WAIT1(); } else { CP_WAIT0(); }
        __syncthreads();

        uint32_t bb   = sb + (uint32_t)(c & 1) * STAGE_B;
        uint32_t Ah_s = bb + 0 * TILE_B;
        uint32_t Al_s = bb + 1 * TILE_B;
        uint32_t Bh_s = bb + 2 * TILE_B;
        uint32_t Bl_s = bb + 3 * TILE_B;

#pragma unroll
        for (int kk = 0; kk < 2; kk++) {
            uint32_t ah[2][4], al[2][4];
#pragma unroll
            for (int i = 0; i < 2; i++) {
                uint32_t ro = (uint32_t)(m0 + i * 16 + a_row) * LDT_B
                              + kk * 32 + a_koff;
                LDSM_X4(ah[i][0], ah[i][1], ah[i][2], ah[i][3], Ah_s + ro);
                LDSM_X4(al[i][0], al[i][1], al[i][2], al[i][3], Al_s + ro);
            }
#pragma unroll
            for (int jp = 0; jp < 4; jp++) {
                uint32_t ro = (uint32_t)(n0 + jp * 16 + b_rin) * LDT_B
                              + kk * 32 + b_koff;
                uint32_t bh[4], bl[4];
                LDSM_X4(bh[0], bh[1], bh[2], bh[3], Bh_s + ro);
                LDSM_X4(bl[0], bl[1], bl[2], bl[3], Bl_s + ro);
#pragma unroll
                for (int i = 0; i < 2; i++) {
                    mma_bf16(acc[i][jp * 2 + 0], ah[i], bh[0], bh[1]);
                    mma_bf16(acc[i][jp * 2 + 0], ah[i], bl[0], bl[1]);
                    mma_bf16(acc[i][jp * 2 + 0], al[i], bh[0], bh[1]);
                    mma_bf16(acc[i][jp * 2 + 1], ah[i], bh[2], bh[3]);
                    mma_bf16(acc[i][jp * 2 + 1], ah[i], bl[2], bl[3]);
                    mma_bf16(acc[i][jp * 2 + 1], al[i], bh[2], bh[3]);
                }
            }
        }
        __syncthreads();
        if (c + 2 < NCH) {
            uint32_t nb = sb + (uint32_t)(c & 1) * STAGE_B;
            int kt = (c + 2) * CH_K;
            issue_tile(Ah, bm, K, kt, nb + 0 * TILE_B, tid);
            issue_tile(Al, bm, K, kt, nb + 1 * TILE_B, tid);
            issue_tile(Bh, bn, K, kt, nb + 2 * TILE_B, tid);
            issue_tile(Bl, bn, K, kt, nb + 3 * TILE_B, tid);
        }
        CP_COMMIT();
    }

    const int rrow = lane >> 2;
    const int rcol = (lane & 3) * 2;
#pragma unroll
    for (int i = 0; i < 2; i++) {
        int r_lo = bm + m0 + i * 16 + rrow;
        int r_hi = r_lo + 8;
#pragma unroll
        for (int j = 0; j < 8; j++) {
            int cc = bn + n0 + j * 8 + rcol;
            float b0 = bias[cc], b1 = bias[cc + 1];
            float2 v0 = make_float2(acc[i][j][0] + b0, acc[i][j][1] + b1);
            float2 v1 = make_float2(acc[i][j][2] + b0, acc[i][j][3] + b1);
            *(float2*)&C[(size_t)r_lo * N + cc] = v0;
            *(float2*)&C[(size_t)r_hi * N + cc] = v1;
        }
    }
}

// ---------------------------------------------------------------------------
// Tensor-core flash attention (causal), bf16x3 for QK^T and PV.
// CTA = 128 q-rows x one (b,h). 8 warps, each owns m16 x all 64 keys/iter.
// K/V double-buffered via cp.async; Q fragments live in registers.
// ---------------------------------------------------------------------------
#define ALD      144                 // 64 bf16 (128B) + 16B pad per row
#define KV_TILE  (64 * ALD)          // 9216 B
#define FA_STAGE (4 * KV_TILE)       // Kh,Kl,Vh,Vl = 36864 B
#define FA_SMEM  (2 * FA_STAGE)      // 73728 B

__global__ __launch_bounds__(256, 2) void flash_tc(
    const __nv_bfloat16* __restrict__ Qh, const __nv_bfloat16* __restrict__ Ql,
    const __nv_bfloat16* __restrict__ Kh, const __nv_bfloat16* __restrict__ Kl,
    const __nv_bfloat16* __restrict__ Vh, const __nv_bfloat16* __restrict__ Vl,
    float* __restrict__ ctx)
{
    extern __shared__ char sm[];
    uint32_t sb = smem_u32(sm);
    const int tid = threadIdx.x, lane = tid & 31, wid = tid >> 5;
    const int qb = (int)gridDim.x - 1 - (int)blockIdx.x;   // big tiles first
    const int h = blockIdx.y, b = blockIdx.z;
    const size_t hoff = ((size_t)(b * NH + h)) * S_LEN * HD;
    const __nv_bfloat16* Qh_g = Qh + hoff + (size_t)qb * 128 * HD;
    const __nv_bfloat16* Ql_g = Ql + hoff + (size_t)qb * 128 * HD;
    const __nv_bfloat16* Kh_g = Kh + hoff;
    const __nv_bfloat16* Kl_g = Kl + hoff;
    const __nv_bfloat16* Vh_g = Vh + hoff;
    const __nv_bfloat16* Vl_g = Vl + hoff;

    // ---- stage Q once (hi at sb, lo at sb + 2*KV_TILE) and load fragments ----
#pragma unroll
    for (int i = 0; i < 4; i++) {
        int idx = tid + i * 256;          // 128 rows x 8 16B-chunks
        int r = idx >> 3, c = idx & 7;
        uint32_t d = sb + (uint32_t)(r * ALD + c * 16);
        CP_ASYNC16(d, Qh_g + r * HD + c * 8);
        CP_ASYNC16(d + 2 * KV_TILE, Ql_g + r * HD + c * 8);
    }
    CP_COMMIT(); CP_WAIT0(); __syncthreads();

    uint32_t qh[4][4], ql[4][4];
    {
        uint32_t base = sb + (uint32_t)((wid * 16 + (lane & 15)) * ALD)
                        + ((lane >> 4) & 1) * 16;
#pragma unroll
        for (int ks = 0; ks < 4; ks++) {
            LDSM_X4(qh[ks][0], qh[ks][1], qh[ks][2], qh[ks][3], base + ks * 32);
            LDSM_X4(ql[ks][0], ql[ks][1], ql[ks][2], ql[ks][3],
                    base + 2 * KV_TILE + ks * 32);
        }
    }
    __syncthreads();

    float o[8][4];
#pragma unroll
    for (int j = 0; j < 8; j++)
#pragma unroll
        for (int q = 0; q < 4; q++) o[j][q] = 0.f;
    float m[2] = {-1e30f, -1e30f}, l[2] = {0.f, 0.f};

    const uint32_t b_rin  = ((lane >> 4) & 1) * 8 + (lane & 7);
    const uint32_t b_koff = ((lane >> 3) & 1) * 16;
    const uint32_t v_row  = (lane & 7) + ((lane >> 3) & 1) * 8;
    const uint32_t v_coff = ((lane >> 4) & 1) * 16;

    const int nIter = 2 * qb + 2;

    // prologue: stage key-block 0 into buf 0
#pragma unroll
    for (int i = 0; i < 2; i++) {
        int idx = tid + i * 256;          // 64 rows x 8 chunks
        int r = idx >> 3, c = idx & 7;
        uint32_t d = sb + (uint32_t)(r * ALD + c * 16);
        int go = r * HD + c * 8;
        CP_ASYNC16(d + 0 * KV_TILE, Kh_g + go);
        CP_ASYNC16(d + 1 * KV_TILE, Kl_g + go);
        CP_ASYNC16(d + 2 * KV_TILE, Vh_g + go);
        CP_ASYNC16(d + 3 * KV_TILE, Vl_g + go);
    }
    CP_COMMIT();

    for (int it = 0; it < nIter; it++) {
        if (it + 1 < nIter) {
            uint32_t nb = sb + (uint32_t)((it + 1) & 1) * FA_STAGE;
            int kbase = (it + 1) * 64 * HD;
#pragma unroll
            for (int i = 0; i < 2; i++) {
                int idx = tid + i * 256;
                int r = idx >> 3, c = idx & 7;
                uint32_t d = nb + (uint32_t)(r * ALD + c * 16);
                int go = kbase + r * HD + c * 8;
                CP_ASYNC16(d + 0 * KV_TILE, Kh_g + go);
                CP_ASYNC16(d + 1 * KV_TILE, Kl_g + go);
                CP_ASYNC16(d + 2 * KV_TILE, Vh_g + go);
                CP_ASYNC16(d + 3 * KV_TILE, Vl_g + go);
            }
            CP_COMMIT();
            CP_WAIT1();
        } else {
            CP_WAIT0();
        }
        __syncthreads();

        uint32_t bb = sb + (uint32_t)(it & 1) * FA_STAGE;

        // ---- S = Q K^T (bf16x3) ----
        float s[8][4];
#pragma unroll
        for (int j = 0; j < 8; j++)
#pragma unroll
            for (int q = 0; q < 4; q++) s[j][q] = 0.f;

#pragma unroll
        for (int ks = 0; ks < 4; ks++) {
#pragma unroll
            for (int jp = 0; jp < 4; jp++) {
                uint32_t ka = bb + (uint32_t)((jp * 16 + b_rin) * ALD)
                              + ks * 32 + b_koff;
                uint32_t kh0, kh1, kh2, kh3, kl0, kl1, kl2, kl3;
                LDSM_X4(kh0, kh1, kh2, kh3, ka);
                LDSM_X4(kl0, kl1, kl2, kl3, ka + KV_TILE);
                mma_bf16(s[jp * 2 + 0], qh[ks], kh0, kh1);
                mma_bf16(s[jp * 2 + 0], qh[ks], kl0, kl1);
                mma_bf16(s[jp * 2 + 0], ql[ks], kh0, kh1);
                mma_bf16(s[jp * 2 + 1], qh[ks], kh2, kh3);
                mma_bf16(s[jp * 2 + 1], qh[ks], kl2, kl3);
                mma_bf16(s[jp * 2 + 1], ql[ks], kh2, kh3);
            }
        }

        // ---- causal mask (only at/past diagonal) ----
        if (it >= 2 * qb) {
            int col0 = it * 64 + (lane & 3) * 2;
#pragma unroll
            for (int rr = 0; rr < 2; rr++) {
                int row = qb * 128 + wid * 16 + (lane >> 2) + rr * 8;
#pragma unroll
                for (int j = 0; j < 8; j++) {
                    int c0 = col0 + j * 8;
                    if (c0 > row)     s[j][rr * 2 + 0] = -1e30f;
                    if (c0 + 1 > row) s[j][rr * 2 + 1] = -1e30f;
                }
            }
        }

        // ---- online softmax (2 rows per thread) ----
#pragma unroll
        for (int rr = 0; rr < 2; rr++) {
            float lm = -1e30f;
#pragma unroll
            for (int j = 0; j < 8; j++)
                lm = fmaxf(lm, fmaxf(s[j][rr * 2], s[j][rr * 2 + 1]));
            lm = fmaxf(lm, __shfl_xor_sync(0xffffffffu, lm, 1));
            lm = fmaxf(lm, __shfl_xor_sync(0xffffffffu, lm, 2));
            float mn = fmaxf(m[rr], lm);
            float corr = __expf(m[rr] - mn);
            float sum = 0.f;
#pragma unroll
            for (int j = 0; j < 8; j++) {
                float p0 = __expf(s[j][rr * 2 + 0] - mn);
                float p1 = __expf(s[j][rr * 2 + 1] - mn);
                s[j][rr * 2 + 0] = p0;
                s[j][rr * 2 + 1] = p1;
                sum += p0 + p1;
            }
            sum += __shfl_xor_sync(0xffffffffu, sum, 1);
            sum += __shfl_xor_sync(0xffffffffu, sum, 2);
            l[rr] = l[rr] * corr + sum;
            m[rr] = mn;
#pragma unroll
            for (int j = 0; j < 8; j++) {
                o[j][rr * 2 + 0] *= corr;
                o[j][rr * 2 + 1] *= corr;
            }
        }

        // ---- O += P V (bf16x3; P split hi/lo, V split hi/lo) ----
#pragma unroll
        for (int ks = 0; ks < 4; ks++) {
            uint32_t pah[4], pal[4];
            split2(s[2 * ks][0],     s[2 * ks][1],     pah[0], pal[0]);
            split2(s[2 * ks][2],     s[2 * ks][3],     pah[1], pal[1]);
            split2(s[2 * ks + 1][0], s[2 * ks + 1][1], pah[2], pal[2]);
            split2(s[2 * ks + 1][2], s[2 * ks + 1][3], pah[3], pal[3]);
            uint32_t va = bb + 2 * KV_TILE
                          + (uint32_t)((ks * 16 + v_row) * ALD) + v_coff;
#pragma unroll
            for (int ng = 0; ng < 4; ng++) {
                uint32_t vh0, vh1, vh2, vh3, vl0, vl1, vl2, vl3;
                LDSM_X4_T(vh0, vh1, vh2, vh3, va + ng * 32);
                LDSM_X4_T(vl0, vl1, vl2, vl3, va + ng * 32 + KV_TILE);
                mma_bf16(o[ng * 2 + 0], pah, vh0, vh1);
                mma_bf16(o[ng * 2 + 0], pah, vl0, vl1);
                mma_bf16(o[ng * 2 + 0], pal, vh0, vh1);
                mma_bf16(o[ng * 2 + 1], pah, vh2, vh3);
                mma_bf16(o[ng * 2 + 1], pah, vl2, vl3);
                mma_bf16(o[ng * 2 + 1], pal, vh2, vh3);
            }
        }
        __syncthreads();   // reads of this buf done before it is re-staged
    }

    // ---- epilogue: O/l -> ctx [tok][H] ----
#pragma unroll
    for (int rr = 0; rr < 2; rr++) {
        float inv = 1.0f / l[rr];
        int tok = b * S_LEN + qb * 128 + wid * 16 + (lane >> 2) + rr * 8;
#pragma unroll
        for (int j = 0; j < 8; j++) {
            int col = h * HD + j * 8 + (lane & 3) * 2;
            float2 v = make_float2(o[j][rr * 2 + 0] * inv,
                                   o[j][rr * 2 + 1] * inv);
            *(float2*)&ctx[(size_t)tok * HID + col] = v;
        }
    }
}

// ---------------------------------------------------------------------------
extern "C" void kernel_launch(void* const* d_in, const int* in_sizes, int n_in,
                              void* d_out, int out_size)
{
    (void)in_sizes; (void)n_in; (void)out_size;
    const float* hidden  = (const float*)d_in[0];
    // d_in[1] = ltor_mask: exactly causal lower-triangular; handled analytically
    const float* W_qkv   = (const float*)d_in[2];
    const float* b_qkv   = (const float*)d_in[3];
    const float* W_dense = (const float*)d_in[4];
    const float* b_dense = (const float*)d_in[5];
    float* out = (float*)d_out;

    float *qkv_ptr = nullptr, *ctx_ptr = nullptr;
    __nv_bfloat16 *ah, *al, *bh, *bl;
    __nv_bfloat16 *qhp, *qlp, *khp, *klp, *vhp, *vlp;
    cudaGetSymbolAddress((void**)&qkv_ptr, g_qkv);
    cudaGetSymbolAddress((void**)&ctx_ptr, g_ctx);
    cudaGetSymbolAddress((void**)&ah, g_Ah);
    cudaGetSymbolAddress((void**)&al, g_Al);
    cudaGetSymbolAddress((void**)&bh, g_Bh);
    cudaGetSymbolAddress((void**)&bl, g_Bl);
    cudaGetSymbolAddress((void**)&qhp, g_Qh);
    cudaGetSymbolAddress((void**)&qlp, g_Ql);
    cudaGetSymbolAddress((void**)&khp, g_Kh);
    cudaGetSymbolAddress((void**)&klp, g_Kl);
    cudaGetSymbolAddress((void**)&vhp, g_Vh);
    cudaGetSymbolAddress((void**)&vlp, g_Vl);

    cudaFuncSetAttribute(gemm_tc,
                         cudaFuncAttributeMaxDynamicSharedMemorySize, GEMM_SMEM);
    cudaFuncSetAttribute(flash_tc,
                         cudaFuncAttributeMaxDynamicSharedMemorySize, FA_SMEM);

    // 1) split hidden -> bf16 hi/lo
    {
        int n4 = M_TOK * HID / 4;
        convert_hilo<<<(n4 + 255) / 256, 256>>>(hidden, ah, al, n4);
    }
    // 2) transpose+split W_qkv
    {
        dim3 grid(3 * HID / 32, HID / 32);
        transpose_hilo<<<grid, dim3(32, 8)>>>(W_qkv, bh, bl, HID, 3 * HID);
    }
    // 3) QKV GEMM
    {
        dim3 grid(3 * HID / 128, M_TOK / 128);
        gemm_tc<<<grid, 256, GEMM_SMEM>>>(ah, al, bh, bl, b_qkv, qkv_ptr,
                                          M_TOK, 3 * HID, HID);
    }
    // 4) split qkv -> per-head bf16 hi/lo (Q pre-scaled by 1/8)
    {
        int n = M_TOK * HID / 4;
        split_qkv_attn<<<n / 256, 256>>>(qkv_ptr, qhp, qlp, khp, klp, vhp, vlp);
    }
    // 5) tensor-core causal flash attention -> ctx
    {
        dim3 grid(S_LEN / 128, NH, B_SZ);
        flash_tc<<<grid, 256, FA_SMEM>>>(qhp, qlp, khp, klp, vhp, vlp, ctx_ptr);
    }
    // 6) split ctx -> bf16 hi/lo
    {
        int n4 = M_TOK * HID / 4;
        convert_hilo<<<(n4 + 255) / 256, 256>>>(ctx_ptr, ah, al, n4);
    }
    // 7) transpose+split W_dense
    {
        dim3 grid(HID / 32, HID / 32);
        transpose_hilo<<<grid, dim3(32, 8)>>>(W_dense, bh, bl, HID, HID);
    }
    // 8) dense GEMM
    {
        dim3 grid(HID / 128, M_TOK / 128);
        gemm_tc<<<grid, 256, GEMM_SMEM>>>(ah, al, bh, bl, b_dense, out,
                                          M_TOK, HID, HID);
    }
}

// round 5
// speedup vs baseline: 2.3645x; 1.0416x over previous
#include <cuda_runtime.h>
#include <cuda_bf16.h>
#include <cstdint>
#include <math.h>

#define B_SZ  2
#define S_LEN 2048
#define HID   1024
#define NH    16
#define HD    64
#define M_TOK (B_SZ * S_LEN)     // 4096

// ---------------------------------------------------------------------------
// Scratch (__device__ globals per allocation-free rule)
// ---------------------------------------------------------------------------
__device__ __nv_bfloat16 g_Ah[(size_t)M_TOK * HID];         // act hi (input / ctx)
__device__ __nv_bfloat16 g_Al[(size_t)M_TOK * HID];         // act lo
__device__ __nv_bfloat16 g_Bh[(size_t)3 * HID * HID];       // weight hi [N][K]
__device__ __nv_bfloat16 g_Bl[(size_t)3 * HID * HID];       // weight lo
#define HELEMS ((size_t)B_SZ * NH * S_LEN * HD)
__device__ __nv_bfloat16 g_Qh[HELEMS], g_Ql[HELEMS];
__device__ __nv_bfloat16 g_Kh[HELEMS], g_Kl[HELEMS];
__device__ __nv_bfloat16 g_Vh[HELEMS], g_Vl[HELEMS];

// ---------------------------------------------------------------------------
// PTX helpers (family-compatible: mma.sync / ldmatrix / cp.async only)
// ---------------------------------------------------------------------------
__device__ __forceinline__ uint32_t smem_u32(const void* p) {
    uint32_t a;
    asm("{ .reg .u64 t; cvta.to.shared.u64 t, %1; cvt.u32.u64 %0, t; }"
        : "=r"(a) : "l"(p));
    return a;
}

#define CP_ASYNC16(dst, src) \
    asm volatile("cp.async.cg.shared.global [%0], [%1], 16;" \
                 :: "r"(dst), "l"(src) : "memory")
#define CP_COMMIT() asm volatile("cp.async.commit_group;" ::: "memory")
#define CP_WAIT1()  asm volatile("cp.async.wait_group 1;" ::: "memory")
#define CP_WAIT0()  asm volatile("cp.async.wait_group 0;" ::: "memory")

#define LDSM_X4(r0, r1, r2, r3, addr) \
    asm volatile("ldmatrix.sync.aligned.m8n8.x4.shared.b16 {%0,%1,%2,%3}, [%4];" \
                 : "=r"(r0), "=r"(r1), "=r"(r2), "=r"(r3) : "r"(addr))
#define LDSM_X4_T(r0, r1, r2, r3, addr) \
    asm volatile("ldmatrix.sync.aligned.m8n8.x4.trans.shared.b16 {%0,%1,%2,%3}, [%4];" \
                 : "=r"(r0), "=r"(r1), "=r"(r2), "=r"(r3) : "r"(addr))

__device__ __forceinline__ void mma_bf16(float* c, const uint32_t* a,
                                         uint32_t b0, uint32_t b1) {
    asm volatile(
        "mma.sync.aligned.m16n8k16.row.col.f32.bf16.bf16.f32 "
        "{%0,%1,%2,%3}, {%4,%5,%6,%7}, {%8,%9}, {%0,%1,%2,%3};"
        : "+f"(c[0]), "+f"(c[1]), "+f"(c[2]), "+f"(c[3])
        : "r"(a[0]), "r"(a[1]), "r"(a[2]), "r"(a[3]), "r"(b0), "r"(b1));
}

// (a, b) -> packed bf16x2 hi + residual bf16x2 lo
__device__ __forceinline__ void split2(float a, float b,
                                       uint32_t& hi, uint32_t& lo) {
    __nv_bfloat162 h = __floats2bfloat162_rn(a, b);
    hi = *reinterpret_cast<uint32_t*>(&h);
    __nv_bfloat162 l = __floats2bfloat162_rn(a - __bfloat162float(h.x),
                                             b - __bfloat162float(h.y));
    lo = *reinterpret_cast<uint32_t*>(&l);
}

// ---------------------------------------------------------------------------
// Prep kernels
// ---------------------------------------------------------------------------
__global__ void convert_hilo(const float* __restrict__ x,
                             __nv_bfloat16* __restrict__ hi,
                             __nv_bfloat16* __restrict__ lo, int n4) {
    int i = blockIdx.x * blockDim.x + threadIdx.x;
    if (i >= n4) return;
    float4 v = ((const float4*)x)[i];
    uint32_t h0, l0, h1, l1;
    split2(v.x, v.y, h0, l0);
    split2(v.z, v.w, h1, l1);
    uint32_t* hp = (uint32_t*)(hi + (size_t)i * 4); hp[0] = h0; hp[1] = h1;
    uint32_t* lp = (uint32_t*)(lo + (size_t)i * 4); lp[0] = l0; lp[1] = l1;
}

// W [K,N] fp32 row-major  ->  Wt hi/lo [N,K] bf16 row-major (K-major for MMA)
__global__ void transpose_hilo(const float* __restrict__ W,
                               __nv_bfloat16* __restrict__ Th,
                               __nv_bfloat16* __restrict__ Tl, int K, int N) {
    __shared__ float t[32][33];
    int tx = threadIdx.x, ty = threadIdx.y;
    int n0 = blockIdx.x * 32, k0 = blockIdx.y * 32;
#pragma unroll
    for (int j = 0; j < 4; j++) {
        int k = k0 + ty + j * 8;
        t[ty + j * 8][tx] = W[(size_t)k * N + n0 + tx];
    }
    __syncthreads();
#pragma unroll
    for (int j = 0; j < 4; j++) {
        int n = n0 + ty + j * 8;
        float v = t[tx][ty + j * 8];
        __nv_bfloat16 h = __float2bfloat16_rn(v);
        Th[(size_t)n * K + k0 + tx] = h;
        Tl[(size_t)n * K + k0 + tx] = __float2bfloat16_rn(v - __bfloat162float(h));
    }
}

// ---------------------------------------------------------------------------
// mma.sync bf16x3 GEMM, 3-stage cp.async pipeline.
// MODE 0: C = A@Wt^T + bias (fp32 out)
// MODE 1: QKV epilogue -> per-head bf16 hi/lo, Q scaled by 1/8
// ---------------------------------------------------------------------------
#define CH_K   32
#define LDT_B  80
#define TILE_B (128 * LDT_B)
#define STAGE_B (4 * TILE_B)             // 40960 B
#define GEMM_SMEM (3 * STAGE_B)          // 122880 B

__device__ __forceinline__ void issue_tile(const __nv_bfloat16* __restrict__ g,
                                           int row0, int K, int kt,
                                           uint32_t smem, int tid) {
#pragma unroll
    for (int i = 0; i < 2; i++) {
        int v = tid + i * 256;
        int r = v >> 2, c = v & 3;
        const __nv_bfloat16* src = g + (size_t)(row0 + r) * K + kt + c * 8;
        uint32_t dst = smem + (uint32_t)(r * LDT_B + c * 16);
        CP_ASYNC16(dst, src);
    }
}

template<int MODE>
__global__ __launch_bounds__(256, 1) void gemm_tc(
    const __nv_bfloat16* __restrict__ Ah, const __nv_bfloat16* __restrict__ Al,
    const __nv_bfloat16* __restrict__ Bh, const __nv_bfloat16* __restrict__ Bl,
    const float* __restrict__ bias, float* __restrict__ C,
    __nv_bfloat16* __restrict__ Qh, __nv_bfloat16* __restrict__ Ql,
    __nv_bfloat16* __restrict__ Kh, __nv_bfloat16* __restrict__ Kl,
    __nv_bfloat16* __restrict__ Vh, __nv_bfloat16* __restrict__ Vl,
    int M, int N, int K)
{
    extern __shared__ char sm[];
    uint32_t sb = smem_u32(sm);
    const int tid  = threadIdx.x;
    const int lane = tid & 31;
    const int wid  = tid >> 5;
    const int m0   = (wid & 3) * 32;
    const int n0   = (wid >> 2) * 64;
    const int bm   = blockIdx.y * 128;
    const int bn   = blockIdx.x * 128;

    float acc[2][8][4];
#pragma unroll
    for (int i = 0; i < 2; i++)
#pragma unroll
        for (int j = 0; j < 8; j++)
#pragma unroll
            for (int q = 0; q < 4; q++) acc[i][j][q] = 0.f;

    const uint32_t a_row  = lane & 15;
    const uint32_t a_koff = ((lane >> 4) & 1) * 16;
    const uint32_t b_rin  = ((lane >> 4) & 1) * 8 + (lane & 7);
    const uint32_t b_koff = ((lane >> 3) & 1) * 16;

    const int NCH = K / CH_K;

    // prologue: stage chunks 0, 1 into slots 0, 1
#pragma unroll
    for (int p = 0; p < 2; p++) {
        uint32_t bb = sb + p * STAGE_B;
        issue_tile(Ah, bm, K, p * CH_K, bb + 0 * TILE_B, tid);
        issue_tile(Al, bm, K, p * CH_K, bb + 1 * TILE_B, tid);
        issue_tile(Bh, bn, K, p * CH_K, bb + 2 * TILE_B, tid);
        issue_tile(Bl, bn, K, p * CH_K, bb + 3 * TILE_B, tid);
        CP_COMMIT();
    }

    for (int c = 0; c < NCH; c++) {
        if (c + 1 < NCH) { CP_WAIT1(); } else { CP_WAIT0(); }
        __syncthreads();   // chunk c visible to all; slot (c+2)%3 free to refill

        if (c + 2 < NCH) {
            uint32_t nb = sb + (uint32_t)((c + 2) % 3) * STAGE_B;
            int kt = (c + 2) * CH_K;
            issue_tile(Ah, bm, K, kt, nb + 0 * TILE_B, tid);
            issue_tile(Al, bm, K, kt, nb + 1 * TILE_B, tid);
            issue_tile(Bh, bn, K, kt, nb + 2 * TILE_B, tid);
            issue_tile(Bl, bn, K, kt, nb + 3 * TILE_B, tid);
            CP_COMMIT();
        }

        uint32_t bb   = sb + (uint32_t)(c % 3) * STAGE_B;
        uint32_t Ah_s = bb + 0 * TILE_B;
        uint32_t Al_s = bb + 1 * TILE_B;
        uint32_t Bh_s = bb + 2 * TILE_B;
        uint32_t Bl_s = bb + 3 * TILE_B;

#pragma unroll
        for (int kk = 0; kk < 2; kk++) {
            uint32_t ah[2][4], al[2][4];
#pragma unroll
            for (int i = 0; i < 2; i++) {
                uint32_t ro = (uint32_t)(m0 + i * 16 + a_row) * LDT_B
                              + kk * 32 + a_koff;
                LDSM_X4(ah[i][0], ah[i][1], ah[i][2], ah[i][3], Ah_s + ro);
                LDSM_X4(al[i][0], al[i][1], al[i][2], al[i][3], Al_s + ro);
            }
#pragma unroll
            for (int jp = 0; jp < 4; jp++) {
                uint32_t ro = (uint32_t)(n0 + jp * 16 + b_rin) * LDT_B
                              + kk * 32 + b_koff;
                uint32_t bh[4], bl[4];
                LDSM_X4(bh[0], bh[1], bh[2], bh[3], Bh_s + ro);
                LDSM_X4(bl[0], bl[1], bl[2], bl[3], Bl_s + ro);
#pragma unroll
                for (int i = 0; i < 2; i++) {
                    mma_bf16(acc[i][jp * 2 + 0], ah[i], bh[0], bh[1]);
                    mma_bf16(acc[i][jp * 2 + 0], ah[i], bl[0], bl[1]);
                    mma_bf16(acc[i][jp * 2 + 0], al[i], bh[0], bh[1]);
                    mma_bf16(acc[i][jp * 2 + 1], ah[i], bh[2], bh[3]);
                    mma_bf16(acc[i][jp * 2 + 1], ah[i], bl[2], bl[3]);
                    mma_bf16(acc[i][jp * 2 + 1], al[i], bh[2], bh[3]);
                }
            }
        }
    }

    const int rrow = lane >> 2;
    const int rcol = (lane & 3) * 2;
#pragma unroll
    for (int i = 0; i < 2; i++) {
        int r_lo = bm + m0 + i * 16 + rrow;
#pragma unroll
        for (int half = 0; half < 2; half++) {
            int row = r_lo + half * 8;
#pragma unroll
            for (int j = 0; j < 8; j++) {
                int col = bn + n0 + j * 8 + rcol;
                float b0 = bias[col], b1 = bias[col + 1];
                float v0 = acc[i][j][half * 2 + 0] + b0;
                float v1 = acc[i][j][half * 2 + 1] + b1;
                if (MODE == 0) {
                    *(float2*)&C[(size_t)row * N + col] = make_float2(v0, v1);
                } else {
                    int sec = col >> 10;           // 0=q 1=k 2=v
                    int hh  = (col & 1023) >> 6;
                    int d   = col & 63;
                    int b   = row >> 11, s = row & 2047;
                    size_t dst = (((size_t)(b * NH + hh)) * S_LEN + s) * HD + d;
                    if (sec == 0) { v0 *= 0.125f; v1 *= 0.125f; }
                    uint32_t hi, lo;
                    split2(v0, v1, hi, lo);
                    __nv_bfloat16* ph = (sec == 0) ? Qh : (sec == 1) ? Kh : Vh;
                    __nv_bfloat16* pl = (sec == 0) ? Ql : (sec == 1) ? Kl : Vl;
                    *(uint32_t*)(ph + dst) = hi;
                    *(uint32_t*)(pl + dst) = lo;
                }
            }
        }
    }
}

// ---------------------------------------------------------------------------
// Tensor-core flash attention (causal), bf16x3; 3-stage cp.async pipeline.
// Epilogue writes ctx directly as bf16 hi/lo (dense-GEMM input).
// ---------------------------------------------------------------------------
#define ALD      144
#define KV_TILE  (64 * ALD)          // 9216 B
#define FA_STAGE (4 * KV_TILE)       // 36864 B
#define FA_SMEM  (3 * FA_STAGE)      // 110592 B

__global__ __launch_bounds__(256, 2) void flash_tc(
    const __nv_bfloat16* __restrict__ Qh, const __nv_bfloat16* __restrict__ Ql,
    const __nv_bfloat16* __restrict__ Kh, const __nv_bfloat16* __restrict__ Kl,
    const __nv_bfloat16* __restrict__ Vh, const __nv_bfloat16* __restrict__ Vl,
    __nv_bfloat16* __restrict__ Ch, __nv_bfloat16* __restrict__ Cl)
{
    extern __shared__ char sm[];
    uint32_t sb = smem_u32(sm);
    const int tid = threadIdx.x, lane = tid & 31, wid = tid >> 5;
    const int qb = (int)gridDim.x - 1 - (int)blockIdx.x;   // big tiles first
    const int h = blockIdx.y, b = blockIdx.z;
    const size_t hoff = ((size_t)(b * NH + h)) * S_LEN * HD;
    const __nv_bfloat16* Qh_g = Qh + hoff + (size_t)qb * 128 * HD;
    const __nv_bfloat16* Ql_g = Ql + hoff + (size_t)qb * 128 * HD;
    const __nv_bfloat16* Kh_g = Kh + hoff;
    const __nv_bfloat16* Kl_g = Kl + hoff;
    const __nv_bfloat16* Vh_g = Vh + hoff;
    const __nv_bfloat16* Vl_g = Vl + hoff;

    // ---- stage Q into slot 0 region, load fragments ----
#pragma unroll
    for (int i = 0; i < 4; i++) {
        int idx = tid + i * 256;
        int r = idx >> 3, c = idx & 7;
        uint32_t d = sb + (uint32_t)(r * ALD + c * 16);
        CP_ASYNC16(d, Qh_g + r * HD + c * 8);
        CP_ASYNC16(d + 2 * KV_TILE, Ql_g + r * HD + c * 8);
    }
    CP_COMMIT(); CP_WAIT0(); __syncthreads();

    uint32_t qh[4][4], ql[4][4];
    {
        uint32_t base = sb + (uint32_t)((wid * 16 + (lane & 15)) * ALD)
                        + ((lane >> 4) & 1) * 16;
#pragma unroll
        for (int ks = 0; ks < 4; ks++) {
            LDSM_X4(qh[ks][0], qh[ks][1], qh[ks][2], qh[ks][3], base + ks * 32);
            LDSM_X4(ql[ks][0], ql[ks][1], ql[ks][2], ql[ks][3],
                    base + 2 * KV_TILE + ks * 32);
        }
    }
    __syncthreads();

    float o[8][4];
#pragma unroll
    for (int j = 0; j < 8; j++)
#pragma unroll
        for (int q = 0; q < 4; q++) o[j][q] = 0.f;
    float m[2] = {-1e30f, -1e30f}, l[2] = {0.f, 0.f};

    const uint32_t b_rin  = ((lane >> 4) & 1) * 8 + (lane & 7);
    const uint32_t b_koff = ((lane >> 3) & 1) * 16;
    const uint32_t v_row  = (lane & 7) + ((lane >> 3) & 1) * 8;
    const uint32_t v_coff = ((lane >> 4) & 1) * 16;

    const int nIter = 2 * qb + 2;

    // prologue: stage key-blocks 0, 1 into slots 0, 1
#pragma unroll
    for (int p = 0; p < 2; p++) {
        if (p < nIter) {
            uint32_t nb = sb + (uint32_t)p * FA_STAGE;
            int kbase = p * 64 * HD;
#pragma unroll
            for (int i = 0; i < 2; i++) {
                int idx = tid + i * 256;
                int r = idx >> 3, c = idx & 7;
                uint32_t d = nb + (uint32_t)(r * ALD + c * 16);
                int go = kbase + r * HD + c * 8;
                CP_ASYNC16(d + 0 * KV_TILE, Kh_g + go);
                CP_ASYNC16(d + 1 * KV_TILE, Kl_g + go);
                CP_ASYNC16(d + 2 * KV_TILE, Vh_g + go);
                CP_ASYNC16(d + 3 * KV_TILE, Vl_g + go);
            }
            CP_COMMIT();
        }
    }

    for (int it = 0; it < nIter; it++) {
        if (it + 1 < nIter) { CP_WAIT1(); } else { CP_WAIT0(); }
        __syncthreads();

        if (it + 2 < nIter) {
            uint32_t nb = sb + (uint32_t)((it + 2) % 3) * FA_STAGE;
            int kbase = (it + 2) * 64 * HD;
#pragma unroll
            for (int i = 0; i < 2; i++) {
                int idx = tid + i * 256;
                int r = idx >> 3, c = idx & 7;
                uint32_t d = nb + (uint32_t)(r * ALD + c * 16);
                int go = kbase + r * HD + c * 8;
                CP_ASYNC16(d + 0 * KV_TILE, Kh_g + go);
                CP_ASYNC16(d + 1 * KV_TILE, Kl_g + go);
                CP_ASYNC16(d + 2 * KV_TILE, Vh_g + go);
                CP_ASYNC16(d + 3 * KV_TILE, Vl_g + go);
            }
            CP_COMMIT();
        }

        uint32_t bb = sb + (uint32_t)(it % 3) * FA_STAGE;

        // ---- S = Q K^T (bf16x3) ----
        float s[8][4];
#pragma unroll
        for (int j = 0; j < 8; j++)
#pragma unroll
            for (int q = 0; q < 4; q++) s[j][q] = 0.f;

#pragma unroll
        for (int ks = 0; ks < 4; ks++) {
#pragma unroll
            for (int jp = 0; jp < 4; jp++) {
                uint32_t ka = bb + (uint32_t)((jp * 16 + b_rin) * ALD)
                              + ks * 32 + b_koff;
                uint32_t kh0, kh1, kh2, kh3, kl0, kl1, kl2, kl3;
                LDSM_X4(kh0, kh1, kh2, kh3, ka);
                LDSM_X4(kl0, kl1, kl2, kl3, ka + KV_TILE);
                mma_bf16(s[jp * 2 + 0], qh[ks], kh0, kh1);
                mma_bf16(s[jp * 2 + 0], qh[ks], kl0, kl1);
                mma_bf16(s[jp * 2 + 0], ql[ks], kh0, kh1);
                mma_bf16(s[jp * 2 + 1], qh[ks], kh2, kh3);
                mma_bf16(s[jp * 2 + 1], qh[ks], kl2, kl3);
                mma_bf16(s[jp * 2 + 1], ql[ks], kh2, kh3);
            }
        }

        // ---- causal mask ----
        if (it >= 2 * qb) {
            int col0 = it * 64 + (lane & 3) * 2;
#pragma unroll
            for (int rr = 0; rr < 2; rr++) {
                int row = qb * 128 + wid * 16 + (lane >> 2) + rr * 8;
#pragma unroll
                for (int j = 0; j < 8; j++) {
                    int c0 = col0 + j * 8;
                    if (c0 > row)     s[j][rr * 2 + 0] = -1e30f;
                    if (c0 + 1 > row) s[j][rr * 2 + 1] = -1e30f;
                }
            }
        }

        // ---- online softmax ----
#pragma unroll
        for (int rr = 0; rr < 2; rr++) {
            float lm = -1e30f;
#pragma unroll
            for (int j = 0; j < 8; j++)
                lm = fmaxf(lm, fmaxf(s[j][rr * 2], s[j][rr * 2 + 1]));
            lm = fmaxf(lm, __shfl_xor_sync(0xffffffffu, lm, 1));
            lm = fmaxf(lm, __shfl_xor_sync(0xffffffffu, lm, 2));
            float mn = fmaxf(m[rr], lm);
            float corr = __expf(m[rr] - mn);
            float sum = 0.f;
#pragma unroll
            for (int j = 0; j < 8; j++) {
                float p0 = __expf(s[j][rr * 2 + 0] - mn);
                float p1 = __expf(s[j][rr * 2 + 1] - mn);
                s[j][rr * 2 + 0] = p0;
                s[j][rr * 2 + 1] = p1;
                sum += p0 + p1;
            }
            sum += __shfl_xor_sync(0xffffffffu, sum, 1);
            sum += __shfl_xor_sync(0xffffffffu, sum, 2);
            l[rr] = l[rr] * corr + sum;
            m[rr] = mn;
#pragma unroll
            for (int j = 0; j < 8; j++) {
                o[j][rr * 2 + 0] *= corr;
                o[j][rr * 2 + 1] *= corr;
            }
        }

        // ---- O += P V (bf16x3) ----
#pragma unroll
        for (int ks = 0; ks < 4; ks++) {
            uint32_t pah[4], pal[4];
            split2(s[2 * ks][0],     s[2 * ks][1],     pah[0], pal[0]);
            split2(s[2 * ks][2],     s[2 * ks][3],     pah[1], pal[1]);
            split2(s[2 * ks + 1][0], s[2 * ks + 1][1], pah[2], pal[2]);
            split2(s[2 * ks + 1][2], s[2 * ks + 1][3], pah[3], pal[3]);
            uint32_t va = bb + 2 * KV_TILE
                          + (uint32_t)((ks * 16 + v_row) * ALD) + v_coff;
#pragma unroll
            for (int ng = 0; ng < 4; ng++) {
                uint32_t vh0, vh1, vh2, vh3, vl0, vl1, vl2, vl3;
                LDSM_X4_T(vh0, vh1, vh2, vh3, va + ng * 32);
                LDSM_X4_T(vl0, vl1, vl2, vl3, va + ng * 32 + KV_TILE);
                mma_bf16(o[ng * 2 + 0], pah, vh0, vh1);
                mma_bf16(o[ng * 2 + 0], pah, vl0, vl1);
                mma_bf16(o[ng * 2 + 0], pal, vh0, vh1);
                mma_bf16(o[ng * 2 + 1], pah, vh2, vh3);
                mma_bf16(o[ng * 2 + 1], pah, vl2, vl3);
                mma_bf16(o[ng * 2 + 1], pal, vh2, vh3);
            }
        }
    }

    // ---- epilogue: O/l -> ctx bf16 hi/lo [tok][H] ----
#pragma unroll
    for (int rr = 0; rr < 2; rr++) {
        float inv = 1.0f / l[rr];
        int tok = b * S_LEN + qb * 128 + wid * 16 + (lane >> 2) + rr * 8;
#pragma unroll
        for (int j = 0; j < 8; j++) {
            int col = h * HD + j * 8 + (lane & 3) * 2;
            uint32_t hi, lo;
            split2(o[j][rr * 2 + 0] * inv, o[j][rr * 2 + 1] * inv, hi, lo);
            *(uint32_t*)(Ch + (size_t)tok * HID + col) = hi;
            *(uint32_t*)(Cl + (size_t)tok * HID + col) = lo;
        }
    }
}

// ---------------------------------------------------------------------------
extern "C" void kernel_launch(void* const* d_in, const int* in_sizes, int n_in,
                              void* d_out, int out_size)
{
    (void)in_sizes; (void)n_in; (void)out_size;
    const float* hidden  = (const float*)d_in[0];
    // d_in[1] = ltor_mask: exactly causal lower-triangular; handled analytically
    const float* W_qkv   = (const float*)d_in[2];
    const float* b_qkv   = (const float*)d_in[3];
    const float* W_dense = (const float*)d_in[4];
    const float* b_dense = (const float*)d_in[5];
    float* out = (float*)d_out;

    __nv_bfloat16 *ah, *al, *bh, *bl;
    __nv_bfloat16 *qhp, *qlp, *khp, *klp, *vhp, *vlp;
    cudaGetSymbolAddress((void**)&ah, g_Ah);
    cudaGetSymbolAddress((void**)&al, g_Al);
    cudaGetSymbolAddress((void**)&bh, g_Bh);
    cudaGetSymbolAddress((void**)&bl, g_Bl);
    cudaGetSymbolAddress((void**)&qhp, g_Qh);
    cudaGetSymbolAddress((void**)&qlp, g_Ql);
    cudaGetSymbolAddress((void**)&khp, g_Kh);
    cudaGetSymbolAddress((void**)&klp, g_Kl);
    cudaGetSymbolAddress((void**)&vhp, g_Vh);
    cudaGetSymbolAddress((void**)&vlp, g_Vl);

    cudaFuncSetAttribute(gemm_tc<0>,
                         cudaFuncAttributeMaxDynamicSharedMemorySize, GEMM_SMEM);
    cudaFuncSetAttribute(gemm_tc<1>,
                         cudaFuncAttributeMaxDynamicSharedMemorySize, GEMM_SMEM);
    cudaFuncSetAttribute(flash_tc,
                         cudaFuncAttributeMaxDynamicSharedMemorySize, FA_SMEM);

    // 1) split hidden -> bf16 hi/lo
    {
        int n4 = M_TOK * HID / 4;
        convert_hilo<<<(n4 + 255) / 256, 256>>>(hidden, ah, al, n4);
    }
    // 2) transpose+split W_qkv
    {
        dim3 grid(3 * HID / 32, HID / 32);
        transpose_hilo<<<grid, dim3(32, 8)>>>(W_qkv, bh, bl, HID, 3 * HID);
    }
    // 3) QKV GEMM with fused per-head split epilogue (Q pre-scaled 1/8)
    {
        dim3 grid(3 * HID / 128, M_TOK / 128);
        gemm_tc<1><<<grid, 256, GEMM_SMEM>>>(ah, al, bh, bl, b_qkv, nullptr,
                                             qhp, qlp, khp, klp, vhp, vlp,
                                             M_TOK, 3 * HID, HID);
    }
    // 4) flash attention -> ctx bf16 hi/lo (into ah/al, dense-GEMM input)
    {
        dim3 grid(S_LEN / 128, NH, B_SZ);
        flash_tc<<<grid, 256, FA_SMEM>>>(qhp, qlp, khp, klp, vhp, vlp, ah, al);
    }
    // 5) transpose+split W_dense
    {
        dim3 grid(HID / 32, HID / 32);
        transpose_hilo<<<grid, dim3(32, 8)>>>(W_dense, bh, bl, HID, HID);
    }
    // 6) dense GEMM -> out (fp32)
    {
        dim3 grid(HID / 128, M_TOK / 128);
        gemm_tc<0><<<grid, 256, GEMM_SMEM>>>(ah, al, bh, bl, b_dense, out,
                                             nullptr, nullptr, nullptr,
                                             nullptr, nullptr, nullptr,
                                             M_TOK, HID, HID);
    }
}

// round 6
// speedup vs baseline: 2.5873x; 1.0942x over previous
#include <cuda_runtime.h>
#include <cuda_bf16.h>
#include <cstdint>
#include <math.h>

#define B_SZ  2
#define S_LEN 2048
#define HID   1024
#define NH    16
#define HD    64
#define M_TOK (B_SZ * S_LEN)     // 4096

#define LOG2E 1.44269504088896341f

// ---------------------------------------------------------------------------
// Scratch (__device__ globals per allocation-free rule)
// ---------------------------------------------------------------------------
__device__ __nv_bfloat16 g_Ah[(size_t)M_TOK * HID];         // act hi (input / ctx)
__device__ __nv_bfloat16 g_Al[(size_t)M_TOK * HID];         // act lo
__device__ __nv_bfloat16 g_Bh[(size_t)3 * HID * HID];       // weight hi [N][K]
__device__ __nv_bfloat16 g_Bl[(size_t)3 * HID * HID];       // weight lo
#define HELEMS ((size_t)B_SZ * NH * S_LEN * HD)
__device__ __nv_bfloat16 g_Qh[HELEMS], g_Ql[HELEMS];
__device__ __nv_bfloat16 g_Kh[HELEMS], g_Kl[HELEMS];
__device__ __nv_bfloat16 g_Vh[HELEMS], g_Vl[HELEMS];

// ---------------------------------------------------------------------------
// PTX helpers (family-compatible: mma.sync / ldmatrix / cp.async only)
// ---------------------------------------------------------------------------
__device__ __forceinline__ uint32_t smem_u32(const void* p) {
    uint32_t a;
    asm("{ .reg .u64 t; cvta.to.shared.u64 t, %1; cvt.u32.u64 %0, t; }"
        : "=r"(a) : "l"(p));
    return a;
}

#define CP_ASYNC16(dst, src) \
    asm volatile("cp.async.cg.shared.global [%0], [%1], 16;" \
                 :: "r"(dst), "l"(src) : "memory")
#define CP_COMMIT() asm volatile("cp.async.commit_group;" ::: "memory")
#define CP_WAIT1()  asm volatile("cp.async.wait_group 1;" ::: "memory")
#define CP_WAIT0()  asm volatile("cp.async.wait_group 0;" ::: "memory")

#define LDSM_X4(r0, r1, r2, r3, addr) \
    asm volatile("ldmatrix.sync.aligned.m8n8.x4.shared.b16 {%0,%1,%2,%3}, [%4];" \
                 : "=r"(r0), "=r"(r1), "=r"(r2), "=r"(r3) : "r"(addr))
#define LDSM_X4_T(r0, r1, r2, r3, addr) \
    asm volatile("ldmatrix.sync.aligned.m8n8.x4.trans.shared.b16 {%0,%1,%2,%3}, [%4];" \
                 : "=r"(r0), "=r"(r1), "=r"(r2), "=r"(r3) : "r"(addr))

__device__ __forceinline__ void mma_bf16(float* c, const uint32_t* a,
                                         uint32_t b0, uint32_t b1) {
    asm volatile(
        "mma.sync.aligned.m16n8k16.row.col.f32.bf16.bf16.f32 "
        "{%0,%1,%2,%3}, {%4,%5,%6,%7}, {%8,%9}, {%0,%1,%2,%3};"
        : "+f"(c[0]), "+f"(c[1]), "+f"(c[2]), "+f"(c[3])
        : "r"(a[0]), "r"(a[1]), "r"(a[2]), "r"(a[3]), "r"(b0), "r"(b1));
}

// (a, b) -> packed bf16x2 hi + residual bf16x2 lo
__device__ __forceinline__ void split2(float a, float b,
                                       uint32_t& hi, uint32_t& lo) {
    __nv_bfloat162 h = __floats2bfloat162_rn(a, b);
    hi = *reinterpret_cast<uint32_t*>(&h);
    __nv_bfloat162 l = __floats2bfloat162_rn(a - __bfloat162float(h.x),
                                             b - __bfloat162float(h.y));
    lo = *reinterpret_cast<uint32_t*>(&l);
}

// ---------------------------------------------------------------------------
// Prep kernels
// ---------------------------------------------------------------------------
__global__ void convert_hilo(const float* __restrict__ x,
                             __nv_bfloat16* __restrict__ hi,
                             __nv_bfloat16* __restrict__ lo, int n4) {
    int i = blockIdx.x * blockDim.x + threadIdx.x;
    if (i >= n4) return;
    float4 v = ((const float4*)x)[i];
    uint32_t h0, l0, h1, l1;
    split2(v.x, v.y, h0, l0);
    split2(v.z, v.w, h1, l1);
    uint32_t* hp = (uint32_t*)(hi + (size_t)i * 4); hp[0] = h0; hp[1] = h1;
    uint32_t* lp = (uint32_t*)(lo + (size_t)i * 4); lp[0] = l0; lp[1] = l1;
}

// W [K,N] fp32 row-major  ->  Wt hi/lo [N,K] bf16 row-major (K-major for MMA)
__global__ void transpose_hilo(const float* __restrict__ W,
                               __nv_bfloat16* __restrict__ Th,
                               __nv_bfloat16* __restrict__ Tl, int K, int N) {
    __shared__ float t[32][33];
    int tx = threadIdx.x, ty = threadIdx.y;
    int n0 = blockIdx.x * 32, k0 = blockIdx.y * 32;
#pragma unroll
    for (int j = 0; j < 4; j++) {
        int k = k0 + ty + j * 8;
        t[ty + j * 8][tx] = W[(size_t)k * N + n0 + tx];
    }
    __syncthreads();
#pragma unroll
    for (int j = 0; j < 4; j++) {
        int n = n0 + ty + j * 8;
        float v = t[tx][ty + j * 8];
        __nv_bfloat16 h = __float2bfloat16_rn(v);
        Th[(size_t)n * K + k0 + tx] = h;
        Tl[(size_t)n * K + k0 + tx] = __float2bfloat16_rn(v - __bfloat162float(h));
    }
}

// ---------------------------------------------------------------------------
// mma.sync bf16x3 GEMM, 2-stage cp.async pipeline, 2 CTAs/SM.
// MODE 0: C = A@Wt^T + bias (fp32 out)
// MODE 1: QKV epilogue -> per-head bf16 hi/lo, Q scaled by (1/8)*log2(e)
// ---------------------------------------------------------------------------
#define CH_K   32
#define LDT_B  80
#define TILE_B (128 * LDT_B)
#define STAGE_B (4 * TILE_B)             // 40960 B
#define GEMM_SMEM (2 * STAGE_B)          // 81920 B -> 2 CTAs/SM

__device__ __forceinline__ void issue_tile(const __nv_bfloat16* __restrict__ g,
                                           int row0, int K, int kt,
                                           uint32_t smem, int tid) {
#pragma unroll
    for (int i = 0; i < 2; i++) {
        int v = tid + i * 256;
        int r = v >> 2, c = v & 3;
        const __nv_bfloat16* src = g + (size_t)(row0 + r) * K + kt + c * 8;
        uint32_t dst = smem + (uint32_t)(r * LDT_B + c * 16);
        CP_ASYNC16(dst, src);
    }
}

template<int MODE>
__global__ __launch_bounds__(256, 2) void gemm_tc(
    const __nv_bfloat16* __restrict__ Ah, const __nv_bfloat16* __restrict__ Al,
    const __nv_bfloat16* __restrict__ Bh, const __nv_bfloat16* __restrict__ Bl,
    const float* __restrict__ bias, float* __restrict__ C,
    __nv_bfloat16* __restrict__ Qh, __nv_bfloat16* __restrict__ Ql,
    __nv_bfloat16* __restrict__ Kh, __nv_bfloat16* __restrict__ Kl,
    __nv_bfloat16* __restrict__ Vh, __nv_bfloat16* __restrict__ Vl,
    int M, int N, int K)
{
    extern __shared__ char sm[];
    uint32_t sb = smem_u32(sm);
    const int tid  = threadIdx.x;
    const int lane = tid & 31;
    const int wid  = tid >> 5;
    const int m0   = (wid & 3) * 32;
    const int n0   = (wid >> 2) * 64;
    const int bm   = blockIdx.y * 128;
    const int bn   = blockIdx.x * 128;

    float acc[2][8][4];
#pragma unroll
    for (int i = 0; i < 2; i++)
#pragma unroll
        for (int j = 0; j < 8; j++)
#pragma unroll
            for (int q = 0; q < 4; q++) acc[i][j][q] = 0.f;

    const uint32_t a_row  = lane & 15;
    const uint32_t a_koff = ((lane >> 4) & 1) * 16;
    const uint32_t b_rin  = ((lane >> 4) & 1) * 8 + (lane & 7);
    const uint32_t b_koff = ((lane >> 3) & 1) * 16;

    const int NCH = K / CH_K;

    // prologue: stage chunks 0, 1
#pragma unroll
    for (int p = 0; p < 2; p++) {
        uint32_t bb = sb + p * STAGE_B;
        issue_tile(Ah, bm, K, p * CH_K, bb + 0 * TILE_B, tid);
        issue_tile(Al, bm, K, p * CH_K, bb + 1 * TILE_B, tid);
        issue_tile(Bh, bn, K, p * CH_K, bb + 2 * TILE_B, tid);
        issue_tile(Bl, bn, K, p * CH_K, bb + 3 * TILE_B, tid);
        CP_COMMIT();
    }

    for (int c = 0; c < NCH; c++) {
        if (c + 1 < NCH) { CP_WAIT1(); } else { CP_WAIT0(); }
        __syncthreads();

        uint32_t bb   = sb + (uint32_t)(c & 1) * STAGE_B;
        uint32_t Ah_s = bb + 0 * TILE_B;
        uint32_t Al_s = bb + 1 * TILE_B;
        uint32_t Bh_s = bb + 2 * TILE_B;
        uint32_t Bl_s = bb + 3 * TILE_B;

#pragma unroll
        for (int kk = 0; kk < 2; kk++) {
            uint32_t ah[2][4], al[2][4];
#pragma unroll
            for (int i = 0; i < 2; i++) {
                uint32_t ro = (uint32_t)(m0 + i * 16 + a_row) * LDT_B
                              + kk * 32 + a_koff;
                LDSM_X4(ah[i][0], ah[i][1], ah[i][2], ah[i][3], Ah_s + ro);
                LDSM_X4(al[i][0], al[i][1], al[i][2], al[i][3], Al_s + ro);
            }
#pragma unroll
            for (int jp = 0; jp < 4; jp++) {
                uint32_t ro = (uint32_t)(n0 + jp * 16 + b_rin) * LDT_B
                              + kk * 32 + b_koff;
                uint32_t bh[4], bl[4];
                LDSM_X4(bh[0], bh[1], bh[2], bh[3], Bh_s + ro);
                LDSM_X4(bl[0], bl[1], bl[2], bl[3], Bl_s + ro);
                // 12 MMAs over 4 independent accumulators: RAW distance 4
                mma_bf16(acc[0][jp * 2 + 0], ah[0], bh[0], bh[1]);
                mma_bf16(acc[0][jp * 2 + 1], ah[0], bh[2], bh[3]);
                mma_bf16(acc[1][jp * 2 + 0], ah[1], bh[0], bh[1]);
                mma_bf16(acc[1][jp * 2 + 1], ah[1], bh[2], bh[3]);
                mma_bf16(acc[0][jp * 2 + 0], ah[0], bl[0], bl[1]);
                mma_bf16(acc[0][jp * 2 + 1], ah[0], bl[2], bl[3]);
                mma_bf16(acc[1][jp * 2 + 0], ah[1], bl[0], bl[1]);
                mma_bf16(acc[1][jp * 2 + 1], ah[1], bl[2], bl[3]);
                mma_bf16(acc[0][jp * 2 + 0], al[0], bh[0], bh[1]);
                mma_bf16(acc[0][jp * 2 + 1], al[0], bh[2], bh[3]);
                mma_bf16(acc[1][jp * 2 + 0], al[1], bh[0], bh[1]);
                mma_bf16(acc[1][jp * 2 + 1], al[1], bh[2], bh[3]);
            }
        }
        __syncthreads();
        if (c + 2 < NCH) {
            uint32_t nb = sb + (uint32_t)(c & 1) * STAGE_B;
            int kt = (c + 2) * CH_K;
            issue_tile(Ah, bm, K, kt, nb + 0 * TILE_B, tid);
            issue_tile(Al, bm, K, kt, nb + 1 * TILE_B, tid);
            issue_tile(Bh, bn, K, kt, nb + 2 * TILE_B, tid);
            issue_tile(Bl, bn, K, kt, nb + 3 * TILE_B, tid);
        }
        CP_COMMIT();
    }

    const int rrow = lane >> 2;
    const int rcol = (lane & 3) * 2;
#pragma unroll
    for (int i = 0; i < 2; i++) {
        int r_lo = bm + m0 + i * 16 + rrow;
#pragma unroll
        for (int half = 0; half < 2; half++) {
            int row = r_lo + half * 8;
#pragma unroll
            for (int j = 0; j < 8; j++) {
                int col = bn + n0 + j * 8 + rcol;
                float b0 = bias[col], b1 = bias[col + 1];
                float v0 = acc[i][j][half * 2 + 0] + b0;
                float v1 = acc[i][j][half * 2 + 1] + b1;
                if (MODE == 0) {
                    *(float2*)&C[(size_t)row * N + col] = make_float2(v0, v1);
                } else {
                    int sec = col >> 10;           // 0=q 1=k 2=v
                    int hh  = (col & 1023) >> 6;
                    int d   = col & 63;
                    int b   = row >> 11, s = row & 2047;
                    size_t dst = (((size_t)(b * NH + hh)) * S_LEN + s) * HD + d;
                    if (sec == 0) {                // scale + base-2 fold
                        v0 *= 0.125f * LOG2E;
                        v1 *= 0.125f * LOG2E;
                    }
                    uint32_t hi, lo;
                    split2(v0, v1, hi, lo);
                    __nv_bfloat16* ph = (sec == 0) ? Qh : (sec == 1) ? Kh : Vh;
                    __nv_bfloat16* pl = (sec == 0) ? Ql : (sec == 1) ? Kl : Vl;
                    *(uint32_t*)(ph + dst) = hi;
                    *(uint32_t*)(pl + dst) = lo;
                }
            }
        }
    }
}

// ---------------------------------------------------------------------------
// Tensor-core flash attention (causal), bf16x3; 3-stage cp.async pipeline.
// Scores are pre-scaled by log2(e) (via Q) -> softmax uses exp2f.
// Epilogue writes ctx directly as bf16 hi/lo (dense-GEMM input).
// ---------------------------------------------------------------------------
#define ALD      144
#define KV_TILE  (64 * ALD)          // 9216 B
#define FA_STAGE (4 * KV_TILE)       // 36864 B
#define FA_SMEM  (3 * FA_STAGE)      // 110592 B

__global__ __launch_bounds__(256, 2) void flash_tc(
    const __nv_bfloat16* __restrict__ Qh, const __nv_bfloat16* __restrict__ Ql,
    const __nv_bfloat16* __restrict__ Kh, const __nv_bfloat16* __restrict__ Kl,
    const __nv_bfloat16* __restrict__ Vh, const __nv_bfloat16* __restrict__ Vl,
    __nv_bfloat16* __restrict__ Ch, __nv_bfloat16* __restrict__ Cl)
{
    extern __shared__ char sm[];
    uint32_t sb = smem_u32(sm);
    const int tid = threadIdx.x, lane = tid & 31, wid = tid >> 5;
    const int qb = (int)gridDim.x - 1 - (int)blockIdx.x;   // big tiles first
    const int h = blockIdx.y, b = blockIdx.z;
    const size_t hoff = ((size_t)(b * NH + h)) * S_LEN * HD;
    const __nv_bfloat16* Qh_g = Qh + hoff + (size_t)qb * 128 * HD;
    const __nv_bfloat16* Ql_g = Ql + hoff + (size_t)qb * 128 * HD;
    const __nv_bfloat16* Kh_g = Kh + hoff;
    const __nv_bfloat16* Kl_g = Kl + hoff;
    const __nv_bfloat16* Vh_g = Vh + hoff;
    const __nv_bfloat16* Vl_g = Vl + hoff;

    // ---- stage Q into slot 0 region, load fragments ----
#pragma unroll
    for (int i = 0; i < 4; i++) {
        int idx = tid + i * 256;
        int r = idx >> 3, c = idx & 7;
        uint32_t d = sb + (uint32_t)(r * ALD + c * 16);
        CP_ASYNC16(d, Qh_g + r * HD + c * 8);
        CP_ASYNC16(d + 2 * KV_TILE, Ql_g + r * HD + c * 8);
    }
    CP_COMMIT(); CP_WAIT0(); __syncthreads();

    uint32_t qh[4][4], ql[4][4];
    {
        uint32_t base = sb + (uint32_t)((wid * 16 + (lane & 15)) * ALD)
                        + ((lane >> 4) & 1) * 16;
#pragma unroll
        for (int ks = 0; ks < 4; ks++) {
            LDSM_X4(qh[ks][0], qh[ks][1], qh[ks][2], qh[ks][3], base + ks * 32);
            LDSM_X4(ql[ks][0], ql[ks][1], ql[ks][2], ql[ks][3],
                    base + 2 * KV_TILE + ks * 32);
        }
    }
    __syncthreads();

    float o[8][4];
#pragma unroll
    for (int j = 0; j < 8; j++)
#pragma unroll
        for (int q = 0; q < 4; q++) o[j][q] = 0.f;
    float m[2] = {-1e30f, -1e30f}, l[2] = {0.f, 0.f};

    const uint32_t b_rin  = ((lane >> 4) & 1) * 8 + (lane & 7);
    const uint32_t b_koff = ((lane >> 3) & 1) * 16;
    const uint32_t v_row  = (lane & 7) + ((lane >> 3) & 1) * 8;
    const uint32_t v_coff = ((lane >> 4) & 1) * 16;

    const int nIter = 2 * qb + 2;

    // prologue: stage key-blocks 0, 1 into slots 0, 1
#pragma unroll
    for (int p = 0; p < 2; p++) {
        if (p < nIter) {
            uint32_t nb = sb + (uint32_t)p * FA_STAGE;
            int kbase = p * 64 * HD;
#pragma unroll
            for (int i = 0; i < 2; i++) {
                int idx = tid + i * 256;
                int r = idx >> 3, c = idx & 7;
                uint32_t d = nb + (uint32_t)(r * ALD + c * 16);
                int go = kbase + r * HD + c * 8;
                CP_ASYNC16(d + 0 * KV_TILE, Kh_g + go);
                CP_ASYNC16(d + 1 * KV_TILE, Kl_g + go);
                CP_ASYNC16(d + 2 * KV_TILE, Vh_g + go);
                CP_ASYNC16(d + 3 * KV_TILE, Vl_g + go);
            }
            CP_COMMIT();
        }
    }

    for (int it = 0; it < nIter; it++) {
        if (it + 1 < nIter) { CP_WAIT1(); } else { CP_WAIT0(); }
        __syncthreads();

        if (it + 2 < nIter) {
            uint32_t nb = sb + (uint32_t)((it + 2) % 3) * FA_STAGE;
            int kbase = (it + 2) * 64 * HD;
#pragma unroll
            for (int i = 0; i < 2; i++) {
                int idx = tid + i * 256;
                int r = idx >> 3, c = idx & 7;
                uint32_t d = nb + (uint32_t)(r * ALD + c * 16);
                int go = kbase + r * HD + c * 8;
                CP_ASYNC16(d + 0 * KV_TILE, Kh_g + go);
                CP_ASYNC16(d + 1 * KV_TILE, Kl_g + go);
                CP_ASYNC16(d + 2 * KV_TILE, Vh_g + go);
                CP_ASYNC16(d + 3 * KV_TILE, Vl_g + go);
            }
            CP_COMMIT();
        }

        uint32_t bb = sb + (uint32_t)(it % 3) * FA_STAGE;

        // ---- S = Q K^T (bf16x3), interleaved accumulators ----
        float s[8][4];
#pragma unroll
        for (int j = 0; j < 8; j++)
#pragma unroll
            for (int q = 0; q < 4; q++) s[j][q] = 0.f;

#pragma unroll
        for (int ks = 0; ks < 4; ks++) {
#pragma unroll
            for (int jp = 0; jp < 4; jp++) {
                uint32_t ka = bb + (uint32_t)((jp * 16 + b_rin) * ALD)
                              + ks * 32 + b_koff;
                uint32_t kh0, kh1, kh2, kh3, kl0, kl1, kl2, kl3;
                LDSM_X4(kh0, kh1, kh2, kh3, ka);
                LDSM_X4(kl0, kl1, kl2, kl3, ka + KV_TILE);
                mma_bf16(s[jp * 2 + 0], qh[ks], kh0, kh1);
                mma_bf16(s[jp * 2 + 1], qh[ks], kh2, kh3);
                mma_bf16(s[jp * 2 + 0], qh[ks], kl0, kl1);
                mma_bf16(s[jp * 2 + 1], qh[ks], kl2, kl3);
                mma_bf16(s[jp * 2 + 0], ql[ks], kh0, kh1);
                mma_bf16(s[jp * 2 + 1], ql[ks], kh2, kh3);
            }
        }

        // ---- causal mask ----
        if (it >= 2 * qb) {
            int col0 = it * 64 + (lane & 3) * 2;
#pragma unroll
            for (int rr = 0; rr < 2; rr++) {
                int row = qb * 128 + wid * 16 + (lane >> 2) + rr * 8;
#pragma unroll
                for (int j = 0; j < 8; j++) {
                    int c0 = col0 + j * 8;
                    if (c0 > row)     s[j][rr * 2 + 0] = -1e30f;
                    if (c0 + 1 > row) s[j][rr * 2 + 1] = -1e30f;
                }
            }
        }

        // ---- online softmax (base-2 domain; scores pre-scaled by log2e) ----
#pragma unroll
        for (int rr = 0; rr < 2; rr++) {
            float lm = -1e30f;
#pragma unroll
            for (int j = 0; j < 8; j++)
                lm = fmaxf(lm, fmaxf(s[j][rr * 2], s[j][rr * 2 + 1]));
            lm = fmaxf(lm, __shfl_xor_sync(0xffffffffu, lm, 1));
            lm = fmaxf(lm, __shfl_xor_sync(0xffffffffu, lm, 2));
            float mn = fmaxf(m[rr], lm);
            float corr = exp2f(m[rr] - mn);
            float sum = 0.f;
#pragma unroll
            for (int j = 0; j < 8; j++) {
                float p0 = exp2f(s[j][rr * 2 + 0] - mn);
                float p1 = exp2f(s[j][rr * 2 + 1] - mn);
                s[j][rr * 2 + 0] = p0;
                s[j][rr * 2 + 1] = p1;
                sum += p0 + p1;
            }
            sum += __shfl_xor_sync(0xffffffffu, sum, 1);
            sum += __shfl_xor_sync(0xffffffffu, sum, 2);
            l[rr] = l[rr] * corr + sum;
            m[rr] = mn;
#pragma unroll
            for (int j = 0; j < 8; j++) {
                o[j][rr * 2 + 0] *= corr;
                o[j][rr * 2 + 1] *= corr;
            }
        }

        // ---- O += P V (bf16x3), interleaved accumulators ----
#pragma unroll
        for (int ks = 0; ks < 4; ks++) {
            uint32_t pah[4], pal[4];
            split2(s[2 * ks][0],     s[2 * ks][1],     pah[0], pal[0]);
            split2(s[2 * ks][2],     s[2 * ks][3],     pah[1], pal[1]);
            split2(s[2 * ks + 1][0], s[2 * ks + 1][1], pah[2], pal[2]);
            split2(s[2 * ks + 1][2], s[2 * ks + 1][3], pah[3], pal[3]);
            uint32_t va = bb + 2 * KV_TILE
                          + (uint32_t)((ks * 16 + v_row) * ALD) + v_coff;
#pragma unroll
            for (int ng = 0; ng < 4; ng++) {
                uint32_t vh0, vh1, vh2, vh3, vl0, vl1, vl2, vl3;
                LDSM_X4_T(vh0, vh1, vh2, vh3, va + ng * 32);
                LDSM_X4_T(vl0, vl1, vl2, vl3, va + ng * 32 + KV_TILE);
                mma_bf16(o[ng * 2 + 0], pah, vh0, vh1);
                mma_bf16(o[ng * 2 + 1], pah, vh2, vh3);
                mma_bf16(o[ng * 2 + 0], pah, vl0, vl1);
                mma_bf16(o[ng * 2 + 1], pah, vl2, vl3);
                mma_bf16(o[ng * 2 + 0], pal, vh0, vh1);
                mma_bf16(o[ng * 2 + 1], pal, vh2, vh3);
            }
        }
    }

    // ---- epilogue: O/l -> ctx bf16 hi/lo [tok][H] ----
#pragma unroll
    for (int rr = 0; rr < 2; rr++) {
        float inv = 1.0f / l[rr];
        int tok = b * S_LEN + qb * 128 + wid * 16 + (lane >> 2) + rr * 8;
#pragma unroll
        for (int j = 0; j < 8; j++) {
            int col = h * HD + j * 8 + (lane & 3) * 2;
            uint32_t hi, lo;
            split2(o[j][rr * 2 + 0] * inv, o[j][rr * 2 + 1] * inv, hi, lo);
            *(uint32_t*)(Ch + (size_t)tok * HID + col) = hi;
            *(uint32_t*)(Cl + (size_t)tok * HID + col) = lo;
        }
    }
}

// ---------------------------------------------------------------------------
extern "C" void kernel_launch(void* const* d_in, const int* in_sizes, int n_in,
                              void* d_out, int out_size)
{
    (void)in_sizes; (void)n_in; (void)out_size;
    const float* hidden  = (const float*)d_in[0];
    // d_in[1] = ltor_mask: exactly causal lower-triangular; handled analytically
    const float* W_qkv   = (const float*)d_in[2];
    const float* b_qkv   = (const float*)d_in[3];
    const float* W_dense = (const float*)d_in[4];
    const float* b_dense = (const float*)d_in[5];
    float* out = (float*)d_out;

    __nv_bfloat16 *ah, *al, *bh, *bl;
    __nv_bfloat16 *qhp, *qlp, *khp, *klp, *vhp, *vlp;
    cudaGetSymbolAddress((void**)&ah, g_Ah);
    cudaGetSymbolAddress((void**)&al, g_Al);
    cudaGetSymbolAddress((void**)&bh, g_Bh);
    cudaGetSymbolAddress((void**)&bl, g_Bl);
    cudaGetSymbolAddress((void**)&qhp, g_Qh);
    cudaGetSymbolAddress((void**)&qlp, g_Ql);
    cudaGetSymbolAddress((void**)&khp, g_Kh);
    cudaGetSymbolAddress((void**)&klp, g_Kl);
    cudaGetSymbolAddress((void**)&vhp, g_Vh);
    cudaGetSymbolAddress((void**)&vlp, g_Vl);

    cudaFuncSetAttribute(gemm_tc<0>,
                         cudaFuncAttributeMaxDynamicSharedMemorySize, GEMM_SMEM);
    cudaFuncSetAttribute(gemm_tc<1>,
                         cudaFuncAttributeMaxDynamicSharedMemorySize, GEMM_SMEM);
    cudaFuncSetAttribute(flash_tc,
                         cudaFuncAttributeMaxDynamicSharedMemorySize, FA_SMEM);

    // 1) split hidden -> bf16 hi/lo
    {
        int n4 = M_TOK * HID / 4;
        convert_hilo<<<(n4 + 255) / 256, 256>>>(hidden, ah, al, n4);
    }
    // 2) transpose+split W_qkv
    {
        dim3 grid(3 * HID / 32, HID / 32);
        transpose_hilo<<<grid, dim3(32, 8)>>>(W_qkv, bh, bl, HID, 3 * HID);
    }
    // 3) QKV GEMM with fused per-head split epilogue (Q scaled 0.125*log2e)
    {
        dim3 grid(3 * HID / 128, M_TOK / 128);
        gemm_tc<1><<<grid, 256, GEMM_SMEM>>>(ah, al, bh, bl, b_qkv, nullptr,
                                             qhp, qlp, khp, klp, vhp, vlp,
                                             M_TOK, 3 * HID, HID);
    }
    // 4) flash attention -> ctx bf16 hi/lo (into ah/al, dense-GEMM input)
    {
        dim3 grid(S_LEN / 128, NH, B_SZ);
        flash_tc<<<grid, 256, FA_SMEM>>>(qhp, qlp, khp, klp, vhp, vlp, ah, al);
    }
    // 5) transpose+split W_dense
    {
        dim3 grid(HID / 32, HID / 32);
        transpose_hilo<<<grid, dim3(32, 8)>>>(W_dense, bh, bl, HID, HID);
    }
    // 6) dense GEMM -> out (fp32)
    {
        dim3 grid(HID / 128, M_TOK / 128);
        gemm_tc<0><<<grid, 256, GEMM_SMEM>>>(ah, al, bh, bl, b_dense, out,
                                             nullptr, nullptr, nullptr,
                                             nullptr, nullptr, nullptr,
                                             M_TOK, HID, HID);
    }
}

// round 7
// speedup vs baseline: 2.7846x; 1.0763x over previous
#include <cuda_runtime.h>
#include <cuda_bf16.h>
#include <cuda_fp16.h>
#include <cstdint>
#include <math.h>

#define B_SZ  2
#define S_LEN 2048
#define HID   1024
#define NH    16
#define HD    64
#define M_TOK (B_SZ * S_LEN)     // 4096

#define LOG2E 1.44269504088896341f

// ---------------------------------------------------------------------------
// Scratch (__device__ globals per allocation-free rule)
// ---------------------------------------------------------------------------
__device__ __nv_bfloat16 g_Ah[(size_t)M_TOK * HID];         // act hi (input / ctx)
__device__ __nv_bfloat16 g_Al[(size_t)M_TOK * HID];         // act lo
__device__ __nv_bfloat16 g_Bh[(size_t)3 * HID * HID];       // weight hi [N][K]
__device__ __nv_bfloat16 g_Bl[(size_t)3 * HID * HID];       // weight lo
#define HELEMS ((size_t)B_SZ * NH * S_LEN * HD)
__device__ __nv_bfloat16 g_Qh[HELEMS], g_Ql[HELEMS];
__device__ __nv_bfloat16 g_Kh[HELEMS], g_Kl[HELEMS];
__device__ __half        g_Vh[HELEMS], g_Vl[HELEMS];        // V as f16 hi/lo

// ---------------------------------------------------------------------------
// PTX helpers (family-compatible: mma.sync / ldmatrix / cp.async only)
// ---------------------------------------------------------------------------
__device__ __forceinline__ uint32_t smem_u32(const void* p) {
    uint32_t a;
    asm("{ .reg .u64 t; cvta.to.shared.u64 t, %1; cvt.u32.u64 %0, t; }"
        : "=r"(a) : "l"(p));
    return a;
}

#define CP_ASYNC16(dst, src) \
    asm volatile("cp.async.cg.shared.global [%0], [%1], 16;" \
                 :: "r"(dst), "l"(src) : "memory")
#define CP_COMMIT() asm volatile("cp.async.commit_group;" ::: "memory")
#define CP_WAIT1()  asm volatile("cp.async.wait_group 1;" ::: "memory")
#define CP_WAIT0()  asm volatile("cp.async.wait_group 0;" ::: "memory")

#define LDSM_X4(r0, r1, r2, r3, addr) \
    asm volatile("ldmatrix.sync.aligned.m8n8.x4.shared.b16 {%0,%1,%2,%3}, [%4];" \
                 : "=r"(r0), "=r"(r1), "=r"(r2), "=r"(r3) : "r"(addr))
#define LDSM_X4_T(r0, r1, r2, r3, addr) \
    asm volatile("ldmatrix.sync.aligned.m8n8.x4.trans.shared.b16 {%0,%1,%2,%3}, [%4];" \
                 : "=r"(r0), "=r"(r1), "=r"(r2), "=r"(r3) : "r"(addr))

__device__ __forceinline__ void mma_bf16(float* c, const uint32_t* a,
                                         uint32_t b0, uint32_t b1) {
    asm volatile(
        "mma.sync.aligned.m16n8k16.row.col.f32.bf16.bf16.f32 "
        "{%0,%1,%2,%3}, {%4,%5,%6,%7}, {%8,%9}, {%0,%1,%2,%3};"
        : "+f"(c[0]), "+f"(c[1]), "+f"(c[2]), "+f"(c[3])
        : "r"(a[0]), "r"(a[1]), "r"(a[2]), "r"(a[3]), "r"(b0), "r"(b1));
}
__device__ __forceinline__ void mma_f16(float* c, const uint32_t* a,
                                        uint32_t b0, uint32_t b1) {
    asm volatile(
        "mma.sync.aligned.m16n8k16.row.col.f32.f16.f16.f32 "
        "{%0,%1,%2,%3}, {%4,%5,%6,%7}, {%8,%9}, {%0,%1,%2,%3};"
        : "+f"(c[0]), "+f"(c[1]), "+f"(c[2]), "+f"(c[3])
        : "r"(a[0]), "r"(a[1]), "r"(a[2]), "r"(a[3]), "r"(b0), "r"(b1));
}

// (a, b) -> packed bf16x2 hi + residual bf16x2 lo
__device__ __forceinline__ void split2(float a, float b,
                                       uint32_t& hi, uint32_t& lo) {
    __nv_bfloat162 h = __floats2bfloat162_rn(a, b);
    hi = *reinterpret_cast<uint32_t*>(&h);
    __nv_bfloat162 l = __floats2bfloat162_rn(a - __bfloat162float(h.x),
                                             b - __bfloat162float(h.y));
    lo = *reinterpret_cast<uint32_t*>(&l);
}
// (a, b) -> packed f16x2 hi + residual f16x2 lo
__device__ __forceinline__ void split2h(float a, float b,
                                        uint32_t& hi, uint32_t& lo) {
    __half2 h = __floats2half2_rn(a, b);
    hi = *reinterpret_cast<uint32_t*>(&h);
    __half2 l = __floats2half2_rn(a - __half2float(__low2half(h)),
                                  b - __half2float(__high2half(h)));
    lo = *reinterpret_cast<uint32_t*>(&l);
}
__device__ __forceinline__ uint32_t pack_h2(float a, float b) {
    __half2 h = __floats2half2_rn(a, b);
    return *reinterpret_cast<uint32_t*>(&h);
}

// ---------------------------------------------------------------------------
// Prep kernels
// ---------------------------------------------------------------------------
__global__ void convert_hilo(const float* __restrict__ x,
                             __nv_bfloat16* __restrict__ hi,
                             __nv_bfloat16* __restrict__ lo, int n4) {
    int i = blockIdx.x * blockDim.x + threadIdx.x;
    if (i >= n4) return;
    float4 v = ((const float4*)x)[i];
    uint32_t h0, l0, h1, l1;
    split2(v.x, v.y, h0, l0);
    split2(v.z, v.w, h1, l1);
    uint32_t* hp = (uint32_t*)(hi + (size_t)i * 4); hp[0] = h0; hp[1] = h1;
    uint32_t* lp = (uint32_t*)(lo + (size_t)i * 4); lp[0] = l0; lp[1] = l1;
}

// W [K,N] fp32 row-major  ->  Wt hi/lo [N,K] bf16 row-major (K-major for MMA)
__global__ void transpose_hilo(const float* __restrict__ W,
                               __nv_bfloat16* __restrict__ Th,
                               __nv_bfloat16* __restrict__ Tl, int K, int N) {
    __shared__ float t[32][33];
    int tx = threadIdx.x, ty = threadIdx.y;
    int n0 = blockIdx.x * 32, k0 = blockIdx.y * 32;
#pragma unroll
    for (int j = 0; j < 4; j++) {
        int k = k0 + ty + j * 8;
        t[ty + j * 8][tx] = W[(size_t)k * N + n0 + tx];
    }
    __syncthreads();
#pragma unroll
    for (int j = 0; j < 4; j++) {
        int n = n0 + ty + j * 8;
        float v = t[tx][ty + j * 8];
        __nv_bfloat16 h = __float2bfloat16_rn(v);
        Th[(size_t)n * K + k0 + tx] = h;
        Tl[(size_t)n * K + k0 + tx] = __float2bfloat16_rn(v - __bfloat162float(h));
    }
}

// ---------------------------------------------------------------------------
// mma.sync bf16x3 GEMM, 2-stage cp.async pipeline, 2 CTAs/SM.
// MODE 0: C = A@Wt^T + bias (fp32 out)
// MODE 1: QKV epilogue -> per-head Q/K bf16 hi/lo (Q scaled), V f16 hi/lo
// ---------------------------------------------------------------------------
#define CH_K   32
#define LDT_B  80
#define TILE_B (128 * LDT_B)
#define STAGE_B (4 * TILE_B)             // 40960 B
#define GEMM_SMEM (2 * STAGE_B)          // 81920 B -> 2 CTAs/SM

__device__ __forceinline__ void issue_tile(const __nv_bfloat16* __restrict__ g,
                                           int row0, int K, int kt,
                                           uint32_t smem, int tid) {
#pragma unroll
    for (int i = 0; i < 2; i++) {
        int v = tid + i * 256;
        int r = v >> 2, c = v & 3;
        const __nv_bfloat16* src = g + (size_t)(row0 + r) * K + kt + c * 8;
        uint32_t dst = smem + (uint32_t)(r * LDT_B + c * 16);
        CP_ASYNC16(dst, src);
    }
}

template<int MODE>
__global__ __launch_bounds__(256, 2) void gemm_tc(
    const __nv_bfloat16* __restrict__ Ah, const __nv_bfloat16* __restrict__ Al,
    const __nv_bfloat16* __restrict__ Bh, const __nv_bfloat16* __restrict__ Bl,
    const float* __restrict__ bias, float* __restrict__ C,
    __nv_bfloat16* __restrict__ Qh, __nv_bfloat16* __restrict__ Ql,
    __nv_bfloat16* __restrict__ Kh, __nv_bfloat16* __restrict__ Kl,
    __half* __restrict__ Vh, __half* __restrict__ Vl,
    int M, int N, int K)
{
    extern __shared__ char sm[];
    uint32_t sb = smem_u32(sm);
    const int tid  = threadIdx.x;
    const int lane = tid & 31;
    const int wid  = tid >> 5;
    const int m0   = (wid & 3) * 32;
    const int n0   = (wid >> 2) * 64;
    const int bm   = blockIdx.y * 128;
    const int bn   = blockIdx.x * 128;

    float acc[2][8][4];
#pragma unroll
    for (int i = 0; i < 2; i++)
#pragma unroll
        for (int j = 0; j < 8; j++)
#pragma unroll
            for (int q = 0; q < 4; q++) acc[i][j][q] = 0.f;

    const uint32_t a_row  = lane & 15;
    const uint32_t a_koff = ((lane >> 4) & 1) * 16;
    const uint32_t b_rin  = ((lane >> 4) & 1) * 8 + (lane & 7);
    const uint32_t b_koff = ((lane >> 3) & 1) * 16;

    const int NCH = K / CH_K;

    // prologue: stage chunks 0, 1
#pragma unroll
    for (int p = 0; p < 2; p++) {
        uint32_t bb = sb + p * STAGE_B;
        issue_tile(Ah, bm, K, p * CH_K, bb + 0 * TILE_B, tid);
        issue_tile(Al, bm, K, p * CH_K, bb + 1 * TILE_B, tid);
        issue_tile(Bh, bn, K, p * CH_K, bb + 2 * TILE_B, tid);
        issue_tile(Bl, bn, K, p * CH_K, bb + 3 * TILE_B, tid);
        CP_COMMIT();
    }

    for (int c = 0; c < NCH; c++) {
        if (c + 1 < NCH) { CP_WAIT1(); } else { CP_WAIT0(); }
        __syncthreads();

        uint32_t bb   = sb + (uint32_t)(c & 1) * STAGE_B;
        uint32_t Ah_s = bb + 0 * TILE_B;
        uint32_t Al_s = bb + 1 * TILE_B;
        uint32_t Bh_s = bb + 2 * TILE_B;
        uint32_t Bl_s = bb + 3 * TILE_B;

#pragma unroll
        for (int kk = 0; kk < 2; kk++) {
            uint32_t ah[2][4], al[2][4];
#pragma unroll
            for (int i = 0; i < 2; i++) {
                uint32_t ro = (uint32_t)(m0 + i * 16 + a_row) * LDT_B
                              + kk * 32 + a_koff;
                LDSM_X4(ah[i][0], ah[i][1], ah[i][2], ah[i][3], Ah_s + ro);
                LDSM_X4(al[i][0], al[i][1], al[i][2], al[i][3], Al_s + ro);
            }
#pragma unroll
            for (int jp = 0; jp < 4; jp++) {
                uint32_t ro = (uint32_t)(n0 + jp * 16 + b_rin) * LDT_B
                              + kk * 32 + b_koff;
                uint32_t bh[4], bl[4];
                LDSM_X4(bh[0], bh[1], bh[2], bh[3], Bh_s + ro);
                LDSM_X4(bl[0], bl[1], bl[2], bl[3], Bl_s + ro);
                // 12 MMAs over 4 independent accumulators: RAW distance 4
                mma_bf16(acc[0][jp * 2 + 0], ah[0], bh[0], bh[1]);
                mma_bf16(acc[0][jp * 2 + 1], ah[0], bh[2], bh[3]);
                mma_bf16(acc[1][jp * 2 + 0], ah[1], bh[0], bh[1]);
                mma_bf16(acc[1][jp * 2 + 1], ah[1], bh[2], bh[3]);
                mma_bf16(acc[0][jp * 2 + 0], ah[0], bl[0], bl[1]);
                mma_bf16(acc[0][jp * 2 + 1], ah[0], bl[2], bl[3]);
                mma_bf16(acc[1][jp * 2 + 0], ah[1], bl[0], bl[1]);
                mma_bf16(acc[1][jp * 2 + 1], ah[1], bl[2], bl[3]);
                mma_bf16(acc[0][jp * 2 + 0], al[0], bh[0], bh[1]);
                mma_bf16(acc[0][jp * 2 + 1], al[0], bh[2], bh[3]);
                mma_bf16(acc[1][jp * 2 + 0], al[1], bh[0], bh[1]);
                mma_bf16(acc[1][jp * 2 + 1], al[1], bh[2], bh[3]);
            }
        }
        __syncthreads();
        if (c + 2 < NCH) {
            uint32_t nb = sb + (uint32_t)(c & 1) * STAGE_B;
            int kt = (c + 2) * CH_K;
            issue_tile(Ah, bm, K, kt, nb + 0 * TILE_B, tid);
            issue_tile(Al, bm, K, kt, nb + 1 * TILE_B, tid);
            issue_tile(Bh, bn, K, kt, nb + 2 * TILE_B, tid);
            issue_tile(Bl, bn, K, kt, nb + 3 * TILE_B, tid);
        }
        CP_COMMIT();
    }

    const int rrow = lane >> 2;
    const int rcol = (lane & 3) * 2;
#pragma unroll
    for (int i = 0; i < 2; i++) {
        int r_lo = bm + m0 + i * 16 + rrow;
#pragma unroll
        for (int half = 0; half < 2; half++) {
            int row = r_lo + half * 8;
#pragma unroll
            for (int j = 0; j < 8; j++) {
                int col = bn + n0 + j * 8 + rcol;
                float b0 = bias[col], b1 = bias[col + 1];
                float v0 = acc[i][j][half * 2 + 0] + b0;
                float v1 = acc[i][j][half * 2 + 1] + b1;
                if (MODE == 0) {
                    *(float2*)&C[(size_t)row * N + col] = make_float2(v0, v1);
                } else {
                    int sec = col >> 10;           // 0=q 1=k 2=v
                    int hh  = (col & 1023) >> 6;
                    int d   = col & 63;
                    int b   = row >> 11, s = row & 2047;
                    size_t dst = (((size_t)(b * NH + hh)) * S_LEN + s) * HD + d;
                    if (sec == 0) {                // scale + base-2 fold
                        v0 *= 0.125f * LOG2E;
                        v1 *= 0.125f * LOG2E;
                    }
                    uint32_t hi, lo;
                    if (sec == 2) {
                        split2h(v0, v1, hi, lo);   // V -> f16 hi/lo
                        *(uint32_t*)(Vh + dst) = hi;
                        *(uint32_t*)(Vl + dst) = lo;
                    } else {
                        split2(v0, v1, hi, lo);    // Q/K -> bf16 hi/lo
                        __nv_bfloat16* ph = (sec == 0) ? Qh : Kh;
                        __nv_bfloat16* pl = (sec == 0) ? Ql : Kl;
                        *(uint32_t*)(ph + dst) = hi;
                        *(uint32_t*)(pl + dst) = lo;
                    }
                }
            }
        }
    }
}

// ---------------------------------------------------------------------------
// Tensor-core flash attention (causal).
// QK^T: bf16x3.  PV: P single f16 x V f16 hi/lo (2 MMA terms).
// Scores pre-scaled by log2(e) (via Q) -> softmax uses exp2f.
// Epilogue writes ctx directly as bf16 hi/lo (dense-GEMM input).
// ---------------------------------------------------------------------------
#define ALD      144
#define KV_TILE  (64 * ALD)          // 9216 B
#define FA_STAGE (4 * KV_TILE)       // Kh,Kl,Vh,Vl = 36864 B
#define FA_SMEM  (3 * FA_STAGE)      // 110592 B

__global__ __launch_bounds__(256, 2) void flash_tc(
    const __nv_bfloat16* __restrict__ Qh, const __nv_bfloat16* __restrict__ Ql,
    const __nv_bfloat16* __restrict__ Kh, const __nv_bfloat16* __restrict__ Kl,
    const __half* __restrict__ Vh, const __half* __restrict__ Vl,
    __nv_bfloat16* __restrict__ Ch, __nv_bfloat16* __restrict__ Cl)
{
    extern __shared__ char sm[];
    uint32_t sb = smem_u32(sm);
    const int tid = threadIdx.x, lane = tid & 31, wid = tid >> 5;
    const int qb = (int)gridDim.x - 1 - (int)blockIdx.x;   // big tiles first
    const int h = blockIdx.y, b = blockIdx.z;
    const size_t hoff = ((size_t)(b * NH + h)) * S_LEN * HD;
    const __nv_bfloat16* Qh_g = Qh + hoff + (size_t)qb * 128 * HD;
    const __nv_bfloat16* Ql_g = Ql + hoff + (size_t)qb * 128 * HD;
    const __nv_bfloat16* Kh_g = Kh + hoff;
    const __nv_bfloat16* Kl_g = Kl + hoff;
    const __half* Vh_g = Vh + hoff;
    const __half* Vl_g = Vl + hoff;

    // ---- stage Q into slot 0 region, load fragments ----
#pragma unroll
    for (int i = 0; i < 4; i++) {
        int idx = tid + i * 256;
        int r = idx >> 3, c = idx & 7;
        uint32_t d = sb + (uint32_t)(r * ALD + c * 16);
        CP_ASYNC16(d, Qh_g + r * HD + c * 8);
        CP_ASYNC16(d + 2 * KV_TILE, Ql_g + r * HD + c * 8);
    }
    CP_COMMIT(); CP_WAIT0(); __syncthreads();

    uint32_t qh[4][4], ql[4][4];
    {
        uint32_t base = sb + (uint32_t)((wid * 16 + (lane & 15)) * ALD)
                        + ((lane >> 4) & 1) * 16;
#pragma unroll
        for (int ks = 0; ks < 4; ks++) {
            LDSM_X4(qh[ks][0], qh[ks][1], qh[ks][2], qh[ks][3], base + ks * 32);
            LDSM_X4(ql[ks][0], ql[ks][1], ql[ks][2], ql[ks][3],
                    base + 2 * KV_TILE + ks * 32);
        }
    }
    __syncthreads();

    float o[8][4];
#pragma unroll
    for (int j = 0; j < 8; j++)
#pragma unroll
        for (int q = 0; q < 4; q++) o[j][q] = 0.f;
    float m[2] = {-1e30f, -1e30f}, l[2] = {0.f, 0.f};

    const uint32_t b_rin  = ((lane >> 4) & 1) * 8 + (lane & 7);
    const uint32_t b_koff = ((lane >> 3) & 1) * 16;
    const uint32_t v_row  = (lane & 7) + ((lane >> 3) & 1) * 8;
    const uint32_t v_coff = ((lane >> 4) & 1) * 16;

    const int nIter = 2 * qb + 2;

    // prologue: stage key-blocks 0, 1 into slots 0, 1
#pragma unroll
    for (int p = 0; p < 2; p++) {
        if (p < nIter) {
            uint32_t nb = sb + (uint32_t)p * FA_STAGE;
            int kbase = p * 64 * HD;
#pragma unroll
            for (int i = 0; i < 2; i++) {
                int idx = tid + i * 256;
                int r = idx >> 3, c = idx & 7;
                uint32_t d = nb + (uint32_t)(r * ALD + c * 16);
                int go = kbase + r * HD + c * 8;
                CP_ASYNC16(d + 0 * KV_TILE, Kh_g + go);
                CP_ASYNC16(d + 1 * KV_TILE, Kl_g + go);
                CP_ASYNC16(d + 2 * KV_TILE, Vh_g + go);
                CP_ASYNC16(d + 3 * KV_TILE, Vl_g + go);
            }
            CP_COMMIT();
        }
    }

    for (int it = 0; it < nIter; it++) {
        if (it + 1 < nIter) { CP_WAIT1(); } else { CP_WAIT0(); }
        __syncthreads();

        if (it + 2 < nIter) {
            uint32_t nb = sb + (uint32_t)((it + 2) % 3) * FA_STAGE;
            int kbase = (it + 2) * 64 * HD;
#pragma unroll
            for (int i = 0; i < 2; i++) {
                int idx = tid + i * 256;
                int r = idx >> 3, c = idx & 7;
                uint32_t d = nb + (uint32_t)(r * ALD + c * 16);
                int go = kbase + r * HD + c * 8;
                CP_ASYNC16(d + 0 * KV_TILE, Kh_g + go);
                CP_ASYNC16(d + 1 * KV_TILE, Kl_g + go);
                CP_ASYNC16(d + 2 * KV_TILE, Vh_g + go);
                CP_ASYNC16(d + 3 * KV_TILE, Vl_g + go);
            }
            CP_COMMIT();
        }

        uint32_t bb = sb + (uint32_t)(it % 3) * FA_STAGE;

        // ---- S = Q K^T (bf16x3), interleaved accumulators ----
        float s[8][4];
#pragma unroll
        for (int j = 0; j < 8; j++)
#pragma unroll
            for (int q = 0; q < 4; q++) s[j][q] = 0.f;

#pragma unroll
        for (int ks = 0; ks < 4; ks++) {
#pragma unroll
            for (int jp = 0; jp < 4; jp++) {
                uint32_t ka = bb + (uint32_t)((jp * 16 + b_rin) * ALD)
                              + ks * 32 + b_koff;
                uint32_t kh0, kh1, kh2, kh3, kl0, kl1, kl2, kl3;
                LDSM_X4(kh0, kh1, kh2, kh3, ka);
                LDSM_X4(kl0, kl1, kl2, kl3, ka + KV_TILE);
                mma_bf16(s[jp * 2 + 0], qh[ks], kh0, kh1);
                mma_bf16(s[jp * 2 + 1], qh[ks], kh2, kh3);
                mma_bf16(s[jp * 2 + 0], qh[ks], kl0, kl1);
                mma_bf16(s[jp * 2 + 1], qh[ks], kl2, kl3);
                mma_bf16(s[jp * 2 + 0], ql[ks], kh0, kh1);
                mma_bf16(s[jp * 2 + 1], ql[ks], kh2, kh3);
            }
        }

        // ---- causal mask ----
        if (it >= 2 * qb) {
            int col0 = it * 64 + (lane & 3) * 2;
#pragma unroll
            for (int rr = 0; rr < 2; rr++) {
                int row = qb * 128 + wid * 16 + (lane >> 2) + rr * 8;
#pragma unroll
                for (int j = 0; j < 8; j++) {
                    int c0 = col0 + j * 8;
                    if (c0 > row)     s[j][rr * 2 + 0] = -1e30f;
                    if (c0 + 1 > row) s[j][rr * 2 + 1] = -1e30f;
                }
            }
        }

        // ---- online softmax (base-2 domain; scores pre-scaled by log2e) ----
#pragma unroll
        for (int rr = 0; rr < 2; rr++) {
            float lm = -1e30f;
#pragma unroll
            for (int j = 0; j < 8; j++)
                lm = fmaxf(lm, fmaxf(s[j][rr * 2], s[j][rr * 2 + 1]));
            lm = fmaxf(lm, __shfl_xor_sync(0xffffffffu, lm, 1));
            lm = fmaxf(lm, __shfl_xor_sync(0xffffffffu, lm, 2));
            float mn = fmaxf(m[rr], lm);
            float corr = exp2f(m[rr] - mn);
            float sum = 0.f;
#pragma unroll
            for (int j = 0; j < 8; j++) {
                float p0 = exp2f(s[j][rr * 2 + 0] - mn);
                float p1 = exp2f(s[j][rr * 2 + 1] - mn);
                s[j][rr * 2 + 0] = p0;
                s[j][rr * 2 + 1] = p1;
                sum += p0 + p1;
            }
            sum += __shfl_xor_sync(0xffffffffu, sum, 1);
            sum += __shfl_xor_sync(0xffffffffu, sum, 2);
            l[rr] = l[rr] * corr + sum;
            m[rr] = mn;
#pragma unroll
            for (int j = 0; j < 8; j++) {
                o[j][rr * 2 + 0] *= corr;
                o[j][rr * 2 + 1] *= corr;
            }
        }

        // ---- O += P V  (P single f16, V f16 hi/lo: 2 MMA terms) ----
#pragma unroll
        for (int ks = 0; ks < 4; ks++) {
            uint32_t p16[4];
            p16[0] = pack_h2(s[2 * ks][0],     s[2 * ks][1]);
            p16[1] = pack_h2(s[2 * ks][2],     s[2 * ks][3]);
            p16[2] = pack_h2(s[2 * ks + 1][0], s[2 * ks + 1][1]);
            p16[3] = pack_h2(s[2 * ks + 1][2], s[2 * ks + 1][3]);
            uint32_t va = bb + 2 * KV_TILE
                          + (uint32_t)((ks * 16 + v_row) * ALD) + v_coff;
#pragma unroll
            for (int ng = 0; ng < 4; ng++) {
                uint32_t vh0, vh1, vh2, vh3, vl0, vl1, vl2, vl3;
                LDSM_X4_T(vh0, vh1, vh2, vh3, va + ng * 32);
                LDSM_X4_T(vl0, vl1, vl2, vl3, va + ng * 32 + KV_TILE);
                mma_f16(o[ng * 2 + 0], p16, vh0, vh1);
                mma_f16(o[ng * 2 + 1], p16, vh2, vh3);
                mma_f16(o[ng * 2 + 0], p16, vl0, vl1);
                mma_f16(o[ng * 2 + 1], p16, vl2, vl3);
            }
        }
    }

    // ---- epilogue: O/l -> ctx bf16 hi/lo [tok][H] ----
#pragma unroll
    for (int rr = 0; rr < 2; rr++) {
        float inv = 1.0f / l[rr];
        int tok = b * S_LEN + qb * 128 + wid * 16 + (lane >> 2) + rr * 8;
#pragma unroll
        for (int j = 0; j < 8; j++) {
            int col = h * HD + j * 8 + (lane & 3) * 2;
            uint32_t hi, lo;
            split2(o[j][rr * 2 + 0] * inv, o[j][rr * 2 + 1] * inv, hi, lo);
            *(uint32_t*)(Ch + (size_t)tok * HID + col) = hi;
            *(uint32_t*)(Cl + (size_t)tok * HID + col) = lo;
        }
    }
}

// ---------------------------------------------------------------------------
extern "C" void kernel_launch(void* const* d_in, const int* in_sizes, int n_in,
                              void* d_out, int out_size)
{
    (void)in_sizes; (void)n_in; (void)out_size;
    const float* hidden  = (const float*)d_in[0];
    // d_in[1] = ltor_mask: exactly causal lower-triangular; handled analytically
    const float* W_qkv   = (const float*)d_in[2];
    const float* b_qkv   = (const float*)d_in[3];
    const float* W_dense = (const float*)d_in[4];
    const float* b_dense = (const float*)d_in[5];
    float* out = (float*)d_out;

    __nv_bfloat16 *ah, *al, *bh, *bl;
    __nv_bfloat16 *qhp, *qlp, *khp, *klp;
    __half *vhp, *vlp;
    cudaGetSymbolAddress((void**)&ah, g_Ah);
    cudaGetSymbolAddress((void**)&al, g_Al);
    cudaGetSymbolAddress((void**)&bh, g_Bh);
    cudaGetSymbolAddress((void**)&bl, g_Bl);
    cudaGetSymbolAddress((void**)&qhp, g_Qh);
    cudaGetSymbolAddress((void**)&qlp, g_Ql);
    cudaGetSymbolAddress((void**)&khp, g_Kh);
    cudaGetSymbolAddress((void**)&klp, g_Kl);
    cudaGetSymbolAddress((void**)&vhp, g_Vh);
    cudaGetSymbolAddress((void**)&vlp, g_Vl);

    cudaFuncSetAttribute(gemm_tc<0>,
                         cudaFuncAttributeMaxDynamicSharedMemorySize, GEMM_SMEM);
    cudaFuncSetAttribute(gemm_tc<1>,
                         cudaFuncAttributeMaxDynamicSharedMemorySize, GEMM_SMEM);
    cudaFuncSetAttribute(flash_tc,
                         cudaFuncAttributeMaxDynamicSharedMemorySize, FA_SMEM);

    // 1) split hidden -> bf16 hi/lo
    {
        int n4 = M_TOK * HID / 4;
        convert_hilo<<<(n4 + 255) / 256, 256>>>(hidden, ah, al, n4);
    }
    // 2) transpose+split W_qkv
    {
        dim3 grid(3 * HID / 32, HID / 32);
        transpose_hilo<<<grid, dim3(32, 8)>>>(W_qkv, bh, bl, HID, 3 * HID);
    }
    // 3) QKV GEMM with fused per-head split epilogue
    {
        dim3 grid(3 * HID / 128, M_TOK / 128);
        gemm_tc<1><<<grid, 256, GEMM_SMEM>>>(ah, al, bh, bl, b_qkv, nullptr,
                                             qhp, qlp, khp, klp, vhp, vlp,
                                             M_TOK, 3 * HID, HID);
    }
    // 4) flash attention -> ctx bf16 hi/lo (into ah/al, dense-GEMM input)
    {
        dim3 grid(S_LEN / 128, NH, B_SZ);
        flash_tc<<<grid, 256, FA_SMEM>>>(qhp, qlp, khp, klp, vhp, vlp, ah, al);
    }
    // 5) transpose+split W_dense
    {
        dim3 grid(HID / 32, HID / 32);
        transpose_hilo<<<grid, dim3(32, 8)>>>(W_dense, bh, bl, HID, HID);
    }
    // 6) dense GEMM -> out (fp32)
    {
        dim3 grid(HID / 128, M_TOK / 128);
        gemm_tc<0><<<grid, 256, GEMM_SMEM>>>(ah, al, bh, bl, b_dense, out,
                                             nullptr, nullptr, nullptr,
                                             nullptr, nullptr, nullptr,
                                             M_TOK, HID, HID);
    }
}

// round 8
// speedup vs baseline: 3.0059x; 1.0795x over previous
#include <cuda_runtime.h>
#include <cuda_bf16.h>
#include <cuda_fp16.h>
#include <cstdint>
#include <math.h>

#define B_SZ  2
#define S_LEN 2048
#define HID   1024
#define NH    16
#define HD    64
#define M_TOK (B_SZ * S_LEN)     // 4096

#define LOG2E 1.44269504088896341f

// ---------------------------------------------------------------------------
// Scratch (__device__ globals per allocation-free rule)
// ---------------------------------------------------------------------------
__device__ __nv_bfloat16 g_Ah[(size_t)M_TOK * HID];         // act hi (input / ctx)
__device__ __nv_bfloat16 g_Al[(size_t)M_TOK * HID];         // act lo
__device__ __nv_bfloat16 g_Bh[(size_t)3 * HID * HID];       // weight hi [N][K]
__device__ __nv_bfloat16 g_Bl[(size_t)3 * HID * HID];       // weight lo
#define HELEMS ((size_t)B_SZ * NH * S_LEN * HD)
__device__ __half g_Qh[HELEMS], g_Ql[HELEMS];               // Q f16 hi/lo (scaled)
__device__ __half g_Kh[HELEMS];                             // K single f16
__device__ __half g_Vh[HELEMS], g_Vl[HELEMS];               // V f16 hi/lo

// ---------------------------------------------------------------------------
// PTX helpers (family-compatible: mma.sync / ldmatrix / cp.async only)
// ---------------------------------------------------------------------------
__device__ __forceinline__ uint32_t smem_u32(const void* p) {
    uint32_t a;
    asm("{ .reg .u64 t; cvta.to.shared.u64 t, %1; cvt.u32.u64 %0, t; }"
        : "=r"(a) : "l"(p));
    return a;
}

#define CP_ASYNC16(dst, src) \
    asm volatile("cp.async.cg.shared.global [%0], [%1], 16;" \
                 :: "r"(dst), "l"(src) : "memory")
#define CP_COMMIT() asm volatile("cp.async.commit_group;" ::: "memory")
#define CP_WAIT1()  asm volatile("cp.async.wait_group 1;" ::: "memory")
#define CP_WAIT0()  asm volatile("cp.async.wait_group 0;" ::: "memory")

#define LDSM_X4(r0, r1, r2, r3, addr) \
    asm volatile("ldmatrix.sync.aligned.m8n8.x4.shared.b16 {%0,%1,%2,%3}, [%4];" \
                 : "=r"(r0), "=r"(r1), "=r"(r2), "=r"(r3) : "r"(addr))
#define LDSM_X4_T(r0, r1, r2, r3, addr) \
    asm volatile("ldmatrix.sync.aligned.m8n8.x4.trans.shared.b16 {%0,%1,%2,%3}, [%4];" \
                 : "=r"(r0), "=r"(r1), "=r"(r2), "=r"(r3) : "r"(addr))

__device__ __forceinline__ void mma_bf16(float* c, const uint32_t* a,
                                         uint32_t b0, uint32_t b1) {
    asm volatile(
        "mma.sync.aligned.m16n8k16.row.col.f32.bf16.bf16.f32 "
        "{%0,%1,%2,%3}, {%4,%5,%6,%7}, {%8,%9}, {%0,%1,%2,%3};"
        : "+f"(c[0]), "+f"(c[1]), "+f"(c[2]), "+f"(c[3])
        : "r"(a[0]), "r"(a[1]), "r"(a[2]), "r"(a[3]), "r"(b0), "r"(b1));
}
__device__ __forceinline__ void mma_f16(float* c, const uint32_t* a,
                                        uint32_t b0, uint32_t b1) {
    asm volatile(
        "mma.sync.aligned.m16n8k16.row.col.f32.f16.f16.f32 "
        "{%0,%1,%2,%3}, {%4,%5,%6,%7}, {%8,%9}, {%0,%1,%2,%3};"
        : "+f"(c[0]), "+f"(c[1]), "+f"(c[2]), "+f"(c[3])
        : "r"(a[0]), "r"(a[1]), "r"(a[2]), "r"(a[3]), "r"(b0), "r"(b1));
}

// (a, b) -> packed bf16x2 hi + residual bf16x2 lo
__device__ __forceinline__ void split2(float a, float b,
                                       uint32_t& hi, uint32_t& lo) {
    __nv_bfloat162 h = __floats2bfloat162_rn(a, b);
    hi = *reinterpret_cast<uint32_t*>(&h);
    __nv_bfloat162 l = __floats2bfloat162_rn(a - __bfloat162float(h.x),
                                             b - __bfloat162float(h.y));
    lo = *reinterpret_cast<uint32_t*>(&l);
}
// (a, b) -> packed f16x2 hi + residual f16x2 lo
__device__ __forceinline__ void split2h(float a, float b,
                                        uint32_t& hi, uint32_t& lo) {
    __half2 h = __floats2half2_rn(a, b);
    hi = *reinterpret_cast<uint32_t*>(&h);
    __half2 l = __floats2half2_rn(a - __half2float(__low2half(h)),
                                  b - __half2float(__high2half(h)));
    lo = *reinterpret_cast<uint32_t*>(&l);
}
__device__ __forceinline__ uint32_t pack_h2(float a, float b) {
    __half2 h = __floats2half2_rn(a, b);
    return *reinterpret_cast<uint32_t*>(&h);
}

// ---------------------------------------------------------------------------
// Prep kernels
// ---------------------------------------------------------------------------
__global__ void convert_hilo(const float* __restrict__ x,
                             __nv_bfloat16* __restrict__ hi,
                             __nv_bfloat16* __restrict__ lo, int n4) {
    int i = blockIdx.x * blockDim.x + threadIdx.x;
    if (i >= n4) return;
    float4 v = ((const float4*)x)[i];
    uint32_t h0, l0, h1, l1;
    split2(v.x, v.y, h0, l0);
    split2(v.z, v.w, h1, l1);
    uint32_t* hp = (uint32_t*)(hi + (size_t)i * 4); hp[0] = h0; hp[1] = h1;
    uint32_t* lp = (uint32_t*)(lo + (size_t)i * 4); lp[0] = l0; lp[1] = l1;
}

// W [K,N] fp32 row-major  ->  Wt hi/lo [N,K] bf16 row-major (K-major for MMA)
__global__ void transpose_hilo(const float* __restrict__ W,
                               __nv_bfloat16* __restrict__ Th,
                               __nv_bfloat16* __restrict__ Tl, int K, int N) {
    __shared__ float t[32][33];
    int tx = threadIdx.x, ty = threadIdx.y;
    int n0 = blockIdx.x * 32, k0 = blockIdx.y * 32;
#pragma unroll
    for (int j = 0; j < 4; j++) {
        int k = k0 + ty + j * 8;
        t[ty + j * 8][tx] = W[(size_t)k * N + n0 + tx];
    }
    __syncthreads();
#pragma unroll
    for (int j = 0; j < 4; j++) {
        int n = n0 + ty + j * 8;
        float v = t[tx][ty + j * 8];
        __nv_bfloat16 h = __float2bfloat16_rn(v);
        Th[(size_t)n * K + k0 + tx] = h;
        Tl[(size_t)n * K + k0 + tx] = __float2bfloat16_rn(v - __bfloat162float(h));
    }
}

// ---------------------------------------------------------------------------
// mma.sync bf16x3 GEMM, 2-stage cp.async pipeline, 2 CTAs/SM.
// MODE 0: C = A@Wt^T + bias (fp32 out)
// MODE 1: QKV epilogue -> Q f16 hi/lo (scaled), K f16 single, V f16 hi/lo
// ---------------------------------------------------------------------------
#define CH_K   32
#define LDT_B  80
#define TILE_B (128 * LDT_B)
#define STAGE_B (4 * TILE_B)             // 40960 B
#define GEMM_SMEM (2 * STAGE_B)          // 81920 B -> 2 CTAs/SM

__device__ __forceinline__ void issue_tile(const __nv_bfloat16* __restrict__ g,
                                           int row0, int K, int kt,
                                           uint32_t smem, int tid) {
#pragma unroll
    for (int i = 0; i < 2; i++) {
        int v = tid + i * 256;
        int r = v >> 2, c = v & 3;
        const __nv_bfloat16* src = g + (size_t)(row0 + r) * K + kt + c * 8;
        uint32_t dst = smem + (uint32_t)(r * LDT_B + c * 16);
        CP_ASYNC16(dst, src);
    }
}

template<int MODE>
__global__ __launch_bounds__(256, 2) void gemm_tc(
    const __nv_bfloat16* __restrict__ Ah, const __nv_bfloat16* __restrict__ Al,
    const __nv_bfloat16* __restrict__ Bh, const __nv_bfloat16* __restrict__ Bl,
    const float* __restrict__ bias, float* __restrict__ C,
    __half* __restrict__ Qh, __half* __restrict__ Ql,
    __half* __restrict__ Kh,
    __half* __restrict__ Vh, __half* __restrict__ Vl,
    int M, int N, int K)
{
    extern __shared__ char sm[];
    uint32_t sb = smem_u32(sm);
    const int tid  = threadIdx.x;
    const int lane = tid & 31;
    const int wid  = tid >> 5;
    const int m0   = (wid & 3) * 32;
    const int n0   = (wid >> 2) * 64;
    const int bm   = blockIdx.y * 128;
    const int bn   = blockIdx.x * 128;

    float acc[2][8][4];
#pragma unroll
    for (int i = 0; i < 2; i++)
#pragma unroll
        for (int j = 0; j < 8; j++)
#pragma unroll
            for (int q = 0; q < 4; q++) acc[i][j][q] = 0.f;

    const uint32_t a_row  = lane & 15;
    const uint32_t a_koff = ((lane >> 4) & 1) * 16;
    const uint32_t b_rin  = ((lane >> 4) & 1) * 8 + (lane & 7);
    const uint32_t b_koff = ((lane >> 3) & 1) * 16;

    const int NCH = K / CH_K;

    // prologue: stage chunks 0, 1
#pragma unroll
    for (int p = 0; p < 2; p++) {
        uint32_t bb = sb + p * STAGE_B;
        issue_tile(Ah, bm, K, p * CH_K, bb + 0 * TILE_B, tid);
        issue_tile(Al, bm, K, p * CH_K, bb + 1 * TILE_B, tid);
        issue_tile(Bh, bn, K, p * CH_K, bb + 2 * TILE_B, tid);
        issue_tile(Bl, bn, K, p * CH_K, bb + 3 * TILE_B, tid);
        CP_COMMIT();
    }

    for (int c = 0; c < NCH; c++) {
        if (c + 1 < NCH) { CP_WAIT1(); } else { CP_WAIT0(); }
        __syncthreads();

        uint32_t bb   = sb + (uint32_t)(c & 1) * STAGE_B;
        uint32_t Ah_s = bb + 0 * TILE_B;
        uint32_t Al_s = bb + 1 * TILE_B;
        uint32_t Bh_s = bb + 2 * TILE_B;
        uint32_t Bl_s = bb + 3 * TILE_B;

#pragma unroll
        for (int kk = 0; kk < 2; kk++) {
            uint32_t ah[2][4], al[2][4];
#pragma unroll
            for (int i = 0; i < 2; i++) {
                uint32_t ro = (uint32_t)(m0 + i * 16 + a_row) * LDT_B
                              + kk * 32 + a_koff;
                LDSM_X4(ah[i][0], ah[i][1], ah[i][2], ah[i][3], Ah_s + ro);
                LDSM_X4(al[i][0], al[i][1], al[i][2], al[i][3], Al_s + ro);
            }
#pragma unroll
            for (int jp = 0; jp < 4; jp++) {
                uint32_t ro = (uint32_t)(n0 + jp * 16 + b_rin) * LDT_B
                              + kk * 32 + b_koff;
                uint32_t bh[4], bl[4];
                LDSM_X4(bh[0], bh[1], bh[2], bh[3], Bh_s + ro);
                LDSM_X4(bl[0], bl[1], bl[2], bl[3], Bl_s + ro);
                // 12 MMAs over 4 independent accumulators: RAW distance 4
                mma_bf16(acc[0][jp * 2 + 0], ah[0], bh[0], bh[1]);
                mma_bf16(acc[0][jp * 2 + 1], ah[0], bh[2], bh[3]);
                mma_bf16(acc[1][jp * 2 + 0], ah[1], bh[0], bh[1]);
                mma_bf16(acc[1][jp * 2 + 1], ah[1], bh[2], bh[3]);
                mma_bf16(acc[0][jp * 2 + 0], ah[0], bl[0], bl[1]);
                mma_bf16(acc[0][jp * 2 + 1], ah[0], bl[2], bl[3]);
                mma_bf16(acc[1][jp * 2 + 0], ah[1], bl[0], bl[1]);
                mma_bf16(acc[1][jp * 2 + 1], ah[1], bl[2], bl[3]);
                mma_bf16(acc[0][jp * 2 + 0], al[0], bh[0], bh[1]);
                mma_bf16(acc[0][jp * 2 + 1], al[0], bh[2], bh[3]);
                mma_bf16(acc[1][jp * 2 + 0], al[1], bh[0], bh[1]);
                mma_bf16(acc[1][jp * 2 + 1], al[1], bh[2], bh[3]);
            }
        }
        __syncthreads();
        if (c + 2 < NCH) {
            uint32_t nb = sb + (uint32_t)(c & 1) * STAGE_B;
            int kt = (c + 2) * CH_K;
            issue_tile(Ah, bm, K, kt, nb + 0 * TILE_B, tid);
            issue_tile(Al, bm, K, kt, nb + 1 * TILE_B, tid);
            issue_tile(Bh, bn, K, kt, nb + 2 * TILE_B, tid);
            issue_tile(Bl, bn, K, kt, nb + 3 * TILE_B, tid);
        }
        CP_COMMIT();
    }

    const int rrow = lane >> 2;
    const int rcol = (lane & 3) * 2;
#pragma unroll
    for (int i = 0; i < 2; i++) {
        int r_lo = bm + m0 + i * 16 + rrow;
#pragma unroll
        for (int half = 0; half < 2; half++) {
            int row = r_lo + half * 8;
#pragma unroll
            for (int j = 0; j < 8; j++) {
                int col = bn + n0 + j * 8 + rcol;
                float b0 = bias[col], b1 = bias[col + 1];
                float v0 = acc[i][j][half * 2 + 0] + b0;
                float v1 = acc[i][j][half * 2 + 1] + b1;
                if (MODE == 0) {
                    *(float2*)&C[(size_t)row * N + col] = make_float2(v0, v1);
                } else {
                    int sec = col >> 10;           // 0=q 1=k 2=v
                    int hh  = (col & 1023) >> 6;
                    int d   = col & 63;
                    int b   = row >> 11, s = row & 2047;
                    size_t dst = (((size_t)(b * NH + hh)) * S_LEN + s) * HD + d;
                    uint32_t hi, lo;
                    if (sec == 0) {                // Q: scale + base-2 fold, f16 hi/lo
                        v0 *= 0.125f * LOG2E;
                        v1 *= 0.125f * LOG2E;
                        split2h(v0, v1, hi, lo);
                        *(uint32_t*)(Qh + dst) = hi;
                        *(uint32_t*)(Ql + dst) = lo;
                    } else if (sec == 1) {         // K: single f16
                        *(uint32_t*)(Kh + dst) = pack_h2(v0, v1);
                    } else {                       // V: f16 hi/lo
                        split2h(v0, v1, hi, lo);
                        *(uint32_t*)(Vh + dst) = hi;
                        *(uint32_t*)(Vl + dst) = lo;
                    }
                }
            }
        }
    }
}

// ---------------------------------------------------------------------------
// Tensor-core flash attention (causal).
// QK^T: Q f16 hi/lo x K single f16 (2 terms).  PV: P f16 x V f16 hi/lo.
// Scores pre-scaled by log2(e) (via Q) -> softmax uses exp2f.
// Epilogue writes ctx directly as bf16 hi/lo (dense-GEMM input).
// ---------------------------------------------------------------------------
#define ALD      144
#define KV_TILE  (64 * ALD)          // 9216 B
#define Q_TILE   (128 * ALD)         // 18432 B
#define FA_STAGE (3 * KV_TILE)       // K, Vh, Vl = 27648 B
#define FA_SMEM  (3 * FA_STAGE)      // 82944 B

__global__ __launch_bounds__(256, 2) void flash_tc(
    const __half* __restrict__ Qh, const __half* __restrict__ Ql,
    const __half* __restrict__ Kh,
    const __half* __restrict__ Vh, const __half* __restrict__ Vl,
    __nv_bfloat16* __restrict__ Ch, __nv_bfloat16* __restrict__ Cl)
{
    extern __shared__ char sm[];
    uint32_t sb = smem_u32(sm);
    const int tid = threadIdx.x, lane = tid & 31, wid = tid >> 5;
    const int qb = (int)gridDim.x - 1 - (int)blockIdx.x;   // big tiles first
    const int h = blockIdx.y, b = blockIdx.z;
    const size_t hoff = ((size_t)(b * NH + h)) * S_LEN * HD;
    const __half* Qh_g = Qh + hoff + (size_t)qb * 128 * HD;
    const __half* Ql_g = Ql + hoff + (size_t)qb * 128 * HD;
    const __half* Kh_g = Kh + hoff;
    const __half* Vh_g = Vh + hoff;
    const __half* Vl_g = Vl + hoff;

    // ---- stage Q (hi at sb, lo at sb + Q_TILE), load fragments ----
#pragma unroll
    for (int i = 0; i < 4; i++) {
        int idx = tid + i * 256;
        int r = idx >> 3, c = idx & 7;
        uint32_t d = sb + (uint32_t)(r * ALD + c * 16);
        CP_ASYNC16(d, Qh_g + r * HD + c * 8);
        CP_ASYNC16(d + Q_TILE, Ql_g + r * HD + c * 8);
    }
    CP_COMMIT(); CP_WAIT0(); __syncthreads();

    uint32_t qh[4][4], ql[4][4];
    {
        uint32_t base = sb + (uint32_t)((wid * 16 + (lane & 15)) * ALD)
                        + ((lane >> 4) & 1) * 16;
#pragma unroll
        for (int ks = 0; ks < 4; ks++) {
            LDSM_X4(qh[ks][0], qh[ks][1], qh[ks][2], qh[ks][3], base + ks * 32);
            LDSM_X4(ql[ks][0], ql[ks][1], ql[ks][2], ql[ks][3],
                    base + Q_TILE + ks * 32);
        }
    }
    __syncthreads();

    float o[8][4];
#pragma unroll
    for (int j = 0; j < 8; j++)
#pragma unroll
        for (int q = 0; q < 4; q++) o[j][q] = 0.f;
    float m[2] = {-1e30f, -1e30f}, l[2] = {0.f, 0.f};

    const uint32_t b_rin  = ((lane >> 4) & 1) * 8 + (lane & 7);
    const uint32_t b_koff = ((lane >> 3) & 1) * 16;
    const uint32_t v_row  = (lane & 7) + ((lane >> 3) & 1) * 8;
    const uint32_t v_coff = ((lane >> 4) & 1) * 16;

    const int nIter = 2 * qb + 2;

    // prologue: stage key-blocks 0, 1 into slots 0, 1
#pragma unroll
    for (int p = 0; p < 2; p++) {
        if (p < nIter) {
            uint32_t nb = sb + (uint32_t)p * FA_STAGE;
            int kbase = p * 64 * HD;
#pragma unroll
            for (int i = 0; i < 2; i++) {
                int idx = tid + i * 256;
                int r = idx >> 3, c = idx & 7;
                uint32_t d = nb + (uint32_t)(r * ALD + c * 16);
                int go = kbase + r * HD + c * 8;
                CP_ASYNC16(d + 0 * KV_TILE, Kh_g + go);
                CP_ASYNC16(d + 1 * KV_TILE, Vh_g + go);
                CP_ASYNC16(d + 2 * KV_TILE, Vl_g + go);
            }
            CP_COMMIT();
        }
    }

    for (int it = 0; it < nIter; it++) {
        if (it + 1 < nIter) { CP_WAIT1(); } else { CP_WAIT0(); }
        __syncthreads();

        if (it + 2 < nIter) {
            uint32_t nb = sb + (uint32_t)((it + 2) % 3) * FA_STAGE;
            int kbase = (it + 2) * 64 * HD;
#pragma unroll
            for (int i = 0; i < 2; i++) {
                int idx = tid + i * 256;
                int r = idx >> 3, c = idx & 7;
                uint32_t d = nb + (uint32_t)(r * ALD + c * 16);
                int go = kbase + r * HD + c * 8;
                CP_ASYNC16(d + 0 * KV_TILE, Kh_g + go);
                CP_ASYNC16(d + 1 * KV_TILE, Vh_g + go);
                CP_ASYNC16(d + 2 * KV_TILE, Vl_g + go);
            }
            CP_COMMIT();
        }

        uint32_t bb = sb + (uint32_t)(it % 3) * FA_STAGE;

        // ---- S = Q K^T (Q hi/lo f16 x K single f16), interleaved accs ----
        float s[8][4];
#pragma unroll
        for (int j = 0; j < 8; j++)
#pragma unroll
            for (int q = 0; q < 4; q++) s[j][q] = 0.f;

#pragma unroll
        for (int ks = 0; ks < 4; ks++) {
#pragma unroll
            for (int jp = 0; jp < 4; jp++) {
                uint32_t ka = bb + (uint32_t)((jp * 16 + b_rin) * ALD)
                              + ks * 32 + b_koff;
                uint32_t k0, k1, k2, k3;
                LDSM_X4(k0, k1, k2, k3, ka);
                mma_f16(s[jp * 2 + 0], qh[ks], k0, k1);
                mma_f16(s[jp * 2 + 1], qh[ks], k2, k3);
                mma_f16(s[jp * 2 + 0], ql[ks], k0, k1);
                mma_f16(s[jp * 2 + 1], ql[ks], k2, k3);
            }
        }

        // ---- causal mask ----
        if (it >= 2 * qb) {
            int col0 = it * 64 + (lane & 3) * 2;
#pragma unroll
            for (int rr = 0; rr < 2; rr++) {
                int row = qb * 128 + wid * 16 + (lane >> 2) + rr * 8;
#pragma unroll
                for (int j = 0; j < 8; j++) {
                    int c0 = col0 + j * 8;
                    if (c0 > row)     s[j][rr * 2 + 0] = -1e30f;
                    if (c0 + 1 > row) s[j][rr * 2 + 1] = -1e30f;
                }
            }
        }

        // ---- online softmax (base-2 domain; scores pre-scaled by log2e) ----
#pragma unroll
        for (int rr = 0; rr < 2; rr++) {
            float lm = -1e30f;
#pragma unroll
            for (int j = 0; j < 8; j++)
                lm = fmaxf(lm, fmaxf(s[j][rr * 2], s[j][rr * 2 + 1]));
            lm = fmaxf(lm, __shfl_xor_sync(0xffffffffu, lm, 1));
            lm = fmaxf(lm, __shfl_xor_sync(0xffffffffu, lm, 2));
            float mn = fmaxf(m[rr], lm);
            float corr = exp2f(m[rr] - mn);
            float sum = 0.f;
#pragma unroll
            for (int j = 0; j < 8; j++) {
                float p0 = exp2f(s[j][rr * 2 + 0] - mn);
                float p1 = exp2f(s[j][rr * 2 + 1] - mn);
                s[j][rr * 2 + 0] = p0;
                s[j][rr * 2 + 1] = p1;
                sum += p0 + p1;
            }
            sum += __shfl_xor_sync(0xffffffffu, sum, 1);
            sum += __shfl_xor_sync(0xffffffffu, sum, 2);
            l[rr] = l[rr] * corr + sum;
            m[rr] = mn;
#pragma unroll
            for (int j = 0; j < 8; j++) {
                o[j][rr * 2 + 0] *= corr;
                o[j][rr * 2 + 1] *= corr;
            }
        }

        // ---- O += P V  (P single f16, V f16 hi/lo: 2 MMA terms) ----
#pragma unroll
        for (int ks = 0; ks < 4; ks++) {
            uint32_t p16[4];
            p16[0] = pack_h2(s[2 * ks][0],     s[2 * ks][1]);
            p16[1] = pack_h2(s[2 * ks][2],     s[2 * ks][3]);
            p16[2] = pack_h2(s[2 * ks + 1][0], s[2 * ks + 1][1]);
            p16[3] = pack_h2(s[2 * ks + 1][2], s[2 * ks + 1][3]);
            uint32_t va = bb + 1 * KV_TILE
                          + (uint32_t)((ks * 16 + v_row) * ALD) + v_coff;
#pragma unroll
            for (int ng = 0; ng < 4; ng++) {
                uint32_t vh0, vh1, vh2, vh3, vl0, vl1, vl2, vl3;
                LDSM_X4_T(vh0, vh1, vh2, vh3, va + ng * 32);
                LDSM_X4_T(vl0, vl1, vl2, vl3, va + ng * 32 + KV_TILE);
                mma_f16(o[ng * 2 + 0], p16, vh0, vh1);
                mma_f16(o[ng * 2 + 1], p16, vh2, vh3);
                mma_f16(o[ng * 2 + 0], p16, vl0, vl1);
                mma_f16(o[ng * 2 + 1], p16, vl2, vl3);
            }
        }
    }

    // ---- epilogue: O/l -> ctx bf16 hi/lo [tok][H] ----
#pragma unroll
    for (int rr = 0; rr < 2; rr++) {
        float inv = 1.0f / l[rr];
        int tok = b * S_LEN + qb * 128 + wid * 16 + (lane >> 2) + rr * 8;
#pragma unroll
        for (int j = 0; j < 8; j++) {
            int col = h * HD + j * 8 + (lane & 3) * 2;
            uint32_t hi, lo;
            split2(o[j][rr * 2 + 0] * inv, o[j][rr * 2 + 1] * inv, hi, lo);
            *(uint32_t*)(Ch + (size_t)tok * HID + col) = hi;
            *(uint32_t*)(Cl + (size_t)tok * HID + col) = lo;
        }
    }
}

// ---------------------------------------------------------------------------
extern "C" void kernel_launch(void* const* d_in, const int* in_sizes, int n_in,
                              void* d_out, int out_size)
{
    (void)in_sizes; (void)n_in; (void)out_size;
    const float* hidden  = (const float*)d_in[0];
    // d_in[1] = ltor_mask: exactly causal lower-triangular; handled analytically
    const float* W_qkv   = (const float*)d_in[2];
    const float* b_qkv   = (const float*)d_in[3];
    const float* W_dense = (const float*)d_in[4];
    const float* b_dense = (const float*)d_in[5];
    float* out = (float*)d_out;

    __nv_bfloat16 *ah, *al, *bh, *bl;
    __half *qhp, *qlp, *khp, *vhp, *vlp;
    cudaGetSymbolAddress((void**)&ah, g_Ah);
    cudaGetSymbolAddress((void**)&al, g_Al);
    cudaGetSymbolAddress((void**)&bh, g_Bh);
    cudaGetSymbolAddress((void**)&bl, g_Bl);
    cudaGetSymbolAddress((void**)&qhp, g_Qh);
    cudaGetSymbolAddress((void**)&qlp, g_Ql);
    cudaGetSymbolAddress((void**)&khp, g_Kh);
    cudaGetSymbolAddress((void**)&vhp, g_Vh);
    cudaGetSymbolAddress((void**)&vlp, g_Vl);

    cudaFuncSetAttribute(gemm_tc<0>,
                         cudaFuncAttributeMaxDynamicSharedMemorySize, GEMM_SMEM);
    cudaFuncSetAttribute(gemm_tc<1>,
                         cudaFuncAttributeMaxDynamicSharedMemorySize, GEMM_SMEM);
    cudaFuncSetAttribute(flash_tc,
                         cudaFuncAttributeMaxDynamicSharedMemorySize, FA_SMEM);

    // 1) split hidden -> bf16 hi/lo
    {
        int n4 = M_TOK * HID / 4;
        convert_hilo<<<(n4 + 255) / 256, 256>>>(hidden, ah, al, n4);
    }
    // 2) transpose+split W_qkv
    {
        dim3 grid(3 * HID / 32, HID / 32);
        transpose_hilo<<<grid, dim3(32, 8)>>>(W_qkv, bh, bl, HID, 3 * HID);
    }
    // 3) QKV GEMM with fused per-head split epilogue
    {
        dim3 grid(3 * HID / 128, M_TOK / 128);
        gemm_tc<1><<<grid, 256, GEMM_SMEM>>>(ah, al, bh, bl, b_qkv, nullptr,
                                             qhp, qlp, khp, vhp, vlp,
                                             M_TOK, 3 * HID, HID);
    }
    // 4) flash attention -> ctx bf16 hi/lo (into ah/al, dense-GEMM input)
    {
        dim3 grid(S_LEN / 128, NH, B_SZ);
        flash_tc<<<grid, 256, FA_SMEM>>>(qhp, qlp, khp, vhp, vlp, ah, al);
    }
    // 5) transpose+split W_dense
    {
        dim3 grid(HID / 32, HID / 32);
        transpose_hilo<<<grid, dim3(32, 8)>>>(W_dense, bh, bl, HID, HID);
    }
    // 6) dense GEMM -> out (fp32)
    {
        dim3 grid(HID / 128, M_TOK / 128);
        gemm_tc<0><<<grid, 256, GEMM_SMEM>>>(ah, al, bh, bl, b_dense, out,
                                             nullptr, nullptr, nullptr,
                                             nullptr, nullptr,
                                             M_TOK, HID, HID);
    }
}

// round 9
// speedup vs baseline: 6.1167x; 2.0349x over previous
#include <cuda_runtime.h>
#include <cuda_bf16.h>
#include <cuda_fp16.h>
#include <cstdint>
#include <math.h>

#define B_SZ  2
#define S_LEN 2048
#define HID   1024
#define NH    16
#define HD    64
#define M_TOK (B_SZ * S_LEN)     // 4096

#define LOG2E 1.44269504088896341f

// ---------------------------------------------------------------------------
// Scratch (__device__ globals per allocation-free rule) — all single f16 now
// ---------------------------------------------------------------------------
__device__ __half g_A[(size_t)M_TOK * HID];          // activations (input / ctx)
__device__ __half g_B[(size_t)3 * HID * HID];        // weights [N][K]
#define HELEMS ((size_t)B_SZ * NH * S_LEN * HD)
__device__ __half g_Q[HELEMS];                       // Q (scaled by 0.125*log2e)
__device__ __half g_K[HELEMS];
__device__ __half g_V[HELEMS];

// ---------------------------------------------------------------------------
// PTX helpers (family-compatible: mma.sync / ldmatrix / cp.async only)
// ---------------------------------------------------------------------------
__device__ __forceinline__ uint32_t smem_u32(const void* p) {
    uint32_t a;
    asm("{ .reg .u64 t; cvta.to.shared.u64 t, %1; cvt.u32.u64 %0, t; }"
        : "=r"(a) : "l"(p));
    return a;
}

#define CP_ASYNC16(dst, src) \
    asm volatile("cp.async.cg.shared.global [%0], [%1], 16;" \
                 :: "r"(dst), "l"(src) : "memory")
#define CP_COMMIT() asm volatile("cp.async.commit_group;" ::: "memory")
#define CP_WAIT1()  asm volatile("cp.async.wait_group 1;" ::: "memory")
#define CP_WAIT0()  asm volatile("cp.async.wait_group 0;" ::: "memory")

#define LDSM_X4(r0, r1, r2, r3, addr) \
    asm volatile("ldmatrix.sync.aligned.m8n8.x4.shared.b16 {%0,%1,%2,%3}, [%4];" \
                 : "=r"(r0), "=r"(r1), "=r"(r2), "=r"(r3) : "r"(addr))
#define LDSM_X4_T(r0, r1, r2, r3, addr) \
    asm volatile("ldmatrix.sync.aligned.m8n8.x4.trans.shared.b16 {%0,%1,%2,%3}, [%4];" \
                 : "=r"(r0), "=r"(r1), "=r"(r2), "=r"(r3) : "r"(addr))

__device__ __forceinline__ void mma_f16(float* c, const uint32_t* a,
                                        uint32_t b0, uint32_t b1) {
    asm volatile(
        "mma.sync.aligned.m16n8k16.row.col.f32.f16.f16.f32 "
        "{%0,%1,%2,%3}, {%4,%5,%6,%7}, {%8,%9}, {%0,%1,%2,%3};"
        : "+f"(c[0]), "+f"(c[1]), "+f"(c[2]), "+f"(c[3])
        : "r"(a[0]), "r"(a[1]), "r"(a[2]), "r"(a[3]), "r"(b0), "r"(b1));
}

__device__ __forceinline__ uint32_t pack_h2(float a, float b) {
    __half2 h = __floats2half2_rn(a, b);
    return *reinterpret_cast<uint32_t*>(&h);
}

// ---------------------------------------------------------------------------
// Prep kernels
// ---------------------------------------------------------------------------
__global__ void convert_f16(const float* __restrict__ x,
                            __half* __restrict__ y, int n4) {
    int i = blockIdx.x * blockDim.x + threadIdx.x;
    if (i >= n4) return;
    float4 v = ((const float4*)x)[i];
    uint32_t* yp = (uint32_t*)(y + (size_t)i * 4);
    yp[0] = pack_h2(v.x, v.y);
    yp[1] = pack_h2(v.z, v.w);
}

// W [K,N] fp32 row-major  ->  Wt [N,K] f16 row-major (K-major for MMA)
__global__ void transpose_f16(const float* __restrict__ W,
                              __half* __restrict__ T, int K, int N) {
    __shared__ float t[32][33];
    int tx = threadIdx.x, ty = threadIdx.y;
    int n0 = blockIdx.x * 32, k0 = blockIdx.y * 32;
#pragma unroll
    for (int j = 0; j < 4; j++) {
        int k = k0 + ty + j * 8;
        t[ty + j * 8][tx] = W[(size_t)k * N + n0 + tx];
    }
    __syncthreads();
#pragma unroll
    for (int j = 0; j < 4; j++) {
        int n = n0 + ty + j * 8;
        T[(size_t)n * K + k0 + tx] = __float2half_rn(t[tx][ty + j * 8]);
    }
}

// ---------------------------------------------------------------------------
// mma.sync single-f16 GEMM, 3-stage cp.async pipeline, 2 CTAs/SM.
// MODE 0: C = A@Wt^T + bias (fp32 out)
// MODE 1: QKV epilogue -> Q (scaled), K, V single f16 per-head
// ---------------------------------------------------------------------------
#define CH_K   32
#define LDT_B  80
#define TILE_B (128 * LDT_B)             // 10240 B
#define STAGE_B (2 * TILE_B)             // A + B = 20480 B
#define GEMM_SMEM (3 * STAGE_B)          // 61440 B -> 2 CTAs/SM

__device__ __forceinline__ void issue_tile(const __half* __restrict__ g,
                                           int row0, int K, int kt,
                                           uint32_t smem, int tid) {
#pragma unroll
    for (int i = 0; i < 2; i++) {
        int v = tid + i * 256;
        int r = v >> 2, c = v & 3;
        const __half* src = g + (size_t)(row0 + r) * K + kt + c * 8;
        uint32_t dst = smem + (uint32_t)(r * LDT_B + c * 16);
        CP_ASYNC16(dst, src);
    }
}

template<int MODE>
__global__ __launch_bounds__(256, 2) void gemm_tc(
    const __half* __restrict__ A, const __half* __restrict__ B,
    const float* __restrict__ bias, float* __restrict__ C,
    __half* __restrict__ Q, __half* __restrict__ Kd, __half* __restrict__ V,
    int M, int N, int K)
{
    extern __shared__ char sm[];
    uint32_t sb = smem_u32(sm);
    const int tid  = threadIdx.x;
    const int lane = tid & 31;
    const int wid  = tid >> 5;
    const int m0   = (wid & 3) * 32;
    const int n0   = (wid >> 2) * 64;
    const int bm   = blockIdx.y * 128;
    const int bn   = blockIdx.x * 128;

    float acc[2][8][4];
#pragma unroll
    for (int i = 0; i < 2; i++)
#pragma unroll
        for (int j = 0; j < 8; j++)
#pragma unroll
            for (int q = 0; q < 4; q++) acc[i][j][q] = 0.f;

    const uint32_t a_row  = lane & 15;
    const uint32_t a_koff = ((lane >> 4) & 1) * 16;
    const uint32_t b_rin  = ((lane >> 4) & 1) * 8 + (lane & 7);
    const uint32_t b_koff = ((lane >> 3) & 1) * 16;

    const int NCH = K / CH_K;

    // prologue: stage chunks 0, 1 into slots 0, 1
#pragma unroll
    for (int p = 0; p < 2; p++) {
        uint32_t bb = sb + p * STAGE_B;
        issue_tile(A, bm, K, p * CH_K, bb + 0 * TILE_B, tid);
        issue_tile(B, bn, K, p * CH_K, bb + 1 * TILE_B, tid);
        CP_COMMIT();
    }

    for (int c = 0; c < NCH; c++) {
        if (c + 1 < NCH) { CP_WAIT1(); } else { CP_WAIT0(); }
        __syncthreads();   // chunk c visible; slot (c+2)%3 free (read at c-1)

        if (c + 2 < NCH) {
            uint32_t nb = sb + (uint32_t)((c + 2) % 3) * STAGE_B;
            int kt = (c + 2) * CH_K;
            issue_tile(A, bm, K, kt, nb + 0 * TILE_B, tid);
            issue_tile(B, bn, K, kt, nb + 1 * TILE_B, tid);
            CP_COMMIT();
        }

        uint32_t bb  = sb + (uint32_t)(c % 3) * STAGE_B;
        uint32_t A_s = bb + 0 * TILE_B;
        uint32_t B_s = bb + 1 * TILE_B;

#pragma unroll
        for (int kk = 0; kk < 2; kk++) {
            uint32_t af[2][4];
#pragma unroll
            for (int i = 0; i < 2; i++) {
                uint32_t ro = (uint32_t)(m0 + i * 16 + a_row) * LDT_B
                              + kk * 32 + a_koff;
                LDSM_X4(af[i][0], af[i][1], af[i][2], af[i][3], A_s + ro);
            }
#pragma unroll
            for (int jp = 0; jp < 4; jp++) {
                uint32_t ro = (uint32_t)(n0 + jp * 16 + b_rin) * LDT_B
                              + kk * 32 + b_koff;
                uint32_t b0, b1, b2, b3;
                LDSM_X4(b0, b1, b2, b3, B_s + ro);
                mma_f16(acc[0][jp * 2 + 0], af[0], b0, b1);
                mma_f16(acc[0][jp * 2 + 1], af[0], b2, b3);
                mma_f16(acc[1][jp * 2 + 0], af[1], b0, b1);
                mma_f16(acc[1][jp * 2 + 1], af[1], b2, b3);
            }
        }
    }

    const int rrow = lane >> 2;
    const int rcol = (lane & 3) * 2;
#pragma unroll
    for (int i = 0; i < 2; i++) {
        int r_lo = bm + m0 + i * 16 + rrow;
#pragma unroll
        for (int half = 0; half < 2; half++) {
            int row = r_lo + half * 8;
#pragma unroll
            for (int j = 0; j < 8; j++) {
                int col = bn + n0 + j * 8 + rcol;
                float b0 = bias[col], b1 = bias[col + 1];
                float v0 = acc[i][j][half * 2 + 0] + b0;
                float v1 = acc[i][j][half * 2 + 1] + b1;
                if (MODE == 0) {
                    *(float2*)&C[(size_t)row * N + col] = make_float2(v0, v1);
                } else {
                    int sec = col >> 10;           // 0=q 1=k 2=v
                    int hh  = (col & 1023) >> 6;
                    int d   = col & 63;
                    int b   = row >> 11, s = row & 2047;
                    size_t dst = (((size_t)(b * NH + hh)) * S_LEN + s) * HD + d;
                    if (sec == 0) {                // Q: scale + base-2 fold
                        v0 *= 0.125f * LOG2E;
                        v1 *= 0.125f * LOG2E;
                    }
                    __half* p = (sec == 0) ? Q : (sec == 1) ? Kd : V;
                    *(uint32_t*)(p + dst) = pack_h2(v0, v1);
                }
            }
        }
    }
}

// ---------------------------------------------------------------------------
// Tensor-core flash attention (causal), all-f16 single precision operands.
// Scores pre-scaled by log2(e) (via Q) -> softmax uses exp2f.
// Epilogue writes ctx directly as f16 (dense-GEMM input).
// ---------------------------------------------------------------------------
#define ALD      144
#define KV_TILE  (64 * ALD)          // 9216 B
#define FA_STAGE (2 * KV_TILE)       // K, V = 18432 B
#define FA_SMEM  (3 * FA_STAGE)      // 55296 B

__global__ __launch_bounds__(256, 2) void flash_tc(
    const __half* __restrict__ Q,
    const __half* __restrict__ K,
    const __half* __restrict__ V,
    __half* __restrict__ Cc)
{
    extern __shared__ char sm[];
    uint32_t sb = smem_u32(sm);
    const int tid = threadIdx.x, lane = tid & 31, wid = tid >> 5;
    const int qb = (int)gridDim.x - 1 - (int)blockIdx.x;   // big tiles first
    const int h = blockIdx.y, b = blockIdx.z;
    const size_t hoff = ((size_t)(b * NH + h)) * S_LEN * HD;
    const __half* Q_g = Q + hoff + (size_t)qb * 128 * HD;
    const __half* K_g = K + hoff;
    const __half* V_g = V + hoff;

    // ---- stage Q (temporarily at sb), load fragments ----
#pragma unroll
    for (int i = 0; i < 4; i++) {
        int idx = tid + i * 256;
        int r = idx >> 3, c = idx & 7;
        CP_ASYNC16(sb + (uint32_t)(r * ALD + c * 16), Q_g + r * HD + c * 8);
    }
    CP_COMMIT(); CP_WAIT0(); __syncthreads();

    uint32_t qf[4][4];
    {
        uint32_t base = sb + (uint32_t)((wid * 16 + (lane & 15)) * ALD)
                        + ((lane >> 4) & 1) * 16;
#pragma unroll
        for (int ks = 0; ks < 4; ks++)
            LDSM_X4(qf[ks][0], qf[ks][1], qf[ks][2], qf[ks][3], base + ks * 32);
    }
    __syncthreads();

    float o[8][4];
#pragma unroll
    for (int j = 0; j < 8; j++)
#pragma unroll
        for (int q = 0; q < 4; q++) o[j][q] = 0.f;
    float m[2] = {-1e30f, -1e30f}, l[2] = {0.f, 0.f};

    const uint32_t b_rin  = ((lane >> 4) & 1) * 8 + (lane & 7);
    const uint32_t b_koff = ((lane >> 3) & 1) * 16;
    const uint32_t v_row  = (lane & 7) + ((lane >> 3) & 1) * 8;
    const uint32_t v_coff = ((lane >> 4) & 1) * 16;

    const int nIter = 2 * qb + 2;

    // prologue: stage key-blocks 0, 1 into slots 0, 1
#pragma unroll
    for (int p = 0; p < 2; p++) {
        if (p < nIter) {
            uint32_t nb = sb + (uint32_t)p * FA_STAGE;
            int kbase = p * 64 * HD;
#pragma unroll
            for (int i = 0; i < 2; i++) {
                int idx = tid + i * 256;
                int r = idx >> 3, c = idx & 7;
                uint32_t d = nb + (uint32_t)(r * ALD + c * 16);
                int go = kbase + r * HD + c * 8;
                CP_ASYNC16(d + 0 * KV_TILE, K_g + go);
                CP_ASYNC16(d + 1 * KV_TILE, V_g + go);
            }
            CP_COMMIT();
        }
    }

    for (int it = 0; it < nIter; it++) {
        if (it + 1 < nIter) { CP_WAIT1(); } else { CP_WAIT0(); }
        __syncthreads();

        if (it + 2 < nIter) {
            uint32_t nb = sb + (uint32_t)((it + 2) % 3) * FA_STAGE;
            int kbase = (it + 2) * 64 * HD;
#pragma unroll
            for (int i = 0; i < 2; i++) {
                int idx = tid + i * 256;
                int r = idx >> 3, c = idx & 7;
                uint32_t d = nb + (uint32_t)(r * ALD + c * 16);
                int go = kbase + r * HD + c * 8;
                CP_ASYNC16(d + 0 * KV_TILE, K_g + go);
                CP_ASYNC16(d + 1 * KV_TILE, V_g + go);
            }
            CP_COMMIT();
        }

        uint32_t bb = sb + (uint32_t)(it % 3) * FA_STAGE;

        // ---- S = Q K^T (single f16), interleaved accumulators ----
        float s[8][4];
#pragma unroll
        for (int j = 0; j < 8; j++)
#pragma unroll
            for (int q = 0; q < 4; q++) s[j][q] = 0.f;

#pragma unroll
        for (int ks = 0; ks < 4; ks++) {
#pragma unroll
            for (int jp = 0; jp < 4; jp++) {
                uint32_t ka = bb + (uint32_t)((jp * 16 + b_rin) * ALD)
                              + ks * 32 + b_koff;
                uint32_t k0, k1, k2, k3;
                LDSM_X4(k0, k1, k2, k3, ka);
                mma_f16(s[jp * 2 + 0], qf[ks], k0, k1);
                mma_f16(s[jp * 2 + 1], qf[ks], k2, k3);
            }
        }

        // ---- causal mask ----
        if (it >= 2 * qb) {
            int col0 = it * 64 + (lane & 3) * 2;
#pragma unroll
            for (int rr = 0; rr < 2; rr++) {
                int row = qb * 128 + wid * 16 + (lane >> 2) + rr * 8;
#pragma unroll
                for (int j = 0; j < 8; j++) {
                    int c0 = col0 + j * 8;
                    if (c0 > row)     s[j][rr * 2 + 0] = -1e30f;
                    if (c0 + 1 > row) s[j][rr * 2 + 1] = -1e30f;
                }
            }
        }

        // ---- online softmax (base-2 domain) ----
#pragma unroll
        for (int rr = 0; rr < 2; rr++) {
            float lm = -1e30f;
#pragma unroll
            for (int j = 0; j < 8; j++)
                lm = fmaxf(lm, fmaxf(s[j][rr * 2], s[j][rr * 2 + 1]));
            lm = fmaxf(lm, __shfl_xor_sync(0xffffffffu, lm, 1));
            lm = fmaxf(lm, __shfl_xor_sync(0xffffffffu, lm, 2));
            float mn = fmaxf(m[rr], lm);
            float corr = exp2f(m[rr] - mn);
            float sum = 0.f;
#pragma unroll
            for (int j = 0; j < 8; j++) {
                float p0 = exp2f(s[j][rr * 2 + 0] - mn);
                float p1 = exp2f(s[j][rr * 2 + 1] - mn);
                s[j][rr * 2 + 0] = p0;
                s[j][rr * 2 + 1] = p1;
                sum += p0 + p1;
            }
            sum += __shfl_xor_sync(0xffffffffu, sum, 1);
            sum += __shfl_xor_sync(0xffffffffu, sum, 2);
            l[rr] = l[rr] * corr + sum;
            m[rr] = mn;
#pragma unroll
            for (int j = 0; j < 8; j++) {
                o[j][rr * 2 + 0] *= corr;
                o[j][rr * 2 + 1] *= corr;
            }
        }

        // ---- O += P V  (single f16) ----
#pragma unroll
        for (int ks = 0; ks < 4; ks++) {
            uint32_t p16[4];
            p16[0] = pack_h2(s[2 * ks][0],     s[2 * ks][1]);
            p16[1] = pack_h2(s[2 * ks][2],     s[2 * ks][3]);
            p16[2] = pack_h2(s[2 * ks + 1][0], s[2 * ks + 1][1]);
            p16[3] = pack_h2(s[2 * ks + 1][2], s[2 * ks + 1][3]);
            uint32_t va = bb + KV_TILE
                          + (uint32_t)((ks * 16 + v_row) * ALD) + v_coff;
#pragma unroll
            for (int ng = 0; ng < 4; ng++) {
                uint32_t v0, v1, v2, v3;
                LDSM_X4_T(v0, v1, v2, v3, va + ng * 32);
                mma_f16(o[ng * 2 + 0], p16, v0, v1);
                mma_f16(o[ng * 2 + 1], p16, v2, v3);
            }
        }
    }

    // ---- epilogue: O/l -> ctx f16 [tok][H] ----
#pragma unroll
    for (int rr = 0; rr < 2; rr++) {
        float inv = 1.0f / l[rr];
        int tok = b * S_LEN + qb * 128 + wid * 16 + (lane >> 2) + rr * 8;
#pragma unroll
        for (int j = 0; j < 8; j++) {
            int col = h * HD + j * 8 + (lane & 3) * 2;
            *(uint32_t*)(Cc + (size_t)tok * HID + col) =
                pack_h2(o[j][rr * 2 + 0] * inv, o[j][rr * 2 + 1] * inv);
        }
    }
}

// ---------------------------------------------------------------------------
extern "C" void kernel_launch(void* const* d_in, const int* in_sizes, int n_in,
                              void* d_out, int out_size)
{
    (void)in_sizes; (void)n_in; (void)out_size;
    const float* hidden  = (const float*)d_in[0];
    // d_in[1] = ltor_mask: exactly causal lower-triangular; handled analytically
    const float* W_qkv   = (const float*)d_in[2];
    const float* b_qkv   = (const float*)d_in[3];
    const float* W_dense = (const float*)d_in[4];
    const float* b_dense = (const float*)d_in[5];
    float* out = (float*)d_out;

    __half *a, *bw, *qp, *kp, *vp;
    cudaGetSymbolAddress((void**)&a,  g_A);
    cudaGetSymbolAddress((void**)&bw, g_B);
    cudaGetSymbolAddress((void**)&qp, g_Q);
    cudaGetSymbolAddress((void**)&kp, g_K);
    cudaGetSymbolAddress((void**)&vp, g_V);

    cudaFuncSetAttribute(gemm_tc<0>,
                         cudaFuncAttributeMaxDynamicSharedMemorySize, GEMM_SMEM);
    cudaFuncSetAttribute(gemm_tc<1>,
                         cudaFuncAttributeMaxDynamicSharedMemorySize, GEMM_SMEM);
    cudaFuncSetAttribute(flash_tc,
                         cudaFuncAttributeMaxDynamicSharedMemorySize, FA_SMEM);

    // 1) convert hidden -> f16
    {
        int n4 = M_TOK * HID / 4;
        convert_f16<<<(n4 + 255) / 256, 256>>>(hidden, a, n4);
    }
    // 2) transpose W_qkv -> f16 [N][K]
    {
        dim3 grid(3 * HID / 32, HID / 32);
        transpose_f16<<<grid, dim3(32, 8)>>>(W_qkv, bw, HID, 3 * HID);
    }
    // 3) QKV GEMM with fused per-head epilogue (Q scaled 0.125*log2e)
    {
        dim3 grid(3 * HID / 128, M_TOK / 128);
        gemm_tc<1><<<grid, 256, GEMM_SMEM>>>(a, bw, b_qkv, nullptr,
                                             qp, kp, vp, M_TOK, 3 * HID, HID);
    }
    // 4) flash attention -> ctx f16 (into g_A, dense-GEMM input)
    {
        dim3 grid(S_LEN / 128, NH, B_SZ);
        flash_tc<<<grid, 256, FA_SMEM>>>(qp, kp, vp, a);
    }
    // 5) transpose W_dense -> f16
    {
        dim3 grid(HID / 32, HID / 32);
        transpose_f16<<<grid, dim3(32, 8)>>>(W_dense, bw, HID, HID);
    }
    // 6) dense GEMM -> out (fp32)
    {
        dim3 grid(HID / 128, M_TOK / 128);
        gemm_tc<0><<<grid, 256, GEMM_SMEM>>>(a, bw, b_dense, out,
                                             nullptr, nullptr, nullptr,
                                             M_TOK, HID, HID);
    }
}

// round 10
// speedup vs baseline: 6.4602x; 1.0562x over previous
#include <cuda_runtime.h>
#include <cuda_bf16.h>
#include <cuda_fp16.h>
#include <cstdint>
#include <math.h>

#define B_SZ  2
#define S_LEN 2048
#define HID   1024
#define NH    16
#define HD    64
#define M_TOK (B_SZ * S_LEN)     // 4096

#define LOG2E 1.44269504088896341f

// ---------------------------------------------------------------------------
// Scratch (__device__ globals per allocation-free rule) — all single f16
// ---------------------------------------------------------------------------
__device__ __half g_A[(size_t)M_TOK * HID];          // activations (input / ctx)
__device__ __half g_B[(size_t)3 * HID * HID];        // weights [N][K]
#define HELEMS ((size_t)B_SZ * NH * S_LEN * HD)
__device__ __half g_Q[HELEMS];                       // Q (scaled by 0.125*log2e)
__device__ __half g_K[HELEMS];
__device__ __half g_V[HELEMS];

// ---------------------------------------------------------------------------
// PTX helpers (family-compatible: mma.sync / ldmatrix / cp.async only)
// ---------------------------------------------------------------------------
__device__ __forceinline__ uint32_t smem_u32(const void* p) {
    uint32_t a;
    asm("{ .reg .u64 t; cvta.to.shared.u64 t, %1; cvt.u32.u64 %0, t; }"
        : "=r"(a) : "l"(p));
    return a;
}

#define CP_ASYNC16(dst, src) \
    asm volatile("cp.async.cg.shared.global [%0], [%1], 16;" \
                 :: "r"(dst), "l"(src) : "memory")
#define CP_COMMIT() asm volatile("cp.async.commit_group;" ::: "memory")
#define CP_WAIT1()  asm volatile("cp.async.wait_group 1;" ::: "memory")
#define CP_WAIT0()  asm volatile("cp.async.wait_group 0;" ::: "memory")

#define LDSM_X4(r0, r1, r2, r3, addr) \
    asm volatile("ldmatrix.sync.aligned.m8n8.x4.shared.b16 {%0,%1,%2,%3}, [%4];" \
                 : "=r"(r0), "=r"(r1), "=r"(r2), "=r"(r3) : "r"(addr))
#define LDSM_X4_T(r0, r1, r2, r3, addr) \
    asm volatile("ldmatrix.sync.aligned.m8n8.x4.trans.shared.b16 {%0,%1,%2,%3}, [%4];" \
                 : "=r"(r0), "=r"(r1), "=r"(r2), "=r"(r3) : "r"(addr))

__device__ __forceinline__ void mma_f16(float* c, const uint32_t* a,
                                        uint32_t b0, uint32_t b1) {
    asm volatile(
        "mma.sync.aligned.m16n8k16.row.col.f32.f16.f16.f32 "
        "{%0,%1,%2,%3}, {%4,%5,%6,%7}, {%8,%9}, {%0,%1,%2,%3};"
        : "+f"(c[0]), "+f"(c[1]), "+f"(c[2]), "+f"(c[3])
        : "r"(a[0]), "r"(a[1]), "r"(a[2]), "r"(a[3]), "r"(b0), "r"(b1));
}

__device__ __forceinline__ uint32_t pack_h2(float a, float b) {
    __half2 h = __floats2half2_rn(a, b);
    return *reinterpret_cast<uint32_t*>(&h);
}

// ---------------------------------------------------------------------------
// Prep kernels
// ---------------------------------------------------------------------------
__global__ void convert_f16(const float* __restrict__ x,
                            __half* __restrict__ y, int n4) {
    int i = blockIdx.x * blockDim.x + threadIdx.x;
    if (i >= n4) return;
    float4 v = ((const float4*)x)[i];
    uint32_t* yp = (uint32_t*)(y + (size_t)i * 4);
    yp[0] = pack_h2(v.x, v.y);
    yp[1] = pack_h2(v.z, v.w);
}

// W [K,N] fp32 row-major  ->  Wt [N,K] f16 row-major (K-major for MMA)
__global__ void transpose_f16(const float* __restrict__ W,
                              __half* __restrict__ T, int K, int N) {
    __shared__ float t[32][33];
    int tx = threadIdx.x, ty = threadIdx.y;
    int n0 = blockIdx.x * 32, k0 = blockIdx.y * 32;
#pragma unroll
    for (int j = 0; j < 4; j++) {
        int k = k0 + ty + j * 8;
        t[ty + j * 8][tx] = W[(size_t)k * N + n0 + tx];
    }
    __syncthreads();
#pragma unroll
    for (int j = 0; j < 4; j++) {
        int n = n0 + ty + j * 8;
        T[(size_t)n * K + k0 + tx] = __float2half_rn(t[tx][ty + j * 8]);
    }
}

// ---------------------------------------------------------------------------
// mma.sync single-f16 GEMM, K-chunk 64, 3-stage cp.async, 2 CTAs/SM.
// MODE 0: C = A@Wt^T + bias (fp32 out)
// MODE 1: QKV epilogue -> Q (scaled), K, V single f16 per-head
// ---------------------------------------------------------------------------
#define CH_K   64
#define LDT_B  144                       // 64 halfs (128B) + 16B pad
#define TILE_B (128 * LDT_B)             // 18432 B
#define STAGE_B (2 * TILE_B)             // A + B = 36864 B
#define GEMM_SMEM (3 * STAGE_B)          // 110592 B -> 2 CTAs/SM (221 KB)

__device__ __forceinline__ void issue_tile(const __half* __restrict__ g,
                                           int row0, int K, int kt,
                                           uint32_t smem, int tid) {
#pragma unroll
    for (int i = 0; i < 4; i++) {
        int v = tid + i * 256;           // 128 rows x 8 16B-chunks
        int r = v >> 3, c = v & 7;
        const __half* src = g + (size_t)(row0 + r) * K + kt + c * 8;
        uint32_t dst = smem + (uint32_t)(r * LDT_B + c * 16);
        CP_ASYNC16(dst, src);
    }
}

template<int MODE>
__global__ __launch_bounds__(256, 2) void gemm_tc(
    const __half* __restrict__ A, const __half* __restrict__ B,
    const float* __restrict__ bias, float* __restrict__ C,
    __half* __restrict__ Q, __half* __restrict__ Kd, __half* __restrict__ V,
    int M, int N, int K)
{
    extern __shared__ char sm[];
    uint32_t sb = smem_u32(sm);
    const int tid  = threadIdx.x;
    const int lane = tid & 31;
    const int wid  = tid >> 5;
    const int m0   = (wid & 3) * 32;
    const int n0   = (wid >> 2) * 64;
    const int bm   = blockIdx.y * 128;
    const int bn   = blockIdx.x * 128;

    float acc[2][8][4];
#pragma unroll
    for (int i = 0; i < 2; i++)
#pragma unroll
        for (int j = 0; j < 8; j++)
#pragma unroll
            for (int q = 0; q < 4; q++) acc[i][j][q] = 0.f;

    const uint32_t a_row  = lane & 15;
    const uint32_t a_koff = ((lane >> 4) & 1) * 16;
    const uint32_t b_rin  = ((lane >> 4) & 1) * 8 + (lane & 7);
    const uint32_t b_koff = ((lane >> 3) & 1) * 16;

    const int NCH = K / CH_K;

    // prologue: stage chunks 0, 1 into slots 0, 1
#pragma unroll
    for (int p = 0; p < 2; p++) {
        uint32_t bb = sb + p * STAGE_B;
        issue_tile(A, bm, K, p * CH_K, bb + 0 * TILE_B, tid);
        issue_tile(B, bn, K, p * CH_K, bb + 1 * TILE_B, tid);
        CP_COMMIT();
    }

    for (int c = 0; c < NCH; c++) {
        if (c + 1 < NCH) { CP_WAIT1(); } else { CP_WAIT0(); }
        __syncthreads();   // chunk c visible; slot (c+2)%3 free (read at c-1)

        if (c + 2 < NCH) {
            uint32_t nb = sb + (uint32_t)((c + 2) % 3) * STAGE_B;
            int kt = (c + 2) * CH_K;
            issue_tile(A, bm, K, kt, nb + 0 * TILE_B, tid);
            issue_tile(B, bn, K, kt, nb + 1 * TILE_B, tid);
            CP_COMMIT();
        }

        uint32_t bb  = sb + (uint32_t)(c % 3) * STAGE_B;
        uint32_t A_s = bb + 0 * TILE_B;
        uint32_t B_s = bb + 1 * TILE_B;

#pragma unroll
        for (int kk = 0; kk < 4; kk++) {
            uint32_t af[2][4];
#pragma unroll
            for (int i = 0; i < 2; i++) {
                uint32_t ro = (uint32_t)(m0 + i * 16 + a_row) * LDT_B
                              + kk * 32 + a_koff;
                LDSM_X4(af[i][0], af[i][1], af[i][2], af[i][3], A_s + ro);
            }
#pragma unroll
            for (int jp = 0; jp < 4; jp++) {
                uint32_t ro = (uint32_t)(n0 + jp * 16 + b_rin) * LDT_B
                              + kk * 32 + b_koff;
                uint32_t b0, b1, b2, b3;
                LDSM_X4(b0, b1, b2, b3, B_s + ro);
                mma_f16(acc[0][jp * 2 + 0], af[0], b0, b1);
                mma_f16(acc[0][jp * 2 + 1], af[0], b2, b3);
                mma_f16(acc[1][jp * 2 + 0], af[1], b0, b1);
                mma_f16(acc[1][jp * 2 + 1], af[1], b2, b3);
            }
        }
    }

    const int rrow = lane >> 2;
    const int rcol = (lane & 3) * 2;
#pragma unroll
    for (int i = 0; i < 2; i++) {
        int r_lo = bm + m0 + i * 16 + rrow;
#pragma unroll
        for (int half = 0; half < 2; half++) {
            int row = r_lo + half * 8;
#pragma unroll
            for (int j = 0; j < 8; j++) {
                int col = bn + n0 + j * 8 + rcol;
                float b0 = bias[col], b1 = bias[col + 1];
                float v0 = acc[i][j][half * 2 + 0] + b0;
                float v1 = acc[i][j][half * 2 + 1] + b1;
                if (MODE == 0) {
                    *(float2*)&C[(size_t)row * N + col] = make_float2(v0, v1);
                } else {
                    int sec = col >> 10;           // 0=q 1=k 2=v
                    int hh  = (col & 1023) >> 6;
                    int d   = col & 63;
                    int b   = row >> 11, s = row & 2047;
                    size_t dst = (((size_t)(b * NH + hh)) * S_LEN + s) * HD + d;
                    if (sec == 0) {                // Q: scale + base-2 fold
                        v0 *= 0.125f * LOG2E;
                        v1 *= 0.125f * LOG2E;
                    }
                    __half* p = (sec == 0) ? Q : (sec == 1) ? Kd : V;
                    *(uint32_t*)(p + dst) = pack_h2(v0, v1);
                }
            }
        }
    }
}

// ---------------------------------------------------------------------------
// Tensor-core flash attention (causal), all-f16 operands.
// Deferred-base softmax: p = exp2(s - m_ref); rescale o,l only when the
// block max exceeds m_ref + 8 (p <= 256 stays comfortably in f16).
// Output o/l is mathematically invariant to the base choice.
// ---------------------------------------------------------------------------
#define ALD      144
#define KV_TILE  (64 * ALD)          // 9216 B
#define FA_STAGE (2 * KV_TILE)       // K, V = 18432 B
#define FA_SMEM  (3 * FA_STAGE)      // 55296 B

__global__ __launch_bounds__(256, 2) void flash_tc(
    const __half* __restrict__ Q,
    const __half* __restrict__ K,
    const __half* __restrict__ V,
    __half* __restrict__ Cc)
{
    extern __shared__ char sm[];
    uint32_t sb = smem_u32(sm);
    const int tid = threadIdx.x, lane = tid & 31, wid = tid >> 5;
    const int qb = (int)gridDim.x - 1 - (int)blockIdx.x;   // big tiles first
    const int h = blockIdx.y, b = blockIdx.z;
    const size_t hoff = ((size_t)(b * NH + h)) * S_LEN * HD;
    const __half* Q_g = Q + hoff + (size_t)qb * 128 * HD;
    const __half* K_g = K + hoff;
    const __half* V_g = V + hoff;

    // ---- stage Q (temporarily at sb), load fragments ----
#pragma unroll
    for (int i = 0; i < 4; i++) {
        int idx = tid + i * 256;
        int r = idx >> 3, c = idx & 7;
        CP_ASYNC16(sb + (uint32_t)(r * ALD + c * 16), Q_g + r * HD + c * 8);
    }
    CP_COMMIT(); CP_WAIT0(); __syncthreads();

    uint32_t qf[4][4];
    {
        uint32_t base = sb + (uint32_t)((wid * 16 + (lane & 15)) * ALD)
                        + ((lane >> 4) & 1) * 16;
#pragma unroll
        for (int ks = 0; ks < 4; ks++)
            LDSM_X4(qf[ks][0], qf[ks][1], qf[ks][2], qf[ks][3], base + ks * 32);
    }
    __syncthreads();

    float o[8][4];
#pragma unroll
    for (int j = 0; j < 8; j++)
#pragma unroll
        for (int q = 0; q < 4; q++) o[j][q] = 0.f;
    float m[2] = {-1e30f, -1e30f}, l[2] = {0.f, 0.f};

    const uint32_t b_rin  = ((lane >> 4) & 1) * 8 + (lane & 7);
    const uint32_t b_koff = ((lane >> 3) & 1) * 16;
    const uint32_t v_row  = (lane & 7) + ((lane >> 3) & 1) * 8;
    const uint32_t v_coff = ((lane >> 4) & 1) * 16;

    const int nIter = 2 * qb + 2;

    // prologue: stage key-blocks 0, 1 into slots 0, 1
#pragma unroll
    for (int p = 0; p < 2; p++) {
        if (p < nIter) {
            uint32_t nb = sb + (uint32_t)p * FA_STAGE;
            int kbase = p * 64 * HD;
#pragma unroll
            for (int i = 0; i < 2; i++) {
                int idx = tid + i * 256;
                int r = idx >> 3, c = idx & 7;
                uint32_t d = nb + (uint32_t)(r * ALD + c * 16);
                int go = kbase + r * HD + c * 8;
                CP_ASYNC16(d + 0 * KV_TILE, K_g + go);
                CP_ASYNC16(d + 1 * KV_TILE, V_g + go);
            }
            CP_COMMIT();
        }
    }

    for (int it = 0; it < nIter; it++) {
        if (it + 1 < nIter) { CP_WAIT1(); } else { CP_WAIT0(); }
        __syncthreads();

        if (it + 2 < nIter) {
            uint32_t nb = sb + (uint32_t)((it + 2) % 3) * FA_STAGE;
            int kbase = (it + 2) * 64 * HD;
#pragma unroll
            for (int i = 0; i < 2; i++) {
                int idx = tid + i * 256;
                int r = idx >> 3, c = idx & 7;
                uint32_t d = nb + (uint32_t)(r * ALD + c * 16);
                int go = kbase + r * HD + c * 8;
                CP_ASYNC16(d + 0 * KV_TILE, K_g + go);
                CP_ASYNC16(d + 1 * KV_TILE, V_g + go);
            }
            CP_COMMIT();
        }

        uint32_t bb = sb + (uint32_t)(it % 3) * FA_STAGE;

        // ---- S = Q K^T (single f16), interleaved accumulators ----
        float s[8][4];
#pragma unroll
        for (int j = 0; j < 8; j++)
#pragma unroll
            for (int q = 0; q < 4; q++) s[j][q] = 0.f;

#pragma unroll
        for (int ks = 0; ks < 4; ks++) {
#pragma unroll
            for (int jp = 0; jp < 4; jp++) {
                uint32_t ka = bb + (uint32_t)((jp * 16 + b_rin) * ALD)
                              + ks * 32 + b_koff;
                uint32_t k0, k1, k2, k3;
                LDSM_X4(k0, k1, k2, k3, ka);
                mma_f16(s[jp * 2 + 0], qf[ks], k0, k1);
                mma_f16(s[jp * 2 + 1], qf[ks], k2, k3);
            }
        }

        // ---- causal mask ----
        if (it >= 2 * qb) {
            int col0 = it * 64 + (lane & 3) * 2;
#pragma unroll
            for (int rr = 0; rr < 2; rr++) {
                int row = qb * 128 + wid * 16 + (lane >> 2) + rr * 8;
#pragma unroll
                for (int j = 0; j < 8; j++) {
                    int c0 = col0 + j * 8;
                    if (c0 > row)     s[j][rr * 2 + 0] = -1e30f;
                    if (c0 + 1 > row) s[j][rr * 2 + 1] = -1e30f;
                }
            }
        }

        // ---- deferred-base online softmax (base-2 domain) ----
#pragma unroll
        for (int rr = 0; rr < 2; rr++) {
            float lm = -1e30f;
#pragma unroll
            for (int j = 0; j < 8; j++)
                lm = fmaxf(lm, fmaxf(s[j][rr * 2], s[j][rr * 2 + 1]));
            lm = fmaxf(lm, __shfl_xor_sync(0xffffffffu, lm, 1));
            lm = fmaxf(lm, __shfl_xor_sync(0xffffffffu, lm, 2));
            if (lm > m[rr] + 8.0f) {       // rescale only on big max advance
                float corr = exp2f(m[rr] - lm);
                l[rr] *= corr;
#pragma unroll
                for (int j = 0; j < 8; j++) {
                    o[j][rr * 2 + 0] *= corr;
                    o[j][rr * 2 + 1] *= corr;
                }
                m[rr] = lm;
            }
            float mn = m[rr];
            float sum = 0.f;
#pragma unroll
            for (int j = 0; j < 8; j++) {
                float p0 = exp2f(s[j][rr * 2 + 0] - mn);
                float p1 = exp2f(s[j][rr * 2 + 1] - mn);
                s[j][rr * 2 + 0] = p0;
                s[j][rr * 2 + 1] = p1;
                sum += p0 + p1;
            }
            sum += __shfl_xor_sync(0xffffffffu, sum, 1);
            sum += __shfl_xor_sync(0xffffffffu, sum, 2);
            l[rr] += sum;
        }

        // ---- O += P V  (single f16) ----
#pragma unroll
        for (int ks = 0; ks < 4; ks++) {
            uint32_t p16[4];
            p16[0] = pack_h2(s[2 * ks][0],     s[2 * ks][1]);
            p16[1] = pack_h2(s[2 * ks][2],     s[2 * ks][3]);
            p16[2] = pack_h2(s[2 * ks + 1][0], s[2 * ks + 1][1]);
            p16[3] = pack_h2(s[2 * ks + 1][2], s[2 * ks + 1][3]);
            uint32_t va = bb + KV_TILE
                          + (uint32_t)((ks * 16 + v_row) * ALD) + v_coff;
#pragma unroll
            for (int ng = 0; ng < 4; ng++) {
                uint32_t v0, v1, v2, v3;
                LDSM_X4_T(v0, v1, v2, v3, va + ng * 32);
                mma_f16(o[ng * 2 + 0], p16, v0, v1);
                mma_f16(o[ng * 2 + 1], p16, v2, v3);
            }
        }
    }

    // ---- epilogue: O/l -> ctx f16 [tok][H] ----
#pragma unroll
    for (int rr = 0; rr < 2; rr++) {
        float inv = 1.0f / l[rr];
        int tok = b * S_LEN + qb * 128 + wid * 16 + (lane >> 2) + rr * 8;
#pragma unroll
        for (int j = 0; j < 8; j++) {
            int col = h * HD + j * 8 + (lane & 3) * 2;
            *(uint32_t*)(Cc + (size_t)tok * HID + col) =
                pack_h2(o[j][rr * 2 + 0] * inv, o[j][rr * 2 + 1] * inv);
        }
    }
}

// ---------------------------------------------------------------------------
extern "C" void kernel_launch(void* const* d_in, const int* in_sizes, int n_in,
                              void* d_out, int out_size)
{
    (void)in_sizes; (void)n_in; (void)out_size;
    const float* hidden  = (const float*)d_in[0];
    // d_in[1] = ltor_mask: exactly causal lower-triangular; handled analytically
    const float* W_qkv   = (const float*)d_in[2];
    const float* b_qkv   = (const float*)d_in[3];
    const float* W_dense = (const float*)d_in[4];
    const float* b_dense = (const float*)d_in[5];
    float* out = (float*)d_out;

    __half *a, *bw, *qp, *kp, *vp;
    cudaGetSymbolAddress((void**)&a,  g_A);
    cudaGetSymbolAddress((void**)&bw, g_B);
    cudaGetSymbolAddress((void**)&qp, g_Q);
    cudaGetSymbolAddress((void**)&kp, g_K);
    cudaGetSymbolAddress((void**)&vp, g_V);

    cudaFuncSetAttribute(gemm_tc<0>,
                         cudaFuncAttributeMaxDynamicSharedMemorySize, GEMM_SMEM);
    cudaFuncSetAttribute(gemm_tc<1>,
                         cudaFuncAttributeMaxDynamicSharedMemorySize, GEMM_SMEM);
    cudaFuncSetAttribute(flash_tc,
                         cudaFuncAttributeMaxDynamicSharedMemorySize, FA_SMEM);

    // 1) convert hidden -> f16
    {
        int n4 = M_TOK * HID / 4;
        convert_f16<<<(n4 + 255) / 256, 256>>>(hidden, a, n4);
    }
    // 2) transpose W_qkv -> f16 [N][K]
    {
        dim3 grid(3 * HID / 32, HID / 32);
        transpose_f16<<<grid, dim3(32, 8)>>>(W_qkv, bw, HID, 3 * HID);
    }
    // 3) QKV GEMM with fused per-head epilogue (Q scaled 0.125*log2e)
    {
        dim3 grid(3 * HID / 128, M_TOK / 128);
        gemm_tc<1><<<grid, 256, GEMM_SMEM>>>(a, bw, b_qkv, nullptr,
                                             qp, kp, vp, M_TOK, 3 * HID, HID);
    }
    // 4) flash attention -> ctx f16 (into g_A, dense-GEMM input)
    {
        dim3 grid(S_LEN / 128, NH, B_SZ);
        flash_tc<<<grid, 256, FA_SMEM>>>(qp, kp, vp, a);
    }
    // 5) transpose W_dense -> f16
    {
        dim3 grid(HID / 32, HID / 32);
        transpose_f16<<<grid, dim3(32, 8)>>>(W_dense, bw, HID, HID);
    }
    // 6) dense GEMM -> out (fp32)
    {
        dim3 grid(HID / 128, M_TOK / 128);
        gemm_tc<0><<<grid, 256, GEMM_SMEM>>>(a, bw, b_dense, out,
                                             nullptr, nullptr, nullptr,
                                             M_TOK, HID, HID);
    }
}